// round 1
// baseline (speedup 1.0000x reference)
#include <cuda_runtime.h>
#include <math.h>

// Problem constants
#define TOK   131072          // B*N*NH tokens = 4096*32
#define MDIM  512
#define FFD   2048
#define MCNT  4096            // B*N attention problems
#define NH    32
#define HEADS 8
#define HD    64

// ---------------- scratch (device globals; no allocation allowed) ----------
__device__ float g_h [TOK*MDIM];
__device__ float g_q [TOK*MDIM];
__device__ float g_k [TOK*MDIM];
__device__ float g_v [TOK*MDIM];
__device__ float g_o [TOK*MDIM];
__device__ float g_t1[TOK*MDIM];
__device__ float g_h1[TOK*MDIM];
__device__ float g_h2[TOK*MDIM];
__device__ float g_ff[(size_t)TOK*FFD];

typedef unsigned long long u64;

__device__ __forceinline__ u64 dup2(float x){
    u64 r; asm("mov.b64 %0, {%1,%1};" : "=l"(r) : "f"(x)); return r;
}
__device__ __forceinline__ void fma2(u64& c, u64 a, u64 b){
    asm("fma.rn.f32x2 %0, %1, %2, %0;" : "+l"(c) : "l"(a), "l"(b));
}
__device__ __forceinline__ float2 unpk(u64 c){
    float2 f; asm("mov.b64 {%0,%1}, %2;" : "=f"(f.x), "=f"(f.y) : "l"(c)); return f;
}

// ---------------- SGEMM: C[M,N] = A[M,K] @ B[K,N], optional SiLU ----------
// BM=BN=128, BK=16, 256 threads, 8x8 per-thread microtile, packed f32x2 FMA.
// Requires: M%128==0, N%128==0, K%16==0 (true for all launches here).
__global__ void __launch_bounds__(256,2)
sgemm_kernel(const float* __restrict__ A, const float* __restrict__ B,
             float* __restrict__ C, int M, int N, int K, int act)
{
    __shared__ __align__(16) float As[2][16][128];
    __shared__ __align__(16) float Bs[2][16][128];

    const int t  = threadIdx.x;
    const int tx = t & 15, ty = t >> 4;
    const int bm = blockIdx.y, bn = blockIdx.x;

    const int aRow = t >> 2,  aCol = (t & 3)  << 2;   // A: 64 rows/pass, 2 passes
    const int bRow = t >> 5,  bCol = (t & 31) << 2;   // B: 8 rows/pass, 2 passes

    const float* Ab = A + (size_t)(bm * 128) * K;
    const float* Bb = B + bn * 128;

    u64 acc[8][4];
    #pragma unroll
    for (int i = 0; i < 8; i++)
        #pragma unroll
        for (int j = 0; j < 4; j++) acc[i][j] = 0ull;

    const int nkt = K >> 4;

    // prologue: tile 0 -> buf 0
    #pragma unroll
    for (int r = 0; r < 2; r++){
        float4 va = *(const float4*)&Ab[(size_t)(aRow + r*64) * K + aCol];
        As[0][aCol+0][aRow + r*64] = va.x;
        As[0][aCol+1][aRow + r*64] = va.y;
        As[0][aCol+2][aRow + r*64] = va.z;
        As[0][aCol+3][aRow + r*64] = va.w;
        float4 vb = *(const float4*)&Bb[(size_t)(bRow + r*8) * N + bCol];
        *(float4*)&Bs[0][bRow + r*8][bCol] = vb;
    }
    __syncthreads();

    for (int kt = 0; kt < nkt; ++kt){
        const int buf = kt & 1;
        float4 pa[2], pb[2];
        if (kt + 1 < nkt){
            const int k0 = (kt + 1) << 4;
            #pragma unroll
            for (int r = 0; r < 2; r++){
                pa[r] = *(const float4*)&Ab[(size_t)(aRow + r*64) * K + k0 + aCol];
                pb[r] = *(const float4*)&Bb[(size_t)(k0 + bRow + r*8) * N + bCol];
            }
        }
        #pragma unroll
        for (int k = 0; k < 16; k++){
            float4 a0 = *(const float4*)&As[buf][k][ty*8];
            float4 a1 = *(const float4*)&As[buf][k][ty*8 + 4];
            ulonglong2 b01 = *(const ulonglong2*)&Bs[buf][k][tx*8];
            ulonglong2 b23 = *(const ulonglong2*)&Bs[buf][k][tx*8 + 4];
            u64 bp[4] = {b01.x, b01.y, b23.x, b23.y};
            float av[8] = {a0.x, a0.y, a0.z, a0.w, a1.x, a1.y, a1.z, a1.w};
            #pragma unroll
            for (int i = 0; i < 8; i++){
                u64 ap = dup2(av[i]);
                #pragma unroll
                for (int j = 0; j < 4; j++) fma2(acc[i][j], ap, bp[j]);
            }
        }
        if (kt + 1 < nkt){
            const int nb = buf ^ 1;
            #pragma unroll
            for (int r = 0; r < 2; r++){
                As[nb][aCol+0][aRow + r*64] = pa[r].x;
                As[nb][aCol+1][aRow + r*64] = pa[r].y;
                As[nb][aCol+2][aRow + r*64] = pa[r].z;
                As[nb][aCol+3][aRow + r*64] = pa[r].w;
                *(float4*)&Bs[nb][bRow + r*8][bCol] = pb[r];
            }
            __syncthreads();
        }
    }

    // epilogue
    const int row0 = bm * 128 + ty * 8;
    const int col0 = bn * 128 + tx * 8;
    #pragma unroll
    for (int i = 0; i < 8; i++){
        #pragma unroll
        for (int j = 0; j < 4; j++){
            float2 c = unpk(acc[i][j]);
            if (act == 1){
                c.x = c.x / (1.f + expf(-c.x));
                c.y = c.y / (1.f + expf(-c.y));
            }
            *(float2*)&C[(size_t)(row0 + i) * N + col0 + 2*j] = c;
        }
    }
}

// ---------------- fused attention (scores + rel-pos bias + softmax + AV) ---
// grid: (HEADS, MCNT), 128 threads. q/k/v/o layout: [m*32+i, h*64+d] fp32.
__global__ void __launch_bounds__(128)
attn_kernel(const float* __restrict__ q, const float* __restrict__ k,
            const float* __restrict__ v,
            const int*   __restrict__ dist, const int* __restrict__ phi,
            const float* __restrict__ dtab, const float* __restrict__ ptab,
            const float* __restrict__ Wb,   float* __restrict__ o)
{
    const int h = blockIdx.x;
    const int m = blockIdx.y;
    const int t = threadIdx.x;

    __shared__ float qs[32][65], ks[32][65], vs[32][65];
    __shared__ float sc[32][33];
    __shared__ float wb[32];

    const size_t base = (size_t)m * NH * MDIM + (size_t)h * HD;
    for (int e = t; e < NH * HD; e += 128){
        int i = e >> 6, d = e & 63;
        size_t idx = base + (size_t)i * MDIM + d;
        qs[i][d] = q[idx];
        ks[i][d] = k[idx];
        vs[i][d] = v[idx];
    }
    if (t < 32) wb[t] = Wb[t * HEADS + h];
    __syncthreads();

    const int i  = t >> 2;
    const int j0 = (t & 3) * 8;
    const int* dr = dist + (size_t)m * (NH*NH) + i * NH;
    const int* fr = phi  + (size_t)m * (NH*NH) + i * NH;

    #pragma unroll
    for (int jj = 0; jj < 8; jj++){
        const int j = j0 + jj;
        float s = 0.f;
        #pragma unroll
        for (int d = 0; d < HD; d++) s += qs[i][d] * ks[j][d];
        const float* dp = dtab + (size_t)dr[j] * 32;
        const float* fp = ptab + (size_t)fr[j] * 32;
        float bsum = 0.f;
        #pragma unroll
        for (int p = 0; p < 32; p++) bsum += dp[p] * fp[p] * wb[p];
        sc[i][j] = s * 0.125f + bsum;      // 1/sqrt(64)
    }
    __syncthreads();

    // softmax over row i (4 threads per row, 8 elems each)
    float mx = -1e30f;
    #pragma unroll
    for (int jj = 0; jj < 8; jj++) mx = fmaxf(mx, sc[i][j0 + jj]);
    mx = fmaxf(mx, __shfl_xor_sync(0xffffffffu, mx, 1));
    mx = fmaxf(mx, __shfl_xor_sync(0xffffffffu, mx, 2));
    float ev[8], sum = 0.f;
    #pragma unroll
    for (int jj = 0; jj < 8; jj++){ ev[jj] = expf(sc[i][j0 + jj] - mx); sum += ev[jj]; }
    sum += __shfl_xor_sync(0xffffffffu, sum, 1);
    sum += __shfl_xor_sync(0xffffffffu, sum, 2);
    const float inv = 1.f / sum;
    #pragma unroll
    for (int jj = 0; jj < 8; jj++) sc[i][j0 + jj] = ev[jj] * inv;
    __syncthreads();

    // o[i, dseg:dseg+16] = att[i,:] @ v[:, dseg:dseg+16]
    const int dseg = (t & 3) * 16;
    float accv[16];
    #pragma unroll
    for (int dd = 0; dd < 16; dd++) accv[dd] = 0.f;
    for (int j = 0; j < NH; j++){
        const float p = sc[i][j];
        #pragma unroll
        for (int dd = 0; dd < 16; dd++) accv[dd] += p * vs[j][dseg + dd];
    }
    float* op = o + base + (size_t)i * MDIM + dseg;
    #pragma unroll
    for (int dd = 0; dd < 16; dd++) op[dd] = accv[dd];
}

// ---------------- fused residual add + LayerNorm (row = 512) --------------
__global__ void __launch_bounds__(128)
add_ln_kernel(const float* __restrict__ a, const float* __restrict__ b,
              const float* __restrict__ g, const float* __restrict__ be,
              float* __restrict__ out)
{
    const int row = blockIdx.x;
    const int t   = threadIdx.x;
    const size_t off = (size_t)row * MDIM + t * 4;

    float4 va = *(const float4*)(a + off);
    float4 vb = *(const float4*)(b + off);
    float4 vv = make_float4(va.x + vb.x, va.y + vb.y, va.z + vb.z, va.w + vb.w);

    float s  = vv.x + vv.y + vv.z + vv.w;
    float ss = vv.x*vv.x + vv.y*vv.y + vv.z*vv.z + vv.w*vv.w;
    #pragma unroll
    for (int o2 = 16; o2; o2 >>= 1){
        s  += __shfl_xor_sync(0xffffffffu, s,  o2);
        ss += __shfl_xor_sync(0xffffffffu, ss, o2);
    }
    __shared__ float sh_s[4], sh_ss[4];
    const int w = t >> 5, l = t & 31;
    if (l == 0){ sh_s[w] = s; sh_ss[w] = ss; }
    __syncthreads();
    s  = sh_s[0]  + sh_s[1]  + sh_s[2]  + sh_s[3];
    ss = sh_ss[0] + sh_ss[1] + sh_ss[2] + sh_ss[3];

    const float mean = s * (1.f / 512.f);
    const float var  = ss * (1.f / 512.f) - mean * mean;
    const float rstd = rsqrtf(var + 1e-5f);

    float4 vg  = *(const float4*)(g  + t*4);
    float4 vbe = *(const float4*)(be + t*4);
    float4 r;
    r.x = (vv.x - mean) * rstd * vg.x + vbe.x;
    r.y = (vv.y - mean) * rstd * vg.y + vbe.y;
    r.z = (vv.z - mean) * rstd * vg.z + vbe.z;
    r.w = (vv.w - mean) * rstd * vg.w + vbe.w;
    *(float4*)(out + off) = r;
}

// ---------------- driver ---------------------------------------------------
extern "C" void kernel_launch(void* const* d_in, const int* in_sizes, int n_in,
                              void* d_out, int out_size)
{
    (void)in_sizes; (void)n_in; (void)out_size;

    const float* x    = (const float*)d_in[0];
    const int*   dist = (const int*)  d_in[1];
    const int*   phis = (const int*)  d_in[2];
    const float* W_in = (const float*)d_in[3];
    const float* dtab = (const float*)d_in[4];
    const float* ptab = (const float*)d_in[5];
    const float* Wb   = (const float*)d_in[6];
    const float* Wq   = (const float*)d_in[7];
    const float* Wk   = (const float*)d_in[8];
    const float* Wv   = (const float*)d_in[9];
    const float* Wo   = (const float*)d_in[10];
    const float* Wf1  = (const float*)d_in[11];
    const float* Wf2  = (const float*)d_in[12];
    const float* g1   = (const float*)d_in[13];
    const float* b1   = (const float*)d_in[14];
    const float* g2   = (const float*)d_in[15];
    const float* b2   = (const float*)d_in[16];
    const float* Wout = (const float*)d_in[17];
    float* out = (float*)d_out;

    float *ph, *pq, *pk, *pv, *po, *pt1, *ph1, *ph2, *pff;
    cudaGetSymbolAddress((void**)&ph,  g_h);
    cudaGetSymbolAddress((void**)&pq,  g_q);
    cudaGetSymbolAddress((void**)&pk,  g_k);
    cudaGetSymbolAddress((void**)&pv,  g_v);
    cudaGetSymbolAddress((void**)&po,  g_o);
    cudaGetSymbolAddress((void**)&pt1, g_t1);
    cudaGetSymbolAddress((void**)&ph1, g_h1);
    cudaGetSymbolAddress((void**)&ph2, g_h2);
    cudaGetSymbolAddress((void**)&pff, g_ff);

    const dim3 gproj(4, TOK/128);      // N=512 GEMMs
    const dim3 gff1 (16, TOK/128);     // N=2048
    const dim3 gout (1, TOK/128);      // N=128

    // 1) h = x @ W_in                                  [TOK,128]@[128,512]
    sgemm_kernel<<<gproj, 256>>>(x,  W_in, ph, TOK, 512, 128, 0);
    // 2) q,k,v = h @ Wq/Wk/Wv                          [TOK,512]@[512,512]
    sgemm_kernel<<<gproj, 256>>>(ph, Wq, pq, TOK, 512, 512, 0);
    sgemm_kernel<<<gproj, 256>>>(ph, Wk, pk, TOK, 512, 512, 0);
    sgemm_kernel<<<gproj, 256>>>(ph, Wv, pv, TOK, 512, 512, 0);
    // 3) attention (bias fused from tables)
    attn_kernel<<<dim3(HEADS, MCNT), 128>>>(pq, pk, pv, dist, phis,
                                            dtab, ptab, Wb, po);
    // 4) att_out = o @ Wo
    sgemm_kernel<<<gproj, 256>>>(po, Wo, pt1, TOK, 512, 512, 0);
    // 5) h1 = LN(h + att_out)
    add_ln_kernel<<<TOK, 128>>>(ph, pt1, g1, b1, ph1);
    // 6) ff = silu(h1 @ Wf1)                           [TOK,512]@[512,2048]
    sgemm_kernel<<<gff1, 256>>>(ph1, Wf1, pff, TOK, 2048, 512, 1);
    // 7) ff2 = ff @ Wf2                                [TOK,2048]@[2048,512]
    sgemm_kernel<<<gproj, 256>>>(pff, Wf2, pt1, TOK, 512, 2048, 0);
    // 8) h2 = LN(h1 + ff2)
    add_ln_kernel<<<TOK, 128>>>(ph1, pt1, g2, b2, ph2);
    // 9) out = h2 @ W_out                              [TOK,512]@[512,128]
    sgemm_kernel<<<gout, 256>>>(ph2, Wout, out, TOK, 128, 512, 0);
}

// round 4
// speedup vs baseline: 1.4355x; 1.4355x over previous
#include <cuda_runtime.h>
#include <cuda_bf16.h>
#include <cstdint>
#include <math.h>

// ---------------- problem constants ----------------
#define TOK   131072          // B*N*NH tokens
#define MDIM  512
#define FFD   2048
#define MCNT  4096
#define NH    32
#define HEADS 8
#define HD    64

// ---------------- helpers ----------------
__device__ __forceinline__ uint32_t smem_to_u32(const void* p){
    uint32_t a;
    asm("{ .reg .u64 t; cvta.to.shared.u64 t, %1; cvt.u32.u64 %0, t; }" : "=r"(a) : "l"(p));
    return a;
}
__device__ __forceinline__ void cp_async16(uint32_t saddr, const void* gaddr){
    asm volatile("cp.async.cg.shared.global [%0], [%1], 16;" :: "r"(saddr), "l"(gaddr));
}
__device__ __forceinline__ void cp_commit(){ asm volatile("cp.async.commit_group;"); }
__device__ __forceinline__ void cp_wait1(){ asm volatile("cp.async.wait_group 1;"); }
__device__ __forceinline__ void cp_wait0(){ asm volatile("cp.async.wait_group 0;"); }

__device__ __forceinline__ void ldm_x4(uint32_t addr, uint32_t& r0, uint32_t& r1,
                                       uint32_t& r2, uint32_t& r3){
    asm volatile("ldmatrix.sync.aligned.m8n8.x4.shared.b16 {%0,%1,%2,%3}, [%4];"
        : "=r"(r0), "=r"(r1), "=r"(r2), "=r"(r3) : "r"(addr));
}
__device__ __forceinline__ void ldm_x2(uint32_t addr, uint32_t& r0, uint32_t& r1){
    asm volatile("ldmatrix.sync.aligned.m8n8.x2.shared.b16 {%0,%1}, [%2];"
        : "=r"(r0), "=r"(r1) : "r"(addr));
}
__device__ __forceinline__ void mma_bf16(float& c0, float& c1, float& c2, float& c3,
                                         uint32_t a0, uint32_t a1, uint32_t a2, uint32_t a3,
                                         uint32_t b0, uint32_t b1){
    asm volatile("mma.sync.aligned.m16n8k16.row.col.f32.bf16.bf16.f32 "
        "{%0,%1,%2,%3}, {%4,%5,%6,%7}, {%8,%9}, {%0,%1,%2,%3};"
        : "+f"(c0), "+f"(c1), "+f"(c2), "+f"(c3)
        : "r"(a0), "r"(a1), "r"(a2), "r"(a3), "r"(b0), "r"(b1));
}

// ---------------- scratch (total ~3.28 GB, under aarch64 .bss reloc limit) --
__device__ __align__(256) float g_f0[TOK*MDIM];   // h, later h2
__device__ __align__(256) float g_f1[TOK*MDIM];   // q, later att_out
__device__ __align__(256) float g_f2[TOK*MDIM];   // k, later h1
__device__ __align__(256) float g_f3[TOK*MDIM];   // v, later ff2
__device__ __align__(256) float g_f4[TOK*MDIM];   // o
__device__ __align__(256) __nv_bfloat16 g_a1[(size_t)TOK*1536];  // split 512-wide acts
__device__ __align__(256) __nv_bfloat16 g_a2[(size_t)TOK*6144];  // split ff acts
__device__ __align__(256) __nv_bfloat16 g_win2 [512*384];
__device__ __align__(256) __nv_bfloat16 g_wq2  [512*1536];
__device__ __align__(256) __nv_bfloat16 g_wk2  [512*1536];
__device__ __align__(256) __nv_bfloat16 g_wv2  [512*1536];
__device__ __align__(256) __nv_bfloat16 g_wo2  [512*1536];
__device__ __align__(256) __nv_bfloat16 g_wf12 [2048*1536];
__device__ __align__(256) __nv_bfloat16 g_wf22 [512*6144];
__device__ __align__(256) __nv_bfloat16 g_wout2[128*1536];

// ---------------- split conversion: activations ----------------
// X fp32 [R,K] -> Y bf16 [R, 3K] = [hi | lo | hi]
__global__ void __launch_bounds__(256)
split_act(const float* __restrict__ X, __nv_bfloat16* __restrict__ Y,
          int K, size_t total /* R*K/4 */)
{
    size_t id = (size_t)blockIdx.x * 256 + threadIdx.x;
    if (id >= total) return;
    int kq = K >> 2;
    size_t r = id / kq;
    int c = (int)(id % kq) << 2;
    float4 x = *(const float4*)(X + r * K + c);
    __nv_bfloat16 h0 = __float2bfloat16(x.x), h1 = __float2bfloat16(x.y);
    __nv_bfloat16 h2 = __float2bfloat16(x.z), h3 = __float2bfloat16(x.w);
    __nv_bfloat16 l0 = __float2bfloat16(x.x - __bfloat162float(h0));
    __nv_bfloat16 l1 = __float2bfloat16(x.y - __bfloat162float(h1));
    __nv_bfloat16 l2 = __float2bfloat16(x.z - __bfloat162float(h2));
    __nv_bfloat16 l3 = __float2bfloat16(x.w - __bfloat162float(h3));
    __nv_bfloat162 hA = __halves2bfloat162(h0, h1), hB = __halves2bfloat162(h2, h3);
    __nv_bfloat162 lA = __halves2bfloat162(l0, l1), lB = __halves2bfloat162(l2, l3);
    size_t ob = r * (size_t)(3 * K);
    *(uint2*)(Y + ob + c)          = make_uint2(*(uint32_t*)&hA, *(uint32_t*)&hB);
    *(uint2*)(Y + ob + K + c)      = make_uint2(*(uint32_t*)&lA, *(uint32_t*)&lB);
    *(uint2*)(Y + ob + 2 * K + c)  = make_uint2(*(uint32_t*)&hA, *(uint32_t*)&hB);
}

// ---------------- split conversion: weights (with transpose) ----------------
// W fp32 [K,N] -> Y bf16 [N, 3K] = rows n: [hi(W[:,n]) | hi | lo]
__global__ void __launch_bounds__(256)
split_wt(const float* __restrict__ W, __nv_bfloat16* __restrict__ Y,
         int K, int N, size_t total /* N*3K */)
{
    size_t id = (size_t)blockIdx.x * 256 + threadIdx.x;
    if (id >= total) return;
    int K3 = 3 * K;
    size_t n = id / K3;
    int c = (int)(id % K3);
    int reg = c / K, cs = c - reg * K;
    float x = W[(size_t)cs * N + n];
    __nv_bfloat16 h = __float2bfloat16(x);
    Y[id] = (reg < 2) ? h : __float2bfloat16(x - __bfloat162float(h));
}

// ---------------- mma.sync bf16 GEMM ----------------
// act==0: C fp32 out.  act==2: SiLU then split-bf16 [hi|lo|hi] into C
// (bf16*, row stride 3*Ntot) — feeds the next GEMM directly.
// BM=BN=128, BK=32, 256 threads (8 warps 2x4), warp tile 64x32,
// SMEM rows padded to 80B -> conflict-free ldmatrix.
__global__ void __launch_bounds__(256)
mma_gemm(const __nv_bfloat16* __restrict__ A, const __nv_bfloat16* __restrict__ Bt,
         void* __restrict__ Cout, int Ks, int Ntot, int act)
{
    __shared__ __align__(16) __nv_bfloat16 As[2][128 * 40];
    __shared__ __align__(16) __nv_bfloat16 Bs[2][128 * 40];

    const int tid  = threadIdx.x;
    const int lane = tid & 31;
    const int wid  = tid >> 5;
    const int wm   = wid >> 2;
    const int wn   = wid & 3;
    const int m0   = blockIdx.y * 128;
    const int n0   = blockIdx.x * 128;

    const __nv_bfloat16* Ab = A  + (size_t)m0 * Ks;
    const __nv_bfloat16* Bb = Bt + (size_t)n0 * Ks;

    uint32_t sA[2] = { smem_to_u32(As[0]), smem_to_u32(As[1]) };
    uint32_t sB[2] = { smem_to_u32(Bs[0]), smem_to_u32(Bs[1]) };

    float c[4][4][4];
    #pragma unroll
    for (int i = 0; i < 4; i++)
        #pragma unroll
        for (int j = 0; j < 4; j++)
            #pragma unroll
            for (int q = 0; q < 4; q++) c[i][j][q] = 0.f;

    const int nkt = Ks >> 5;

    auto load_tile = [&](int kc, int buf){
        const int cbase = kc << 5;
        #pragma unroll
        for (int it = 0; it < 2; it++){
            int idx = tid + it * 256;
            int r = idx >> 2, ch = idx & 3;
            cp_async16(sA[buf] + r * 80 + ch * 16,
                       Ab + (size_t)r * Ks + cbase + ch * 8);
            cp_async16(sB[buf] + r * 80 + ch * 16,
                       Bb + (size_t)r * Ks + cbase + ch * 8);
        }
    };

    load_tile(0, 0);
    cp_commit();

    for (int kt = 0; kt < nkt; kt++){
        const int buf = kt & 1;
        if (kt + 1 < nkt){
            load_tile(kt + 1, buf ^ 1);
            cp_commit();
            cp_wait1();
        } else {
            cp_wait0();
        }
        __syncthreads();

        #pragma unroll
        for (int ks = 0; ks < 2; ks++){
            uint32_t a[4][4], b[4][2];
            #pragma unroll
            for (int mf = 0; mf < 4; mf++){
                int r = wm * 64 + mf * 16 + (lane & 15);
                int col = ks * 16 + (lane >> 4) * 8;
                ldm_x4(sA[buf] + r * 80 + col * 2,
                       a[mf][0], a[mf][1], a[mf][2], a[mf][3]);
            }
            #pragma unroll
            for (int nf = 0; nf < 4; nf++){
                int r = wn * 32 + nf * 8 + (lane & 7);
                int col = ks * 16 + ((lane >> 3) & 1) * 8;
                ldm_x2(sB[buf] + r * 80 + col * 2, b[nf][0], b[nf][1]);
            }
            #pragma unroll
            for (int mf = 0; mf < 4; mf++)
                #pragma unroll
                for (int nf = 0; nf < 4; nf++)
                    mma_bf16(c[mf][nf][0], c[mf][nf][1], c[mf][nf][2], c[mf][nf][3],
                             a[mf][0], a[mf][1], a[mf][2], a[mf][3],
                             b[nf][0], b[nf][1]);
        }
        __syncthreads();
    }

    // epilogue
    if (act == 0){
        float* C = (float*)Cout;
        #pragma unroll
        for (int mf = 0; mf < 4; mf++){
            const int row = m0 + wm * 64 + mf * 16 + (lane >> 2);
            #pragma unroll
            for (int nf = 0; nf < 4; nf++){
                const int col = n0 + wn * 32 + nf * 8 + (lane & 3) * 2;
                *(float2*)&C[(size_t)row * Ntot + col] =
                    make_float2(c[mf][nf][0], c[mf][nf][1]);
                *(float2*)&C[(size_t)(row + 8) * Ntot + col] =
                    make_float2(c[mf][nf][2], c[mf][nf][3]);
            }
        }
    } else {
        // SiLU + split-bf16 [hi | lo | hi], row stride 3*Ntot
        __nv_bfloat16* Y = (__nv_bfloat16*)Cout;
        const int K3 = 3 * Ntot;
        #pragma unroll
        for (int mf = 0; mf < 4; mf++){
            const int row = m0 + wm * 64 + mf * 16 + (lane >> 2);
            #pragma unroll
            for (int nf = 0; nf < 4; nf++){
                const int col = n0 + wn * 32 + nf * 8 + (lane & 3) * 2;
                #pragma unroll
                for (int half = 0; half < 2; half++){
                    float fx = c[mf][nf][half * 2 + 0];
                    float fy = c[mf][nf][half * 2 + 1];
                    fx = fx / (1.f + expf(-fx));
                    fy = fy / (1.f + expf(-fy));
                    __nv_bfloat16 hx = __float2bfloat16(fx);
                    __nv_bfloat16 hy = __float2bfloat16(fy);
                    __nv_bfloat16 lx = __float2bfloat16(fx - __bfloat162float(hx));
                    __nv_bfloat16 ly = __float2bfloat16(fy - __bfloat162float(hy));
                    __nv_bfloat162 hp = __halves2bfloat162(hx, hy);
                    __nv_bfloat162 lp = __halves2bfloat162(lx, ly);
                    size_t rb = (size_t)(row + half * 8) * K3;
                    *(__nv_bfloat162*)&Y[rb + col]            = hp;
                    *(__nv_bfloat162*)&Y[rb + Ntot + col]     = lp;
                    *(__nv_bfloat162*)&Y[rb + 2 * Ntot + col] = hp;
                }
            }
        }
    }
}

// ---------------- fused attention ----------------
__global__ void __launch_bounds__(128)
attn_kernel(const float* __restrict__ q, const float* __restrict__ k,
            const float* __restrict__ v,
            const int*   __restrict__ dist, const int* __restrict__ phi,
            const float* __restrict__ dtab, const float* __restrict__ ptab,
            const float* __restrict__ Wb,   float* __restrict__ o)
{
    const int h = blockIdx.x;
    const int m = blockIdx.y;
    const int t = threadIdx.x;

    __shared__ float qs[32][65], ks[32][65], vs[32][65];
    __shared__ float sc[32][33];
    __shared__ float wb[32];

    const size_t base = (size_t)m * NH * MDIM + (size_t)h * HD;
    for (int e = t; e < NH * HD; e += 128){
        int i = e >> 6, d = e & 63;
        size_t idx = base + (size_t)i * MDIM + d;
        qs[i][d] = q[idx];
        ks[i][d] = k[idx];
        vs[i][d] = v[idx];
    }
    if (t < 32) wb[t] = Wb[t * HEADS + h];
    __syncthreads();

    const int i  = t >> 2;
    const int j0 = (t & 3) * 8;
    const int* dr = dist + (size_t)m * (NH*NH) + i * NH;
    const int* fr = phi  + (size_t)m * (NH*NH) + i * NH;

    #pragma unroll
    for (int jj = 0; jj < 8; jj++){
        const int j = j0 + jj;
        float s = 0.f;
        #pragma unroll
        for (int d = 0; d < HD; d++) s += qs[i][d] * ks[j][d];
        const float* dp = dtab + (size_t)dr[j] * 32;
        const float* fp = ptab + (size_t)fr[j] * 32;
        float bsum = 0.f;
        #pragma unroll
        for (int p = 0; p < 32; p++) bsum += dp[p] * fp[p] * wb[p];
        sc[i][j] = s * 0.125f + bsum;
    }
    __syncthreads();

    float mx = -1e30f;
    #pragma unroll
    for (int jj = 0; jj < 8; jj++) mx = fmaxf(mx, sc[i][j0 + jj]);
    mx = fmaxf(mx, __shfl_xor_sync(0xffffffffu, mx, 1));
    mx = fmaxf(mx, __shfl_xor_sync(0xffffffffu, mx, 2));
    float ev[8], sum = 0.f;
    #pragma unroll
    for (int jj = 0; jj < 8; jj++){ ev[jj] = expf(sc[i][j0 + jj] - mx); sum += ev[jj]; }
    sum += __shfl_xor_sync(0xffffffffu, sum, 1);
    sum += __shfl_xor_sync(0xffffffffu, sum, 2);
    const float inv = 1.f / sum;
    #pragma unroll
    for (int jj = 0; jj < 8; jj++) sc[i][j0 + jj] = ev[jj] * inv;
    __syncthreads();

    const int dseg = (t & 3) * 16;
    float accv[16];
    #pragma unroll
    for (int dd = 0; dd < 16; dd++) accv[dd] = 0.f;
    for (int j = 0; j < NH; j++){
        const float p = sc[i][j];
        #pragma unroll
        for (int dd = 0; dd < 16; dd++) accv[dd] += p * vs[j][dseg + dd];
    }
    float* op = o + base + (size_t)i * MDIM + dseg;
    #pragma unroll
    for (int dd = 0; dd < 16; dd++) op[dd] = accv[dd];
}

// ---------------- fused residual add + LayerNorm ----------------
__global__ void __launch_bounds__(128)
add_ln_kernel(const float* __restrict__ a, const float* __restrict__ b,
              const float* __restrict__ g, const float* __restrict__ be,
              float* __restrict__ out)
{
    const int row = blockIdx.x;
    const int t   = threadIdx.x;
    const size_t off = (size_t)row * MDIM + t * 4;

    float4 va = *(const float4*)(a + off);
    float4 vb = *(const float4*)(b + off);
    float4 vv = make_float4(va.x + vb.x, va.y + vb.y, va.z + vb.z, va.w + vb.w);

    float s  = vv.x + vv.y + vv.z + vv.w;
    float ss = vv.x*vv.x + vv.y*vv.y + vv.z*vv.z + vv.w*vv.w;
    #pragma unroll
    for (int o2 = 16; o2; o2 >>= 1){
        s  += __shfl_xor_sync(0xffffffffu, s,  o2);
        ss += __shfl_xor_sync(0xffffffffu, ss, o2);
    }
    __shared__ float sh_s[4], sh_ss[4];
    const int w = t >> 5, l = t & 31;
    if (l == 0){ sh_s[w] = s; sh_ss[w] = ss; }
    __syncthreads();
    s  = sh_s[0]  + sh_s[1]  + sh_s[2]  + sh_s[3];
    ss = sh_ss[0] + sh_ss[1] + sh_ss[2] + sh_ss[3];

    const float mean = s * (1.f / 512.f);
    const float var  = ss * (1.f / 512.f) - mean * mean;
    const float rstd = rsqrtf(var + 1e-5f);

    float4 vg  = *(const float4*)(g  + t*4);
    float4 vbe = *(const float4*)(be + t*4);
    float4 r;
    r.x = (vv.x - mean) * rstd * vg.x + vbe.x;
    r.y = (vv.y - mean) * rstd * vg.y + vbe.y;
    r.z = (vv.z - mean) * rstd * vg.z + vbe.z;
    r.w = (vv.w - mean) * rstd * vg.w + vbe.w;
    *(float4*)(out + off) = r;
}

// ---------------- driver ----------------
static inline void conv_act(const float* X, __nv_bfloat16* Y, int K){
    size_t total = (size_t)TOK * K / 4;
    split_act<<<(unsigned)((total + 255) / 256), 256>>>(X, Y, K, total);
}
static inline void conv_wt(const float* W, __nv_bfloat16* Y, int K, int N){
    size_t total = (size_t)N * 3 * K;
    split_wt<<<(unsigned)((total + 255) / 256), 256>>>(W, Y, K, N, total);
}

extern "C" void kernel_launch(void* const* d_in, const int* in_sizes, int n_in,
                              void* d_out, int out_size)
{
    (void)in_sizes; (void)n_in; (void)out_size;

    const float* x    = (const float*)d_in[0];
    const int*   dist = (const int*)  d_in[1];
    const int*   phis = (const int*)  d_in[2];
    const float* W_in = (const float*)d_in[3];
    const float* dtab = (const float*)d_in[4];
    const float* ptab = (const float*)d_in[5];
    const float* Wb   = (const float*)d_in[6];
    const float* Wq   = (const float*)d_in[7];
    const float* Wk   = (const float*)d_in[8];
    const float* Wv   = (const float*)d_in[9];
    const float* Wo   = (const float*)d_in[10];
    const float* Wf1  = (const float*)d_in[11];
    const float* Wf2  = (const float*)d_in[12];
    const float* g1   = (const float*)d_in[13];
    const float* b1   = (const float*)d_in[14];
    const float* g2   = (const float*)d_in[15];
    const float* b2   = (const float*)d_in[16];
    const float* Wout = (const float*)d_in[17];
    float* out = (float*)d_out;

    float *pf0, *pf1, *pf2, *pf3, *pf4;
    __nv_bfloat16 *pa1, *pa2, *pwin, *pwq, *pwk, *pwv, *pwo, *pwf1, *pwf2, *pwout;
    cudaGetSymbolAddress((void**)&pf0, g_f0);
    cudaGetSymbolAddress((void**)&pf1, g_f1);
    cudaGetSymbolAddress((void**)&pf2, g_f2);
    cudaGetSymbolAddress((void**)&pf3, g_f3);
    cudaGetSymbolAddress((void**)&pf4, g_f4);
    cudaGetSymbolAddress((void**)&pa1,  g_a1);
    cudaGetSymbolAddress((void**)&pa2,  g_a2);
    cudaGetSymbolAddress((void**)&pwin, g_win2);
    cudaGetSymbolAddress((void**)&pwq,  g_wq2);
    cudaGetSymbolAddress((void**)&pwk,  g_wk2);
    cudaGetSymbolAddress((void**)&pwv,  g_wv2);
    cudaGetSymbolAddress((void**)&pwo,  g_wo2);
    cudaGetSymbolAddress((void**)&pwf1, g_wf12);
    cudaGetSymbolAddress((void**)&pwf2, g_wf22);
    cudaGetSymbolAddress((void**)&pwout,g_wout2);

    const unsigned MT = TOK / 128;   // 1024 m-tiles

    // weight conversions
    conv_wt(W_in, pwin, 128, 512);
    conv_wt(Wq,   pwq,  512, 512);
    conv_wt(Wk,   pwk,  512, 512);
    conv_wt(Wv,   pwv,  512, 512);
    conv_wt(Wo,   pwo,  512, 512);
    conv_wt(Wf1,  pwf1, 512, 2048);
    conv_wt(Wf2,  pwf2, 2048, 512);
    conv_wt(Wout, pwout,512, 128);

    // 1) h = x @ W_in  -> f0
    conv_act(x, pa1, 128);
    mma_gemm<<<dim3(4, MT), 256>>>(pa1, pwin, pf0, 384, 512, 0);
    // 2) q,k,v -> f1,f2,f3
    conv_act(pf0, pa1, 512);
    mma_gemm<<<dim3(4, MT), 256>>>(pa1, pwq, pf1, 1536, 512, 0);
    mma_gemm<<<dim3(4, MT), 256>>>(pa1, pwk, pf2, 1536, 512, 0);
    mma_gemm<<<dim3(4, MT), 256>>>(pa1, pwv, pf3, 1536, 512, 0);
    // 3) attention -> f4
    attn_kernel<<<dim3(HEADS, MCNT), 128>>>(pf1, pf2, pf3, dist, phis,
                                            dtab, ptab, Wb, pf4);
    // 4) att_out = o @ Wo -> f1 (q dead)
    conv_act(pf4, pa1, 512);
    mma_gemm<<<dim3(4, MT), 256>>>(pa1, pwo, pf1, 1536, 512, 0);
    // 5) h1 = LN(h + att_out) -> f2 (k dead)
    add_ln_kernel<<<TOK, 128>>>(pf0, pf1, g1, b1, pf2);
    // 6) ff = silu(h1 @ Wf1) -> split bf16 directly into a2
    conv_act(pf2, pa1, 512);
    mma_gemm<<<dim3(16, MT), 256>>>(pa1, pwf1, pa2, 1536, 2048, 2);
    // 7) ff2 = ff @ Wf2 -> f3 (v dead)
    mma_gemm<<<dim3(4, MT), 256>>>(pa2, pwf2, pf3, 6144, 512, 0);
    // 8) h2 = LN(h1 + ff2) -> f0 (h dead)
    add_ln_kernel<<<TOK, 128>>>(pf2, pf3, g2, b2, pf0);
    // 9) out = h2 @ W_out
    conv_act(pf0, pa1, 512);
    mma_gemm<<<dim3(1, MT), 256>>>(pa1, pwout, out, 1536, 128, 0);
}

// round 6
// speedup vs baseline: 1.4597x; 1.0169x over previous
#include <cuda_runtime.h>
#include <cuda_bf16.h>
#include <cstdint>
#include <math.h>

// ---------------- problem constants ----------------
#define TOK   131072          // B*N*NH tokens
#define MDIM  512
#define FFD   2048
#define MCNT  4096
#define NH    32
#define HEADS 8
#define HD    64

// ---------------- helpers ----------------
__device__ __forceinline__ uint32_t smem_to_u32(const void* p){
    uint32_t a;
    asm("{ .reg .u64 t; cvta.to.shared.u64 t, %1; cvt.u32.u64 %0, t; }" : "=r"(a) : "l"(p));
    return a;
}
__device__ __forceinline__ void cp_async16(uint32_t saddr, const void* gaddr){
    asm volatile("cp.async.cg.shared.global [%0], [%1], 16;" :: "r"(saddr), "l"(gaddr));
}
__device__ __forceinline__ void cp_commit(){ asm volatile("cp.async.commit_group;"); }
template<int N>
__device__ __forceinline__ void cp_wait(){ asm volatile("cp.async.wait_group %0;" :: "n"(N)); }

__device__ __forceinline__ void ldm_x4(uint32_t addr, uint32_t& r0, uint32_t& r1,
                                       uint32_t& r2, uint32_t& r3){
    asm volatile("ldmatrix.sync.aligned.m8n8.x4.shared.b16 {%0,%1,%2,%3}, [%4];"
        : "=r"(r0), "=r"(r1), "=r"(r2), "=r"(r3) : "r"(addr));
}
__device__ __forceinline__ void mma_bf16(float& c0, float& c1, float& c2, float& c3,
                                         uint32_t a0, uint32_t a1, uint32_t a2, uint32_t a3,
                                         uint32_t b0, uint32_t b1){
    asm volatile("mma.sync.aligned.m16n8k16.row.col.f32.bf16.bf16.f32 "
        "{%0,%1,%2,%3}, {%4,%5,%6,%7}, {%8,%9}, {%0,%1,%2,%3};"
        : "+f"(c0), "+f"(c1), "+f"(c2), "+f"(c3)
        : "r"(a0), "r"(a1), "r"(a2), "r"(a3), "r"(b0), "r"(b1));
}
__device__ __forceinline__ void split2(float f, __nv_bfloat16& h, __nv_bfloat16& l){
    h = __float2bfloat16(f);
    l = __float2bfloat16(f - __bfloat162float(h));
}

// ---------------- scratch (~2.3 GB) ----------------
__device__ __align__(256) float g_f0 [TOK*MDIM];          // h (residual)
__device__ __align__(256) float g_qkv[(size_t)TOK*1536];  // qkv / att_out / h1 / ff2
__device__ __align__(256) __nv_bfloat16 g_a1[(size_t)TOK*1024];  // split 512-wide acts
__device__ __align__(256) __nv_bfloat16 g_a2[(size_t)TOK*4096];  // split ff / x acts
__device__ __align__(256) __nv_bfloat16 g_win2 [512*256];
__device__ __align__(256) __nv_bfloat16 g_wqkv2[(size_t)1536*1024];
__device__ __align__(256) __nv_bfloat16 g_wo2  [512*1024];
__device__ __align__(256) __nv_bfloat16 g_wf12 [(size_t)2048*1024];
__device__ __align__(256) __nv_bfloat16 g_wf22 [(size_t)512*4096];
__device__ __align__(256) __nv_bfloat16 g_wout2[128*1024];

// ---------------- split conversion: activations (x only) ----------------
// X fp32 [R,K] -> Y bf16 [R, 2K] = [hi | lo]
__global__ void __launch_bounds__(256)
split_act(const float* __restrict__ X, __nv_bfloat16* __restrict__ Y,
          int K, size_t total /* R*K/4 */)
{
    size_t id = (size_t)blockIdx.x * 256 + threadIdx.x;
    if (id >= total) return;
    int kq = K >> 2;
    size_t r = id / kq;
    int c = (int)(id % kq) << 2;
    float4 x = *(const float4*)(X + r * K + c);
    __nv_bfloat16 h0,h1,h2,h3,l0,l1,l2,l3;
    split2(x.x,h0,l0); split2(x.y,h1,l1); split2(x.z,h2,l2); split2(x.w,h3,l3);
    __nv_bfloat162 hA = __halves2bfloat162(h0,h1), hB = __halves2bfloat162(h2,h3);
    __nv_bfloat162 lA = __halves2bfloat162(l0,l1), lB = __halves2bfloat162(l2,l3);
    size_t ob = r * (size_t)(2 * K);
    *(uint2*)(Y + ob + c)     = make_uint2(*(uint32_t*)&hA, *(uint32_t*)&hB);
    *(uint2*)(Y + ob + K + c) = make_uint2(*(uint32_t*)&lA, *(uint32_t*)&lB);
}

// ---------------- split conversion: weights (with transpose) ----------------
// W fp32 [K,N] -> Y bf16 [N, 2K]: row n = [hi(W[:,n]) | lo(W[:,n])]
__global__ void __launch_bounds__(256)
split_wt(const float* __restrict__ W, __nv_bfloat16* __restrict__ Y,
         int K, int N, size_t total /* N*2K */)
{
    size_t id = (size_t)blockIdx.x * 256 + threadIdx.x;
    if (id >= total) return;
    int K2 = 2 * K;
    size_t n = id / K2;
    int c = (int)(id % K2);
    int reg = c >= K, cs = c - (reg ? K : 0);
    float x = W[(size_t)cs * N + n];
    __nv_bfloat16 h, l;
    split2(x, h, l);
    Y[id] = reg ? l : h;
}

// ---------------- mma.sync bf16 GEMM, 3-segment split schedule ----------------
// A [M, 2K] = [hi|lo], Bt [Ntot, 2K] = [hi|lo] (K-major rows).
// Segments: (Ahi,Bhi), (Alo,Bhi), (Ahi,Blo) accumulated in registers.
// BM=128, BN=32*NFRAG, BK=32, 3 stages, 256 threads (8 warps 2x4),
// warp tile 64 x (8*NFRAG). mode: 0=f32, 1=silu+split, 2=f32+split.
template<int NFRAG>
__global__ void __launch_bounds__(256)
mma_gemm(const __nv_bfloat16* __restrict__ A, const __nv_bfloat16* __restrict__ Bt,
         float* __restrict__ Cf, __nv_bfloat16* __restrict__ Csp,
         int K, int Ntot, int mode)
{
    constexpr int BN = 32 * NFRAG;
    constexpr int STAGES = 3;
    constexpr int A_BYTES = 128 * 80;
    constexpr int STAGE_BYTES = (128 + BN) * 80;
    extern __shared__ __align__(16) char smem[];

    const int tid  = threadIdx.x;
    const int lane = tid & 31;
    const int wid  = tid >> 5;
    const int wm   = wid >> 2;
    const int wn   = wid & 3;
    const int m0   = blockIdx.y * 128;
    const int n0   = blockIdx.x * BN;

    const int lda = 2 * K;
    const __nv_bfloat16* Ab = A  + (size_t)m0 * lda;
    const __nv_bfloat16* Bb = Bt + (size_t)n0 * lda;
    const uint32_t sbase = smem_to_u32(smem);

    float c[4][NFRAG][4];
    #pragma unroll
    for (int i = 0; i < 4; i++)
        #pragma unroll
        for (int j = 0; j < NFRAG; j++)
            #pragma unroll
            for (int q = 0; q < 4; q++) c[i][j][q] = 0.f;

    const int kch = K >> 5;
    const int nch = 3 * kch;

    auto load_chunk = [&](int tt, int stage){
        int seg = (tt >= kch) + (tt >= 2 * kch);
        int kk = tt - seg * kch;
        int ac = ((seg == 1) ? K : 0) + (kk << 5);
        int bc = ((seg == 2) ? K : 0) + (kk << 5);
        uint32_t sa = sbase + stage * STAGE_BYTES;
        uint32_t sb = sa + A_BYTES;
        #pragma unroll
        for (int it = 0; it < 2; it++){
            int idx = tid + it * 256;
            int r = idx >> 2, ch = idx & 3;
            cp_async16(sa + r * 80 + ch * 16, Ab + (size_t)r * lda + ac + ch * 8);
        }
        #pragma unroll
        for (int it = 0; it < NFRAG / 2; it++){
            int idx = tid + it * 256;
            int r = idx >> 2, ch = idx & 3;
            cp_async16(sb + r * 80 + ch * 16, Bb + (size_t)r * lda + bc + ch * 8);
        }
    };

    #pragma unroll
    for (int s = 0; s < STAGES - 1; s++){
        if (s < nch) load_chunk(s, s);
        cp_commit();
    }

    for (int t = 0; t < nch; t++){
        cp_wait<STAGES - 2>();
        __syncthreads();
        const int pf = t + STAGES - 1;
        if (pf < nch) load_chunk(pf, pf % STAGES);
        cp_commit();

        const uint32_t sa = sbase + (t % STAGES) * STAGE_BYTES;
        const uint32_t sb = sa + A_BYTES;
        #pragma unroll
        for (int ks = 0; ks < 2; ks++){
            uint32_t a[4][4], b[NFRAG][2];
            #pragma unroll
            for (int mf = 0; mf < 4; mf++){
                int r = wm * 64 + mf * 16 + (lane & 15);
                int col = ks * 16 + (lane >> 4) * 8;
                ldm_x4(sa + r * 80 + col * 2, a[mf][0], a[mf][1], a[mf][2], a[mf][3]);
            }
            #pragma unroll
            for (int g = 0; g < NFRAG / 2; g++){
                int r = wn * (8 * NFRAG) + g * 16 + ((lane >> 4) << 3) + (lane & 7);
                int col = ks * 16 + ((lane >> 3) & 1) * 8;
                ldm_x4(sb + r * 80 + col * 2,
                       b[2*g][0], b[2*g][1], b[2*g+1][0], b[2*g+1][1]);
            }
            #pragma unroll
            for (int mf = 0; mf < 4; mf++)
                #pragma unroll
                for (int nf = 0; nf < NFRAG; nf++)
                    mma_bf16(c[mf][nf][0], c[mf][nf][1], c[mf][nf][2], c[mf][nf][3],
                             a[mf][0], a[mf][1], a[mf][2], a[mf][3],
                             b[nf][0], b[nf][1]);
        }
    }

    // epilogue
    #pragma unroll
    for (int mf = 0; mf < 4; mf++){
        #pragma unroll
        for (int half = 0; half < 2; half++){
            const int row = m0 + wm * 64 + mf * 16 + (lane >> 2) + half * 8;
            #pragma unroll
            for (int nf = 0; nf < NFRAG; nf++){
                const int col = n0 + wn * (8 * NFRAG) + nf * 8 + (lane & 3) * 2;
                float fx = c[mf][nf][half * 2 + 0];
                float fy = c[mf][nf][half * 2 + 1];
                if (mode == 1){
                    fx = fx / (1.f + __expf(-fx));
                    fy = fy / (1.f + __expf(-fy));
                }
                if (mode != 1){
                    *(float2*)&Cf[(size_t)row * Ntot + col] = make_float2(fx, fy);
                }
                if (mode != 0){
                    __nv_bfloat16 hx, hy, lx, ly;
                    split2(fx, hx, lx);
                    split2(fy, hy, ly);
                    __nv_bfloat162 hp = __halves2bfloat162(hx, hy);
                    __nv_bfloat162 lp = __halves2bfloat162(lx, ly);
                    size_t rb = (size_t)row * (2 * Ntot);
                    *(__nv_bfloat162*)&Csp[rb + col]        = hp;
                    *(__nv_bfloat162*)&Csp[rb + Ntot + col] = lp;
                }
            }
        }
    }
}

// ---------------- fused attention (qkv packed; split-bf16 output) ----------
__global__ void __launch_bounds__(128)
attn_kernel(const float* __restrict__ qkv,
            const int*   __restrict__ dist, const int* __restrict__ phi,
            const float* __restrict__ dtab, const float* __restrict__ ptab,
            const float* __restrict__ Wb,   __nv_bfloat16* __restrict__ osp)
{
    const int h = blockIdx.x;
    const int m = blockIdx.y;
    const int t = threadIdx.x;

    __shared__ float qs[32][65], ks[32][65], vs[32][65];
    __shared__ float sc[32][33];
    __shared__ float wb[32];

    const size_t base = (size_t)m * NH * 1536 + (size_t)h * HD;
    for (int e = t; e < NH * HD; e += 128){
        int i = e >> 6, d = e & 63;
        size_t idx = base + (size_t)i * 1536 + d;
        qs[i][d] = qkv[idx];
        ks[i][d] = qkv[idx + 512];
        vs[i][d] = qkv[idx + 1024];
    }
    if (t < 32) wb[t] = Wb[t * HEADS + h];
    __syncthreads();

    const int i  = t >> 2;
    const int j0 = (t & 3) * 8;
    const int* dr = dist + (size_t)m * (NH*NH) + i * NH;
    const int* fr = phi  + (size_t)m * (NH*NH) + i * NH;

    #pragma unroll
    for (int jj = 0; jj < 8; jj++){
        const int j = j0 + jj;
        float s = 0.f;
        #pragma unroll
        for (int d = 0; d < HD; d++) s += qs[i][d] * ks[j][d];
        const float* dp = dtab + (size_t)dr[j] * 32;
        const float* fp = ptab + (size_t)fr[j] * 32;
        float bsum = 0.f;
        #pragma unroll
        for (int p = 0; p < 32; p++) bsum += dp[p] * fp[p] * wb[p];
        sc[i][j] = s * 0.125f + bsum;
    }
    __syncthreads();

    float mx = -1e30f;
    #pragma unroll
    for (int jj = 0; jj < 8; jj++) mx = fmaxf(mx, sc[i][j0 + jj]);
    mx = fmaxf(mx, __shfl_xor_sync(0xffffffffu, mx, 1));
    mx = fmaxf(mx, __shfl_xor_sync(0xffffffffu, mx, 2));
    float ev[8], sum = 0.f;
    #pragma unroll
    for (int jj = 0; jj < 8; jj++){ ev[jj] = expf(sc[i][j0 + jj] - mx); sum += ev[jj]; }
    sum += __shfl_xor_sync(0xffffffffu, sum, 1);
    sum += __shfl_xor_sync(0xffffffffu, sum, 2);
    const float inv = 1.f / sum;
    #pragma unroll
    for (int jj = 0; jj < 8; jj++) sc[i][j0 + jj] = ev[jj] * inv;
    __syncthreads();

    const int dseg = (t & 3) * 16;
    float accv[16];
    #pragma unroll
    for (int dd = 0; dd < 16; dd++) accv[dd] = 0.f;
    for (int j = 0; j < NH; j++){
        const float p = sc[i][j];
        #pragma unroll
        for (int dd = 0; dd < 16; dd++) accv[dd] += p * vs[j][dseg + dd];
    }
    // split-bf16 output, row stride 1024 = [hi(512) | lo(512)]
    size_t rb = ((size_t)m * NH + i) * 1024 + (size_t)h * HD + dseg;
    #pragma unroll
    for (int dd = 0; dd < 16; dd += 2){
        __nv_bfloat16 hx, hy, lx, ly;
        split2(accv[dd],   hx, lx);
        split2(accv[dd+1], hy, ly);
        *(__nv_bfloat162*)&osp[rb + dd]       = __halves2bfloat162(hx, hy);
        *(__nv_bfloat162*)&osp[rb + 512 + dd] = __halves2bfloat162(lx, ly);
    }
}

// ---------------- fused residual add + LayerNorm (+optional split out) ----
__global__ void __launch_bounds__(128)
add_ln_kernel2(const float* __restrict__ a, const float* __restrict__ b,
               const float* __restrict__ g, const float* __restrict__ be,
               float* __restrict__ outf, __nv_bfloat16* __restrict__ outsp)
{
    const int row = blockIdx.x;
    const int t   = threadIdx.x;
    const size_t off = (size_t)row * MDIM + t * 4;

    float4 va = *(const float4*)(a + off);
    float4 vb = *(const float4*)(b + off);
    float4 vv = make_float4(va.x + vb.x, va.y + vb.y, va.z + vb.z, va.w + vb.w);

    float s  = vv.x + vv.y + vv.z + vv.w;
    float ss = vv.x*vv.x + vv.y*vv.y + vv.z*vv.z + vv.w*vv.w;
    #pragma unroll
    for (int o2 = 16; o2; o2 >>= 1){
        s  += __shfl_xor_sync(0xffffffffu, s,  o2);
        ss += __shfl_xor_sync(0xffffffffu, ss, o2);
    }
    __shared__ float sh_s[4], sh_ss[4];
    const int w = t >> 5, l = t & 31;
    if (l == 0){ sh_s[w] = s; sh_ss[w] = ss; }
    __syncthreads();
    s  = sh_s[0]  + sh_s[1]  + sh_s[2]  + sh_s[3];
    ss = sh_ss[0] + sh_ss[1] + sh_ss[2] + sh_ss[3];

    const float mean = s * (1.f / 512.f);
    const float var  = ss * (1.f / 512.f) - mean * mean;
    const float rstd = rsqrtf(var + 1e-5f);

    float4 vg  = *(const float4*)(g  + t*4);
    float4 vbe = *(const float4*)(be + t*4);
    float4 r;
    r.x = (vv.x - mean) * rstd * vg.x + vbe.x;
    r.y = (vv.y - mean) * rstd * vg.y + vbe.y;
    r.z = (vv.z - mean) * rstd * vg.z + vbe.z;
    r.w = (vv.w - mean) * rstd * vg.w + vbe.w;
    if (outf) *(float4*)(outf + off) = r;
    if (outsp){
        __nv_bfloat16 h0,h1,h2,h3,l0,l1,l2,l3;
        split2(r.x,h0,l0); split2(r.y,h1,l1); split2(r.z,h2,l2); split2(r.w,h3,l3);
        __nv_bfloat162 hA = __halves2bfloat162(h0,h1), hB = __halves2bfloat162(h2,h3);
        __nv_bfloat162 lA = __halves2bfloat162(l0,l1), lB = __halves2bfloat162(l2,l3);
        size_t rb = (size_t)row * 1024 + t * 4;
        *(uint2*)(outsp + rb)       = make_uint2(*(uint32_t*)&hA, *(uint32_t*)&hB);
        *(uint2*)(outsp + rb + 512) = make_uint2(*(uint32_t*)&lA, *(uint32_t*)&lB);
    }
}

// ---------------- driver ----------------
static inline void conv_wt(const float* W, __nv_bfloat16* Y, int K, int N){
    size_t total = (size_t)N * 2 * K;
    split_wt<<<(unsigned)((total + 255) / 256), 256>>>(W, Y, K, N, total);
}

extern "C" void kernel_launch(void* const* d_in, const int* in_sizes, int n_in,
                              void* d_out, int out_size)
{
    (void)in_sizes; (void)n_in; (void)out_size;

    const float* x    = (const float*)d_in[0];
    const int*   dist = (const int*)  d_in[1];
    const int*   phis = (const int*)  d_in[2];
    const float* W_in = (const float*)d_in[3];
    const float* dtab = (const float*)d_in[4];
    const float* ptab = (const float*)d_in[5];
    const float* Wb   = (const float*)d_in[6];
    const float* Wq   = (const float*)d_in[7];
    const float* Wk   = (const float*)d_in[8];
    const float* Wv   = (const float*)d_in[9];
    const float* Wo   = (const float*)d_in[10];
    const float* Wf1  = (const float*)d_in[11];
    const float* Wf2  = (const float*)d_in[12];
    const float* g1   = (const float*)d_in[13];
    const float* b1   = (const float*)d_in[14];
    const float* g2   = (const float*)d_in[15];
    const float* b2   = (const float*)d_in[16];
    const float* Wout = (const float*)d_in[17];
    float* out = (float*)d_out;

    float *pf0, *pqkv;
    __nv_bfloat16 *pa1, *pa2, *pwin, *pwqkv, *pwo, *pwf1, *pwf2, *pwout;
    cudaGetSymbolAddress((void**)&pf0,  g_f0);
    cudaGetSymbolAddress((void**)&pqkv, g_qkv);
    cudaGetSymbolAddress((void**)&pa1,  g_a1);
    cudaGetSymbolAddress((void**)&pa2,  g_a2);
    cudaGetSymbolAddress((void**)&pwin, g_win2);
    cudaGetSymbolAddress((void**)&pwqkv,g_wqkv2);
    cudaGetSymbolAddress((void**)&pwo,  g_wo2);
    cudaGetSymbolAddress((void**)&pwf1, g_wf12);
    cudaGetSymbolAddress((void**)&pwf2, g_wf22);
    cudaGetSymbolAddress((void**)&pwout,g_wout2);

    float* att_out = pqkv;                       // aliases (sequential deps)
    float* h1      = pqkv + (size_t)TOK * 512;
    float* ff2     = pqkv + (size_t)TOK * 1024;

    const int SM8 = (128 + 256) * 80 * 3;   // 92160
    const int SM4 = (128 + 128) * 80 * 3;   // 61440
    cudaFuncSetAttribute(mma_gemm<8>, cudaFuncAttributeMaxDynamicSharedMemorySize, SM8);
    cudaFuncSetAttribute(mma_gemm<4>, cudaFuncAttributeMaxDynamicSharedMemorySize, SM4);

    const unsigned MT = TOK / 128;   // 1024 m-tiles

    // weight conversions ([hi|lo], 2K rows-major by N)
    conv_wt(W_in, pwin, 128, 512);
    conv_wt(Wq,   pwqkv,                     512, 512);
    conv_wt(Wk,   pwqkv + (size_t)512*1024,  512, 512);
    conv_wt(Wv,   pwqkv + (size_t)1024*1024, 512, 512);
    conv_wt(Wo,   pwo,  512, 512);
    conv_wt(Wf1,  pwf1, 512, 2048);
    conv_wt(Wf2,  pwf2, 2048, 512);
    conv_wt(Wout, pwout,512, 128);

    // split x -> a2  [TOK, 256]
    {
        size_t total = (size_t)TOK * 128 / 4;
        split_act<<<(unsigned)((total + 255) / 256), 256>>>(x, pa2, 128, total);
    }
    // 1) h = x @ W_in -> f0 (fp32) + split -> a1
    mma_gemm<8><<<dim3(2, MT), 256, SM8>>>(pa2, pwin, pf0, pa1, 128, 512, 2);
    // 2) qkv = h @ Wqkv -> qkv fp32 [TOK,1536]
    mma_gemm<8><<<dim3(6, MT), 256, SM8>>>(pa1, pwqkv, pqkv, nullptr, 512, 1536, 0);
    // 3) attention -> split o -> a1
    attn_kernel<<<dim3(HEADS, MCNT), 128>>>(pqkv, dist, phis, dtab, ptab, Wb, pa1);
    // 4) att_out = o @ Wo -> fp32 (qkv region reused)
    mma_gemm<8><<<dim3(2, MT), 256, SM8>>>(pa1, pwo, att_out, nullptr, 512, 512, 0);
    // 5) h1 = LN(h + att_out) -> fp32 h1 + split -> a1
    add_ln_kernel2<<<TOK, 128>>>(pf0, att_out, g1, b1, h1, pa1);
    // 6) ff = silu(h1 @ Wf1) -> split -> a2
    mma_gemm<8><<<dim3(8, MT), 256, SM8>>>(pa1, pwf1, nullptr, pa2, 512, 2048, 1);
    // 7) ff2 = ff @ Wf2 -> fp32
    mma_gemm<8><<<dim3(2, MT), 256, SM8>>>(pa2, pwf2, ff2, nullptr, 2048, 512, 0);
    // 8) h2 = LN(h1 + ff2) -> split only -> a1
    add_ln_kernel2<<<TOK, 128>>>(h1, ff2, g2, b2, nullptr, pa1);
    // 9) out = h2 @ W_out
    mma_gemm<4><<<dim3(1, MT), 256, SM4>>>(pa1, pwout, out, nullptr, 512, 128, 0);
}

// round 7
// speedup vs baseline: 1.4675x; 1.0053x over previous
#include <cuda_runtime.h>
#include <cuda_bf16.h>
#include <cstdint>
#include <math.h>

// ---------------- problem constants ----------------
#define TOK   131072          // B*N*NH tokens
#define MDIM  512
#define FFD   2048
#define MCNT  4096
#define NH    32
#define HEADS 8
#define HD    64

// ---------------- helpers ----------------
__device__ __forceinline__ uint32_t smem_to_u32(const void* p){
    uint32_t a;
    asm("{ .reg .u64 t; cvta.to.shared.u64 t, %1; cvt.u32.u64 %0, t; }" : "=r"(a) : "l"(p));
    return a;
}
__device__ __forceinline__ void cp_async16(uint32_t saddr, const void* gaddr){
    asm volatile("cp.async.cg.shared.global [%0], [%1], 16;" :: "r"(saddr), "l"(gaddr));
}
__device__ __forceinline__ void cp_commit(){ asm volatile("cp.async.commit_group;"); }
template<int N>
__device__ __forceinline__ void cp_wait(){ asm volatile("cp.async.wait_group %0;" :: "n"(N)); }

__device__ __forceinline__ void ldm_x4(uint32_t addr, uint32_t& r0, uint32_t& r1,
                                       uint32_t& r2, uint32_t& r3){
    asm volatile("ldmatrix.sync.aligned.m8n8.x4.shared.b16 {%0,%1,%2,%3}, [%4];"
        : "=r"(r0), "=r"(r1), "=r"(r2), "=r"(r3) : "r"(addr));
}
__device__ __forceinline__ void mma_bf16(float& c0, float& c1, float& c2, float& c3,
                                         uint32_t a0, uint32_t a1, uint32_t a2, uint32_t a3,
                                         uint32_t b0, uint32_t b1){
    asm volatile("mma.sync.aligned.m16n8k16.row.col.f32.bf16.bf16.f32 "
        "{%0,%1,%2,%3}, {%4,%5,%6,%7}, {%8,%9}, {%0,%1,%2,%3};"
        : "+f"(c0), "+f"(c1), "+f"(c2), "+f"(c3)
        : "r"(a0), "r"(a1), "r"(a2), "r"(a3), "r"(b0), "r"(b1));
}
__device__ __forceinline__ void split2(float f, __nv_bfloat16& h, __nv_bfloat16& l){
    h = __float2bfloat16(f);
    l = __float2bfloat16(f - __bfloat162float(h));
}

// ---------------- scratch (~2.3 GB) ----------------
__device__ __align__(256) float g_f0 [TOK*MDIM];          // h (residual)
__device__ __align__(256) float g_qkv[(size_t)TOK*1536];  // qkv / att_out / h1 / ff2
__device__ __align__(256) __nv_bfloat16 g_a1[(size_t)TOK*1024];  // split 512-wide acts
__device__ __align__(256) __nv_bfloat16 g_a2[(size_t)TOK*4096];  // split ff / x acts
__device__ __align__(256) __nv_bfloat16 g_win2 [512*256];
__device__ __align__(256) __nv_bfloat16 g_wqkv2[(size_t)1536*1024];
__device__ __align__(256) __nv_bfloat16 g_wo2  [512*1024];
__device__ __align__(256) __nv_bfloat16 g_wf12 [(size_t)2048*1024];
__device__ __align__(256) __nv_bfloat16 g_wf22 [(size_t)512*4096];
__device__ __align__(256) __nv_bfloat16 g_wout2[128*1024];

// ---------------- fused weight conversion (ONE launch for all 8) ----------
// W fp32 [K,N] -> Y bf16 [N, 2K]: row n = [hi(W[:,n]) | lo(W[:,n])]
struct WtDesc { const float* W; __nv_bfloat16* Y; int K; int N; };
struct WtTable { WtDesc d[8]; };

__global__ void __launch_bounds__(256)
split_wt_all(WtTable tab)
{
    const WtDesc& e = tab.d[blockIdx.y];
    size_t total = (size_t)e.N * 2 * e.K;
    size_t id = (size_t)blockIdx.x * 256 + threadIdx.x;
    if (id >= total) return;
    int K2 = 2 * e.K;
    size_t n = id / K2;
    int c = (int)(id % K2);
    int reg = c >= e.K, cs = c - (reg ? e.K : 0);
    float x = e.W[(size_t)cs * e.N + n];
    __nv_bfloat16 h, l;
    split2(x, h, l);
    e.Y[id] = reg ? l : h;
}

// ---------------- split conversion: activations (x only) ----------------
__global__ void __launch_bounds__(256)
split_act(const float* __restrict__ X, __nv_bfloat16* __restrict__ Y,
          int K, size_t total /* R*K/4 */)
{
    size_t id = (size_t)blockIdx.x * 256 + threadIdx.x;
    if (id >= total) return;
    int kq = K >> 2;
    size_t r = id / kq;
    int c = (int)(id % kq) << 2;
    float4 x = *(const float4*)(X + r * K + c);
    __nv_bfloat16 h0,h1,h2,h3,l0,l1,l2,l3;
    split2(x.x,h0,l0); split2(x.y,h1,l1); split2(x.z,h2,l2); split2(x.w,h3,l3);
    __nv_bfloat162 hA = __halves2bfloat162(h0,h1), hB = __halves2bfloat162(h2,h3);
    __nv_bfloat162 lA = __halves2bfloat162(l0,l1), lB = __halves2bfloat162(l2,l3);
    size_t ob = r * (size_t)(2 * K);
    *(uint2*)(Y + ob + c)     = make_uint2(*(uint32_t*)&hA, *(uint32_t*)&hB);
    *(uint2*)(Y + ob + K + c) = make_uint2(*(uint32_t*)&lA, *(uint32_t*)&lB);
}

// ---------------- mma.sync bf16 GEMM, 3-segment split schedule ----------------
// A [M, 2K] = [hi|lo], Bt [Ntot, 2K] = [hi|lo] (K-major rows).
// Segments: (Ahi,Bhi), (Alo,Bhi), (Ahi,Blo) accumulated in registers.
// CTA tile 128 x (32*WN); WM=2 x WN warps; warp tile 64x32; BK=32; 3 stages.
// WN=8: 512 threads (4 warps/SMSP). mode: 0=f32, 1=silu+split, 2=f32+split.
template<int WN>
__global__ void __launch_bounds__(64*WN)
mma_gemm(const __nv_bfloat16* __restrict__ A, const __nv_bfloat16* __restrict__ Bt,
         float* __restrict__ Cf, __nv_bfloat16* __restrict__ Csp,
         int K, int Ntot, int mode)
{
    constexpr int BN = 32 * WN;
    constexpr int THREADS = 64 * WN;
    constexpr int STAGES = 3;
    constexpr int A_BYTES = 128 * 80;
    constexpr int STAGE_BYTES = (128 + BN) * 80;
    constexpr int A_CH = (128 * 4) / THREADS;   // 16B chunks per thread for A
    constexpr int B_CH = (BN * 4) / THREADS;    // 16B chunks per thread for B
    extern __shared__ __align__(16) char smem[];

    const int tid  = threadIdx.x;
    const int lane = tid & 31;
    const int wid  = tid >> 5;
    const int wm   = wid / WN;        // 0..1
    const int wn   = wid % WN;        // 0..WN-1
    const int m0   = blockIdx.y * 128;
    const int n0   = blockIdx.x * BN;

    const int lda = 2 * K;
    const __nv_bfloat16* Ab = A  + (size_t)m0 * lda;
    const __nv_bfloat16* Bb = Bt + (size_t)n0 * lda;
    const uint32_t sbase = smem_to_u32(smem);

    float c[4][4][4];
    #pragma unroll
    for (int i = 0; i < 4; i++)
        #pragma unroll
        for (int j = 0; j < 4; j++)
            #pragma unroll
            for (int q = 0; q < 4; q++) c[i][j][q] = 0.f;

    const int kch = K >> 5;
    const int nch = 3 * kch;

    auto load_chunk = [&](int tt, int stage){
        int seg = (tt >= kch) + (tt >= 2 * kch);
        int kk = tt - seg * kch;
        int ac = ((seg == 1) ? K : 0) + (kk << 5);
        int bc = ((seg == 2) ? K : 0) + (kk << 5);
        uint32_t sa = sbase + stage * STAGE_BYTES;
        uint32_t sb = sa + A_BYTES;
        #pragma unroll
        for (int it = 0; it < A_CH; it++){
            int idx = tid + it * THREADS;
            int r = idx >> 2, ch = idx & 3;
            cp_async16(sa + r * 80 + ch * 16, Ab + (size_t)r * lda + ac + ch * 8);
        }
        #pragma unroll
        for (int it = 0; it < B_CH; it++){
            int idx = tid + it * THREADS;
            int r = idx >> 2, ch = idx & 3;
            cp_async16(sb + r * 80 + ch * 16, Bb + (size_t)r * lda + bc + ch * 8);
        }
    };

    #pragma unroll
    for (int s = 0; s < STAGES - 1; s++){
        if (s < nch) load_chunk(s, s);
        cp_commit();
    }

    for (int t = 0; t < nch; t++){
        cp_wait<STAGES - 2>();
        __syncthreads();
        const int pf = t + STAGES - 1;
        if (pf < nch) load_chunk(pf, pf % STAGES);
        cp_commit();

        const uint32_t sa = sbase + (t % STAGES) * STAGE_BYTES;
        const uint32_t sb = sa + A_BYTES;
        #pragma unroll
        for (int ks = 0; ks < 2; ks++){
            uint32_t a[4][4], b[4][2];
            #pragma unroll
            for (int mf = 0; mf < 4; mf++){
                int r = wm * 64 + mf * 16 + (lane & 15);
                int col = ks * 16 + (lane >> 4) * 8;
                ldm_x4(sa + r * 80 + col * 2, a[mf][0], a[mf][1], a[mf][2], a[mf][3]);
            }
            #pragma unroll
            for (int g = 0; g < 2; g++){
                int r = wn * 32 + g * 16 + ((lane >> 4) << 3) + (lane & 7);
                int col = ks * 16 + ((lane >> 3) & 1) * 8;
                ldm_x4(sb + r * 80 + col * 2,
                       b[2*g][0], b[2*g][1], b[2*g+1][0], b[2*g+1][1]);
            }
            #pragma unroll
            for (int mf = 0; mf < 4; mf++)
                #pragma unroll
                for (int nf = 0; nf < 4; nf++)
                    mma_bf16(c[mf][nf][0], c[mf][nf][1], c[mf][nf][2], c[mf][nf][3],
                             a[mf][0], a[mf][1], a[mf][2], a[mf][3],
                             b[nf][0], b[nf][1]);
        }
    }

    // epilogue
    #pragma unroll
    for (int mf = 0; mf < 4; mf++){
        #pragma unroll
        for (int half = 0; half < 2; half++){
            const int row = m0 + wm * 64 + mf * 16 + (lane >> 2) + half * 8;
            #pragma unroll
            for (int nf = 0; nf < 4; nf++){
                const int col = n0 + wn * 32 + nf * 8 + (lane & 3) * 2;
                float fx = c[mf][nf][half * 2 + 0];
                float fy = c[mf][nf][half * 2 + 1];
                if (mode == 1){
                    fx = fx / (1.f + __expf(-fx));
                    fy = fy / (1.f + __expf(-fy));
                }
                if (mode != 1){
                    *(float2*)&Cf[(size_t)row * Ntot + col] = make_float2(fx, fy);
                }
                if (mode != 0){
                    __nv_bfloat16 hx, hy, lx, ly;
                    split2(fx, hx, lx);
                    split2(fy, hy, ly);
                    __nv_bfloat162 hp = __halves2bfloat162(hx, hy);
                    __nv_bfloat162 lp = __halves2bfloat162(lx, ly);
                    size_t rb = (size_t)row * (2 * Ntot);
                    *(__nv_bfloat162*)&Csp[rb + col]        = hp;
                    *(__nv_bfloat162*)&Csp[rb + Ntot + col] = lp;
                }
            }
        }
    }
}

// ---------------- fused attention (qkv packed; split-bf16 output) ----------
__global__ void __launch_bounds__(128)
attn_kernel(const float* __restrict__ qkv,
            const int*   __restrict__ dist, const int* __restrict__ phi,
            const float* __restrict__ dtab, const float* __restrict__ ptab,
            const float* __restrict__ Wb,   __nv_bfloat16* __restrict__ osp)
{
    const int h = blockIdx.x;
    const int m = blockIdx.y;
    const int t = threadIdx.x;

    __shared__ float qs[32][65], ks[32][65], vs[32][65];
    __shared__ float sc[32][33];
    __shared__ float wb[32];

    const size_t base = (size_t)m * NH * 1536 + (size_t)h * HD;
    for (int e = t; e < NH * HD; e += 128){
        int i = e >> 6, d = e & 63;
        size_t idx = base + (size_t)i * 1536 + d;
        qs[i][d] = qkv[idx];
        ks[i][d] = qkv[idx + 512];
        vs[i][d] = qkv[idx + 1024];
    }
    if (t < 32) wb[t] = Wb[t * HEADS + h];
    __syncthreads();

    const int i  = t >> 2;
    const int j0 = (t & 3) * 8;
    const int* dr = dist + (size_t)m * (NH*NH) + i * NH;
    const int* fr = phi  + (size_t)m * (NH*NH) + i * NH;

    #pragma unroll
    for (int jj = 0; jj < 8; jj++){
        const int j = j0 + jj;
        float s = 0.f;
        #pragma unroll
        for (int d = 0; d < HD; d++) s += qs[i][d] * ks[j][d];
        const float* dp = dtab + (size_t)dr[j] * 32;
        const float* fp = ptab + (size_t)fr[j] * 32;
        float bsum = 0.f;
        #pragma unroll
        for (int p = 0; p < 32; p++) bsum += dp[p] * fp[p] * wb[p];
        sc[i][j] = s * 0.125f + bsum;
    }
    __syncthreads();

    float mx = -1e30f;
    #pragma unroll
    for (int jj = 0; jj < 8; jj++) mx = fmaxf(mx, sc[i][j0 + jj]);
    mx = fmaxf(mx, __shfl_xor_sync(0xffffffffu, mx, 1));
    mx = fmaxf(mx, __shfl_xor_sync(0xffffffffu, mx, 2));
    float ev[8], sum = 0.f;
    #pragma unroll
    for (int jj = 0; jj < 8; jj++){ ev[jj] = __expf(sc[i][j0 + jj] - mx); sum += ev[jj]; }
    sum += __shfl_xor_sync(0xffffffffu, sum, 1);
    sum += __shfl_xor_sync(0xffffffffu, sum, 2);
    const float inv = 1.f / sum;
    #pragma unroll
    for (int jj = 0; jj < 8; jj++) sc[i][j0 + jj] = ev[jj] * inv;
    __syncthreads();

    const int dseg = (t & 3) * 16;
    float accv[16];
    #pragma unroll
    for (int dd = 0; dd < 16; dd++) accv[dd] = 0.f;
    for (int j = 0; j < NH; j++){
        const float p = sc[i][j];
        #pragma unroll
        for (int dd = 0; dd < 16; dd++) accv[dd] += p * vs[j][dseg + dd];
    }
    // split-bf16 output, row stride 1024 = [hi(512) | lo(512)]
    size_t rb = ((size_t)m * NH + i) * 1024 + (size_t)h * HD + dseg;
    #pragma unroll
    for (int dd = 0; dd < 16; dd += 2){
        __nv_bfloat16 hx, hy, lx, ly;
        split2(accv[dd],   hx, lx);
        split2(accv[dd+1], hy, ly);
        *(__nv_bfloat162*)&osp[rb + dd]       = __halves2bfloat162(hx, hy);
        *(__nv_bfloat162*)&osp[rb + 512 + dd] = __halves2bfloat162(lx, ly);
    }
}

// ---------------- fused residual add + LayerNorm (+optional split out) ----
__global__ void __launch_bounds__(128)
add_ln_kernel2(const float* __restrict__ a, const float* __restrict__ b,
               const float* __restrict__ g, const float* __restrict__ be,
               float* __restrict__ outf, __nv_bfloat16* __restrict__ outsp)
{
    const int row = blockIdx.x;
    const int t   = threadIdx.x;
    const size_t off = (size_t)row * MDIM + t * 4;

    float4 va = *(const float4*)(a + off);
    float4 vb = *(const float4*)(b + off);
    float4 vv = make_float4(va.x + vb.x, va.y + vb.y, va.z + vb.z, va.w + vb.w);

    float s  = vv.x + vv.y + vv.z + vv.w;
    float ss = vv.x*vv.x + vv.y*vv.y + vv.z*vv.z + vv.w*vv.w;
    #pragma unroll
    for (int o2 = 16; o2; o2 >>= 1){
        s  += __shfl_xor_sync(0xffffffffu, s,  o2);
        ss += __shfl_xor_sync(0xffffffffu, ss, o2);
    }
    __shared__ float sh_s[4], sh_ss[4];
    const int w = t >> 5, l = t & 31;
    if (l == 0){ sh_s[w] = s; sh_ss[w] = ss; }
    __syncthreads();
    s  = sh_s[0]  + sh_s[1]  + sh_s[2]  + sh_s[3];
    ss = sh_ss[0] + sh_ss[1] + sh_ss[2] + sh_ss[3];

    const float mean = s * (1.f / 512.f);
    const float var  = ss * (1.f / 512.f) - mean * mean;
    const float rstd = rsqrtf(var + 1e-5f);

    float4 vg  = *(const float4*)(g  + t*4);
    float4 vbe = *(const float4*)(be + t*4);
    float4 r;
    r.x = (vv.x - mean) * rstd * vg.x + vbe.x;
    r.y = (vv.y - mean) * rstd * vg.y + vbe.y;
    r.z = (vv.z - mean) * rstd * vg.z + vbe.z;
    r.w = (vv.w - mean) * rstd * vg.w + vbe.w;
    if (outf) *(float4*)(outf + off) = r;
    if (outsp){
        __nv_bfloat16 h0,h1,h2,h3,l0,l1,l2,l3;
        split2(r.x,h0,l0); split2(r.y,h1,l1); split2(r.z,h2,l2); split2(r.w,h3,l3);
        __nv_bfloat162 hA = __halves2bfloat162(h0,h1), hB = __halves2bfloat162(h2,h3);
        __nv_bfloat162 lA = __halves2bfloat162(l0,l1), lB = __halves2bfloat162(l2,l3);
        size_t rb = (size_t)row * 1024 + t * 4;
        *(uint2*)(outsp + rb)       = make_uint2(*(uint32_t*)&hA, *(uint32_t*)&hB);
        *(uint2*)(outsp + rb + 512) = make_uint2(*(uint32_t*)&lA, *(uint32_t*)&lB);
    }
}

// ---------------- driver ----------------
extern "C" void kernel_launch(void* const* d_in, const int* in_sizes, int n_in,
                              void* d_out, int out_size)
{
    (void)in_sizes; (void)n_in; (void)out_size;

    const float* x    = (const float*)d_in[0];
    const int*   dist = (const int*)  d_in[1];
    const int*   phis = (const int*)  d_in[2];
    const float* W_in = (const float*)d_in[3];
    const float* dtab = (const float*)d_in[4];
    const float* ptab = (const float*)d_in[5];
    const float* Wb   = (const float*)d_in[6];
    const float* Wq   = (const float*)d_in[7];
    const float* Wk   = (const float*)d_in[8];
    const float* Wv   = (const float*)d_in[9];
    const float* Wo   = (const float*)d_in[10];
    const float* Wf1  = (const float*)d_in[11];
    const float* Wf2  = (const float*)d_in[12];
    const float* g1   = (const float*)d_in[13];
    const float* b1   = (const float*)d_in[14];
    const float* g2   = (const float*)d_in[15];
    const float* b2   = (const float*)d_in[16];
    const float* Wout = (const float*)d_in[17];
    float* out = (float*)d_out;

    float *pf0, *pqkv;
    __nv_bfloat16 *pa1, *pa2, *pwin, *pwqkv, *pwo, *pwf1, *pwf2, *pwout;
    cudaGetSymbolAddress((void**)&pf0,  g_f0);
    cudaGetSymbolAddress((void**)&pqkv, g_qkv);
    cudaGetSymbolAddress((void**)&pa1,  g_a1);
    cudaGetSymbolAddress((void**)&pa2,  g_a2);
    cudaGetSymbolAddress((void**)&pwin, g_win2);
    cudaGetSymbolAddress((void**)&pwqkv,g_wqkv2);
    cudaGetSymbolAddress((void**)&pwo,  g_wo2);
    cudaGetSymbolAddress((void**)&pwf1, g_wf12);
    cudaGetSymbolAddress((void**)&pwf2, g_wf22);
    cudaGetSymbolAddress((void**)&pwout,g_wout2);

    float* att_out = pqkv;                       // aliases (sequential deps)
    float* h1      = pqkv + (size_t)TOK * 512;
    float* ff2     = pqkv + (size_t)TOK * 1024;

    const int SM8 = (128 + 256) * 80 * 3;   // 92160
    const int SM4 = (128 + 128) * 80 * 3;   // 61440
    cudaFuncSetAttribute(mma_gemm<8>, cudaFuncAttributeMaxDynamicSharedMemorySize, SM8);
    cudaFuncSetAttribute(mma_gemm<4>, cudaFuncAttributeMaxDynamicSharedMemorySize, SM4);

    const unsigned MT = TOK / 128;   // 1024 m-tiles

    // 0) ALL weight conversions in one launch ([hi|lo], length-2K rows by N)
    WtTable tab;
    tab.d[0] = { W_in, pwin,                      128,  512 };
    tab.d[1] = { Wq,   pwqkv,                     512,  512 };
    tab.d[2] = { Wk,   pwqkv + (size_t)512*1024,  512,  512 };
    tab.d[3] = { Wv,   pwqkv + (size_t)1024*1024, 512,  512 };
    tab.d[4] = { Wo,   pwo,                       512,  512 };
    tab.d[5] = { Wf1,  pwf1,                      512, 2048 };
    tab.d[6] = { Wf2,  pwf2,                     2048,  512 };
    tab.d[7] = { Wout, pwout,                     512,  128 };
    {
        // max total = 2048*1024 elements -> 8192 blocks of 256
        split_wt_all<<<dim3(8192, 8), 256>>>(tab);
    }
    // 1) split x -> a2  [TOK, 256]
    {
        size_t total = (size_t)TOK * 128 / 4;
        split_act<<<(unsigned)((total + 255) / 256), 256>>>(x, pa2, 128, total);
    }
    // 2) h = x @ W_in -> f0 (fp32) + split -> a1
    mma_gemm<8><<<dim3(2, MT), 512, SM8>>>(pa2, pwin, pf0, pa1, 128, 512, 2);
    // 3) qkv = h @ Wqkv -> qkv fp32 [TOK,1536]
    mma_gemm<8><<<dim3(6, MT), 512, SM8>>>(pa1, pwqkv, pqkv, nullptr, 512, 1536, 0);
    // 4) attention -> split o -> a1
    attn_kernel<<<dim3(HEADS, MCNT), 128>>>(pqkv, dist, phis, dtab, ptab, Wb, pa1);
    // 5) att_out = o @ Wo -> fp32  [ncu -s 5 lands HERE]
    mma_gemm<8><<<dim3(2, MT), 512, SM8>>>(pa1, pwo, att_out, nullptr, 512, 512, 0);
    // 6) h1 = LN(h + att_out) -> fp32 h1 + split -> a1
    add_ln_kernel2<<<TOK, 128>>>(pf0, att_out, g1, b1, h1, pa1);
    // 7) ff = silu(h1 @ Wf1) -> split -> a2
    mma_gemm<8><<<dim3(8, MT), 512, SM8>>>(pa1, pwf1, nullptr, pa2, 512, 2048, 1);
    // 8) ff2 = ff @ Wf2 -> fp32
    mma_gemm<8><<<dim3(2, MT), 512, SM8>>>(pa2, pwf2, ff2, nullptr, 2048, 512, 0);
    // 9) h2 = LN(h1 + ff2) -> split only -> a1
    add_ln_kernel2<<<TOK, 128>>>(h1, ff2, g2, b2, nullptr, pa1);
    // 10) out = h2 @ W_out
    mma_gemm<4><<<dim3(1, MT), 256, SM4>>>(pa1, pwout, out, nullptr, 512, 128, 0);
}

// round 9
// speedup vs baseline: 2.1874x; 1.4906x over previous
#include <cuda_runtime.h>
#include <cuda_bf16.h>
#include <cstdint>
#include <math.h>

// ---------------- problem constants ----------------
#define TOK   131072          // B*N*NH tokens
#define MDIM  512
#define FFD   2048
#define MCNT  4096
#define NH    32
#define HEADS 8
#define HD    64

// ---------------- helpers ----------------
__device__ __forceinline__ uint32_t smem_to_u32(const void* p){
    uint32_t a;
    asm("{ .reg .u64 t; cvta.to.shared.u64 t, %1; cvt.u32.u64 %0, t; }" : "=r"(a) : "l"(p));
    return a;
}
__device__ __forceinline__ void cp_async16(uint32_t saddr, const void* gaddr){
    asm volatile("cp.async.cg.shared.global [%0], [%1], 16;" :: "r"(saddr), "l"(gaddr));
}
__device__ __forceinline__ void cp_commit(){ asm volatile("cp.async.commit_group;"); }
template<int N>
__device__ __forceinline__ void cp_wait(){ asm volatile("cp.async.wait_group %0;" :: "n"(N)); }

__device__ __forceinline__ void ldm_x4(uint32_t addr, uint32_t& r0, uint32_t& r1,
                                       uint32_t& r2, uint32_t& r3){
    asm volatile("ldmatrix.sync.aligned.m8n8.x4.shared.b16 {%0,%1,%2,%3}, [%4];"
        : "=r"(r0), "=r"(r1), "=r"(r2), "=r"(r3) : "r"(addr));
}
__device__ __forceinline__ void mma_bf16(float& c0, float& c1, float& c2, float& c3,
                                         uint32_t a0, uint32_t a1, uint32_t a2, uint32_t a3,
                                         uint32_t b0, uint32_t b1){
    asm volatile("mma.sync.aligned.m16n8k16.row.col.f32.bf16.bf16.f32 "
        "{%0,%1,%2,%3}, {%4,%5,%6,%7}, {%8,%9}, {%0,%1,%2,%3};"
        : "+f"(c0), "+f"(c1), "+f"(c2), "+f"(c3)
        : "r"(a0), "r"(a1), "r"(a2), "r"(a3), "r"(b0), "r"(b1));
}
__device__ __forceinline__ void split2(float f, __nv_bfloat16& h, __nv_bfloat16& l){
    h = __float2bfloat16(f);
    l = __float2bfloat16(f - __bfloat162float(h));
}

// ---------------- scratch (~2.3 GB) ----------------
__device__ __align__(256) float g_f0 [TOK*MDIM];          // h (residual)
__device__ __align__(256) float g_qkv[(size_t)TOK*1536];  // qkv / att_out / h1 / ff2
__device__ __align__(256) __nv_bfloat16 g_a1[(size_t)TOK*1024];  // split 512-wide acts
__device__ __align__(256) __nv_bfloat16 g_a2[(size_t)TOK*4096];  // split ff / x acts
__device__ __align__(256) __nv_bfloat16 g_win2 [512*256];
__device__ __align__(256) __nv_bfloat16 g_wqkv2[(size_t)1536*1024];
__device__ __align__(256) __nv_bfloat16 g_wo2  [512*1024];
__device__ __align__(256) __nv_bfloat16 g_wf12 [(size_t)2048*1024];
__device__ __align__(256) __nv_bfloat16 g_wf22 [(size_t)512*4096];
__device__ __align__(256) __nv_bfloat16 g_wout2[128*1024];

// ---------------- fused weight conversion (ONE launch for all 8) ----------
struct WtDesc { const float* W; __nv_bfloat16* Y; int K; int N; };
struct WtTable { WtDesc d[8]; };

__global__ void __launch_bounds__(256)
split_wt_all(WtTable tab)
{
    const WtDesc& e = tab.d[blockIdx.y];
    size_t total = (size_t)e.N * 2 * e.K;
    size_t id = (size_t)blockIdx.x * 256 + threadIdx.x;
    if (id >= total) return;
    int K2 = 2 * e.K;
    size_t n = id / K2;
    int c = (int)(id % K2);
    int reg = c >= e.K, cs = c - (reg ? e.K : 0);
    float x = e.W[(size_t)cs * e.N + n];
    __nv_bfloat16 h, l;
    split2(x, h, l);
    e.Y[id] = reg ? l : h;
}

// ---------------- split conversion: activations (x only) ----------------
__global__ void __launch_bounds__(256)
split_act(const float* __restrict__ X, __nv_bfloat16* __restrict__ Y,
          int K, size_t total /* R*K/4 */)
{
    size_t id = (size_t)blockIdx.x * 256 + threadIdx.x;
    if (id >= total) return;
    int kq = K >> 2;
    size_t r = id / kq;
    int c = (int)(id % kq) << 2;
    float4 x = *(const float4*)(X + r * K + c);
    __nv_bfloat16 h0,h1,h2,h3,l0,l1,l2,l3;
    split2(x.x,h0,l0); split2(x.y,h1,l1); split2(x.z,h2,l2); split2(x.w,h3,l3);
    __nv_bfloat162 hA = __halves2bfloat162(h0,h1), hB = __halves2bfloat162(h2,h3);
    __nv_bfloat162 lA = __halves2bfloat162(l0,l1), lB = __halves2bfloat162(l2,l3);
    size_t ob = r * (size_t)(2 * K);
    *(uint2*)(Y + ob + c)     = make_uint2(*(uint32_t*)&hA, *(uint32_t*)&hB);
    *(uint2*)(Y + ob + K + c) = make_uint2(*(uint32_t*)&lA, *(uint32_t*)&lB);
}

// ---------------- mma.sync bf16 GEMM, 3-segment split schedule ----------------
// A [M, 2K] = [hi|lo], Bt [Ntot, 2K] = [hi|lo] (K-major rows).
// Segments: (Ahi,Bhi), (Alo,Bhi), (Ahi,Blo) accumulated in registers.
// CTA tile 128 x (32*NFRAG); 8 warps (2x4); warp tile 64 x (8*NFRAG); BK=32;
// 4-stage cp.async pipeline. mode: 0=f32, 1=silu+split, 2=f32+split.
template<int NFRAG>
__global__ void __launch_bounds__(256)
mma_gemm(const __nv_bfloat16* __restrict__ A, const __nv_bfloat16* __restrict__ Bt,
         float* __restrict__ Cf, __nv_bfloat16* __restrict__ Csp,
         int K, int Ntot, int mode)
{
    constexpr int BN = 32 * NFRAG;
    constexpr int WNW = 8 * NFRAG;       // warp n-width
    constexpr int THREADS = 256;
    constexpr int STAGES = 4;
    constexpr int A_BYTES = 128 * 80;
    constexpr int STAGE_BYTES = (128 + BN) * 80;
    constexpr int A_CH = (128 * 4) / THREADS;
    constexpr int B_CH = (BN * 4) / THREADS;
    extern __shared__ __align__(16) char smem[];

    const int tid  = threadIdx.x;
    const int lane = tid & 31;
    const int wid  = tid >> 5;
    const int wm   = wid >> 2;        // 0..1
    const int wn   = wid & 3;         // 0..3
    const int m0   = blockIdx.y * 128;
    const int n0   = blockIdx.x * BN;

    const int lda = 2 * K;
    const __nv_bfloat16* Ab = A  + (size_t)m0 * lda;
    const __nv_bfloat16* Bb = Bt + (size_t)n0 * lda;
    const uint32_t sbase = smem_to_u32(smem);

    float c[4][NFRAG][4];
    #pragma unroll
    for (int i = 0; i < 4; i++)
        #pragma unroll
        for (int j = 0; j < NFRAG; j++)
            #pragma unroll
            for (int q = 0; q < 4; q++) c[i][j][q] = 0.f;

    const int kch = K >> 5;
    const int nch = 3 * kch;

    auto load_chunk = [&](int tt, int stage){
        int seg = (tt >= kch) + (tt >= 2 * kch);
        int kk = tt - seg * kch;
        int ac = ((seg == 1) ? K : 0) + (kk << 5);
        int bc = ((seg == 2) ? K : 0) + (kk << 5);
        uint32_t sa = sbase + stage * STAGE_BYTES;
        uint32_t sb = sa + A_BYTES;
        #pragma unroll
        for (int it = 0; it < A_CH; it++){
            int idx = tid + it * THREADS;
            int r = idx >> 2, ch = idx & 3;
            cp_async16(sa + r * 80 + ch * 16, Ab + (size_t)r * lda + ac + ch * 8);
        }
        #pragma unroll
        for (int it = 0; it < B_CH; it++){
            int idx = tid + it * THREADS;
            int r = idx >> 2, ch = idx & 3;
            cp_async16(sb + r * 80 + ch * 16, Bb + (size_t)r * lda + bc + ch * 8);
        }
    };

    #pragma unroll
    for (int s = 0; s < STAGES - 1; s++){
        if (s < nch) load_chunk(s, s);
        cp_commit();
    }

    for (int t = 0; t < nch; t++){
        cp_wait<STAGES - 2>();
        __syncthreads();
        const int pf = t + STAGES - 1;
        if (pf < nch) load_chunk(pf, pf % STAGES);
        cp_commit();

        const uint32_t sa = sbase + (t % STAGES) * STAGE_BYTES;
        const uint32_t sb = sa + A_BYTES;
        #pragma unroll
        for (int ks = 0; ks < 2; ks++){
            uint32_t a[4][4], b[NFRAG][2];
            #pragma unroll
            for (int mf = 0; mf < 4; mf++){
                int r = wm * 64 + mf * 16 + (lane & 15);
                int col = ks * 16 + (lane >> 4) * 8;
                ldm_x4(sa + r * 80 + col * 2, a[mf][0], a[mf][1], a[mf][2], a[mf][3]);
            }
            #pragma unroll
            for (int g = 0; g < NFRAG / 2; g++){
                int r = wn * WNW + g * 16 + ((lane >> 4) << 3) + (lane & 7);
                int col = ks * 16 + ((lane >> 3) & 1) * 8;
                ldm_x4(sb + r * 80 + col * 2,
                       b[2*g][0], b[2*g][1], b[2*g+1][0], b[2*g+1][1]);
            }
            #pragma unroll
            for (int mf = 0; mf < 4; mf++)
                #pragma unroll
                for (int nf = 0; nf < NFRAG; nf++)
                    mma_bf16(c[mf][nf][0], c[mf][nf][1], c[mf][nf][2], c[mf][nf][3],
                             a[mf][0], a[mf][1], a[mf][2], a[mf][3],
                             b[nf][0], b[nf][1]);
        }
    }

    // epilogue
    #pragma unroll
    for (int mf = 0; mf < 4; mf++){
        #pragma unroll
        for (int half = 0; half < 2; half++){
            const int row = m0 + wm * 64 + mf * 16 + (lane >> 2) + half * 8;
            #pragma unroll
            for (int nf = 0; nf < NFRAG; nf++){
                const int col = n0 + wn * WNW + nf * 8 + (lane & 3) * 2;
                float fx = c[mf][nf][half * 2 + 0];
                float fy = c[mf][nf][half * 2 + 1];
                if (mode == 1){
                    fx = fx / (1.f + __expf(-fx));
                    fy = fy / (1.f + __expf(-fy));
                }
                if (mode != 1){
                    *(float2*)&Cf[(size_t)row * Ntot + col] = make_float2(fx, fy);
                }
                if (mode != 0){
                    __nv_bfloat16 hx, hy, lx, ly;
                    split2(fx, hx, lx);
                    split2(fy, hy, ly);
                    __nv_bfloat162 hp = __halves2bfloat162(hx, hy);
                    __nv_bfloat162 lp = __halves2bfloat162(lx, ly);
                    size_t rb = (size_t)row * (2 * Ntot);
                    *(__nv_bfloat162*)&Csp[rb + col]        = hp;
                    *(__nv_bfloat162*)&Csp[rb + Ntot + col] = lp;
                }
            }
        }
    }
}

// ---------------- fused attention: one block per m, all 8 heads ------------
// Bias gathered ONCE per (i,j) pair (float4 loads), expanded to all heads.
__global__ void __launch_bounds__(256)
attn_kernel(const float* __restrict__ qkv,
            const int*   __restrict__ dist, const int* __restrict__ phi,
            const float* __restrict__ dtab, const float* __restrict__ ptab,
            const float* __restrict__ Wb,   __nv_bfloat16* __restrict__ osp)
{
    extern __shared__ float sm[];
    float* bias8 = sm;              // [h*1056 + i*33 + j]  (8448)
    float* qs    = sm + 8448;       // [i*68 + d]           (2176)
    float* ks    = sm + 10624;      // (2176)
    float* vs    = sm + 12800;      // (2176)
    float* sc    = sm + 14976;      // [i*33 + j]           (1056)
    float* wb8   = sm + 16032;      // [p*8 + h]            (256)

    const int m = blockIdx.x;
    const int t = threadIdx.x;

    wb8[t] = Wb[t];                 // 256 = PED*HEADS
    __syncthreads();

    // ---- bias for all heads: 4 pairs per thread ----
    const int base_mm = m * (NH * NH);
    #pragma unroll
    for (int q4 = 0; q4 < 4; q4++){
        int pair = t * 4 + q4;              // 0..1023
        int i = pair >> 5, j = pair & 31;
        int id = dist[base_mm + pair];
        int ip = phi [base_mm + pair];
        const float4* dp = (const float4*)(dtab + (size_t)id * 32);
        const float4* fp = (const float4*)(ptab + (size_t)ip * 32);
        float acc[8];
        #pragma unroll
        for (int h = 0; h < 8; h++) acc[h] = 0.f;
        #pragma unroll
        for (int v4 = 0; v4 < 8; v4++){
            float4 d4 = dp[v4];
            float4 f4 = fp[v4];
            float pr[4] = { d4.x*f4.x, d4.y*f4.y, d4.z*f4.z, d4.w*f4.w };
            #pragma unroll
            for (int pp = 0; pp < 4; pp++){
                int p = v4 * 4 + pp;
                #pragma unroll
                for (int h = 0; h < 8; h++)
                    acc[h] += pr[pp] * wb8[p * 8 + h];
            }
        }
        #pragma unroll
        for (int h = 0; h < 8; h++) bias8[h * 1056 + i * 33 + j] = acc[h];
    }

    const int i = t >> 3;          // row 0..31
    const int g = t & 7;           // group 0..7

    for (int h = 0; h < 8; h++){
        __syncthreads();   // bias ready (h=0) / prior head done (h>0)
        // load q,k,v head slices (32 rows x 16 float4 each), vectorized
        #pragma unroll
        for (int it = 0; it < 2; it++){
            int idx = t + it * 256;        // 0..511
            int r  = idx >> 4;             // row 0..31
            int c4 = idx & 15;             // float4 within row 0..15
            size_t gb = (size_t)(m * NH + r) * 1536 + h * 64 + c4 * 4;
            *(float4*)(qs + r * 68 + c4 * 4) = *(const float4*)(qkv + gb);
            *(float4*)(ks + r * 68 + c4 * 4) = *(const float4*)(qkv + gb + 512);
            *(float4*)(vs + r * 68 + c4 * 4) = *(const float4*)(qkv + gb + 1024);
        }
        __syncthreads();

        // scores: 4 j's per thread
        float sv[4];
        #pragma unroll
        for (int jj = 0; jj < 4; jj++){
            int j = g * 4 + jj;
            float s = 0.f;
            #pragma unroll
            for (int d4 = 0; d4 < 16; d4++){
                float4 qa = *(float4*)(qs + i * 68 + d4 * 4);
                float4 ka = *(float4*)(ks + j * 68 + d4 * 4);
                s += qa.x*ka.x + qa.y*ka.y + qa.z*ka.z + qa.w*ka.w;
            }
            sv[jj] = s * 0.125f + bias8[h * 1056 + i * 33 + j];
        }
        // softmax across the 8 threads of row i (lanes contiguous in warp)
        float mx = fmaxf(fmaxf(sv[0], sv[1]), fmaxf(sv[2], sv[3]));
        mx = fmaxf(mx, __shfl_xor_sync(0xffffffffu, mx, 1));
        mx = fmaxf(mx, __shfl_xor_sync(0xffffffffu, mx, 2));
        mx = fmaxf(mx, __shfl_xor_sync(0xffffffffu, mx, 4));
        float ev[4], sum = 0.f;
        #pragma unroll
        for (int jj = 0; jj < 4; jj++){ ev[jj] = __expf(sv[jj] - mx); sum += ev[jj]; }
        sum += __shfl_xor_sync(0xffffffffu, sum, 1);
        sum += __shfl_xor_sync(0xffffffffu, sum, 2);
        sum += __shfl_xor_sync(0xffffffffu, sum, 4);
        const float inv = 1.f / sum;
        #pragma unroll
        for (int jj = 0; jj < 4; jj++) sc[i * 33 + g * 4 + jj] = ev[jj] * inv;
        __syncwarp();

        // AV: thread owns d-segment g*8 .. g*8+7 of row i
        const int dseg = g * 8;
        float acc[8];
        #pragma unroll
        for (int dd = 0; dd < 8; dd++) acc[dd] = 0.f;
        for (int j = 0; j < NH; j++){
            float p = sc[i * 33 + j];
            float4 v0 = *(float4*)(vs + j * 68 + dseg);
            float4 v1 = *(float4*)(vs + j * 68 + dseg + 4);
            acc[0] += p * v0.x; acc[1] += p * v0.y;
            acc[2] += p * v0.z; acc[3] += p * v0.w;
            acc[4] += p * v1.x; acc[5] += p * v1.y;
            acc[6] += p * v1.z; acc[7] += p * v1.w;
        }
        // split-bf16 output, row stride 1024 = [hi(512) | lo(512)]
        size_t rb = ((size_t)(m * NH) + i) * 1024 + h * 64 + dseg;
        #pragma unroll
        for (int dd = 0; dd < 8; dd += 2){
            __nv_bfloat16 hx, hy, lx, ly;
            split2(acc[dd],   hx, lx);
            split2(acc[dd+1], hy, ly);
            *(__nv_bfloat162*)&osp[rb + dd]       = __halves2bfloat162(hx, hy);
            *(__nv_bfloat162*)&osp[rb + 512 + dd] = __halves2bfloat162(lx, ly);
        }
    }
}

// ---------------- fused residual add + LayerNorm (+optional split out) ----
__global__ void __launch_bounds__(128)
add_ln_kernel2(const float* __restrict__ a, const float* __restrict__ b,
               const float* __restrict__ g, const float* __restrict__ be,
               float* __restrict__ outf, __nv_bfloat16* __restrict__ outsp)
{
    const int row = blockIdx.x;
    const int t   = threadIdx.x;
    const size_t off = (size_t)row * MDIM + t * 4;

    float4 va = *(const float4*)(a + off);
    float4 vb = *(const float4*)(b + off);
    float4 vv = make_float4(va.x + vb.x, va.y + vb.y, va.z + vb.z, va.w + vb.w);

    float s  = vv.x + vv.y + vv.z + vv.w;
    float ss = vv.x*vv.x + vv.y*vv.y + vv.z*vv.z + vv.w*vv.w;
    #pragma unroll
    for (int o2 = 16; o2; o2 >>= 1){
        s  += __shfl_xor_sync(0xffffffffu, s,  o2);
        ss += __shfl_xor_sync(0xffffffffu, ss, o2);
    }
    __shared__ float sh_s[4], sh_ss[4];
    const int w = t >> 5, l = t & 31;
    if (l == 0){ sh_s[w] = s; sh_ss[w] = ss; }
    __syncthreads();
    s  = sh_s[0]  + sh_s[1]  + sh_s[2]  + sh_s[3];
    ss = sh_ss[0] + sh_ss[1] + sh_ss[2] + sh_ss[3];

    const float mean = s * (1.f / 512.f);
    const float var  = ss * (1.f / 512.f) - mean * mean;
    const float rstd = rsqrtf(var + 1e-5f);

    float4 vg  = *(const float4*)(g  + t*4);
    float4 vbe = *(const float4*)(be + t*4);
    float4 r;
    r.x = (vv.x - mean) * rstd * vg.x + vbe.x;
    r.y = (vv.y - mean) * rstd * vg.y + vbe.y;
    r.z = (vv.z - mean) * rstd * vg.z + vbe.z;
    r.w = (vv.w - mean) * rstd * vg.w + vbe.w;
    if (outf) *(float4*)(outf + off) = r;
    if (outsp){
        __nv_bfloat16 h0,h1,h2,h3,l0,l1,l2,l3;
        split2(r.x,h0,l0); split2(r.y,h1,l1); split2(r.z,h2,l2); split2(r.w,h3,l3);
        __nv_bfloat162 hA = __halves2bfloat162(h0,h1), hB = __halves2bfloat162(h2,h3);
        __nv_bfloat162 lA = __halves2bfloat162(l0,l1), lB = __halves2bfloat162(l2,l3);
        size_t rb = (size_t)row * 1024 + t * 4;
        *(uint2*)(outsp + rb)       = make_uint2(*(uint32_t*)&hA, *(uint32_t*)&hB);
        *(uint2*)(outsp + rb + 512) = make_uint2(*(uint32_t*)&lA, *(uint32_t*)&lB);
    }
}

// ---------------- driver ----------------
extern "C" void kernel_launch(void* const* d_in, const int* in_sizes, int n_in,
                              void* d_out, int out_size)
{
    (void)in_sizes; (void)n_in; (void)out_size;

    const float* x    = (const float*)d_in[0];
    const int*   dist = (const int*)  d_in[1];
    const int*   phis = (const int*)  d_in[2];
    const float* W_in = (const float*)d_in[3];
    const float* dtab = (const float*)d_in[4];
    const float* ptab = (const float*)d_in[5];
    const float* Wb   = (const float*)d_in[6];
    const float* Wq   = (const float*)d_in[7];
    const float* Wk   = (const float*)d_in[8];
    const float* Wv   = (const float*)d_in[9];
    const float* Wo   = (const float*)d_in[10];
    const float* Wf1  = (const float*)d_in[11];
    const float* Wf2  = (const float*)d_in[12];
    const float* g1   = (const float*)d_in[13];
    const float* b1   = (const float*)d_in[14];
    const float* g2   = (const float*)d_in[15];
    const float* b2   = (const float*)d_in[16];
    const float* Wout = (const float*)d_in[17];
    float* out = (float*)d_out;

    float *pf0, *pqkv;
    __nv_bfloat16 *pa1, *pa2, *pwin, *pwqkv, *pwo, *pwf1, *pwf2, *pwout;
    cudaGetSymbolAddress((void**)&pf0,  g_f0);
    cudaGetSymbolAddress((void**)&pqkv, g_qkv);
    cudaGetSymbolAddress((void**)&pa1,  g_a1);
    cudaGetSymbolAddress((void**)&pa2,  g_a2);
    cudaGetSymbolAddress((void**)&pwin, g_win2);
    cudaGetSymbolAddress((void**)&pwqkv,g_wqkv2);
    cudaGetSymbolAddress((void**)&pwo,  g_wo2);
    cudaGetSymbolAddress((void**)&pwf1, g_wf12);
    cudaGetSymbolAddress((void**)&pwf2, g_wf22);
    cudaGetSymbolAddress((void**)&pwout,g_wout2);

    float* att_out = pqkv;                       // aliases (sequential deps)
    float* h1      = pqkv + (size_t)TOK * 512;
    float* ff2     = pqkv + (size_t)TOK * 1024;

    const int SM8 = (128 + 256) * 80 * 4;   // 122880
    const int SM4 = (128 + 128) * 80 * 4;   // 81920
    const int SMA = 16288 * 4;              // 65152 (attention)
    cudaFuncSetAttribute(mma_gemm<8>, cudaFuncAttributeMaxDynamicSharedMemorySize, SM8);
    cudaFuncSetAttribute(mma_gemm<4>, cudaFuncAttributeMaxDynamicSharedMemorySize, SM4);
    cudaFuncSetAttribute(attn_kernel, cudaFuncAttributeMaxDynamicSharedMemorySize, SMA);

    const unsigned MT = TOK / 128;   // 1024 m-tiles

    // 0) all weight conversions in one launch
    WtTable tab;
    tab.d[0] = { W_in, pwin,                      128,  512 };
    tab.d[1] = { Wq,   pwqkv,                     512,  512 };
    tab.d[2] = { Wk,   pwqkv + (size_t)512*1024,  512,  512 };
    tab.d[3] = { Wv,   pwqkv + (size_t)1024*1024, 512,  512 };
    tab.d[4] = { Wo,   pwo,                       512,  512 };
    tab.d[5] = { Wf1,  pwf1,                      512, 2048 };
    tab.d[6] = { Wf2,  pwf2,                     2048,  512 };
    tab.d[7] = { Wout, pwout,                     512,  128 };
    split_wt_all<<<dim3(8192, 8), 256>>>(tab);

    // 1) split x -> a2  [TOK, 256]
    {
        size_t total = (size_t)TOK * 128 / 4;
        split_act<<<(unsigned)((total + 255) / 256), 256>>>(x, pa2, 128, total);
    }
    // 2) h = x @ W_in -> f0 (fp32) + split -> a1
    mma_gemm<8><<<dim3(2, MT), 256, SM8>>>(pa2, pwin, pf0, pa1, 128, 512, 2);
    // 3) qkv = h @ Wqkv -> fp32 [TOK,1536]
    mma_gemm<8><<<dim3(6, MT), 256, SM8>>>(pa1, pwqkv, pqkv, nullptr, 512, 1536, 0);
    // 4) attention -> split o -> a1
    attn_kernel<<<MCNT, 256, SMA>>>(pqkv, dist, phis, dtab, ptab, Wb, pa1);
    // 5) att_out = o @ Wo -> fp32
    mma_gemm<8><<<dim3(2, MT), 256, SM8>>>(pa1, pwo, att_out, nullptr, 512, 512, 0);
    // 6) h1 = LN(h + att_out) -> fp32 h1 + split -> a1
    add_ln_kernel2<<<TOK, 128>>>(pf0, att_out, g1, b1, h1, pa1);
    // 7) ff = silu(h1 @ Wf1) -> split -> a2
    mma_gemm<8><<<dim3(8, MT), 256, SM8>>>(pa1, pwf1, nullptr, pa2, 512, 2048, 1);
    // 8) ff2 = ff @ Wf2 -> fp32
    mma_gemm<8><<<dim3(2, MT), 256, SM8>>>(pa2, pwf2, ff2, nullptr, 2048, 512, 0);
    // 9) h2 = LN(h1 + ff2) -> split only -> a1
    add_ln_kernel2<<<TOK, 128>>>(h1, ff2, g2, b2, nullptr, pa1);
    // 10) out = h2 @ W_out
    mma_gemm<4><<<dim3(1, MT), 256, SM4>>>(pa1, pwout, out, nullptr, 512, 128, 0);
}

// round 10
// speedup vs baseline: 2.4411x; 1.1160x over previous
#include <cuda_runtime.h>
#include <cuda_bf16.h>
#include <cstdint>
#include <math.h>

// ---------------- problem constants ----------------
#define TOK   131072          // B*N*NH tokens
#define MDIM  512
#define FFD   2048
#define MCNT  4096
#define NH    32
#define HEADS 8
#define HD    64

// ---------------- helpers ----------------
__device__ __forceinline__ uint32_t smem_to_u32(const void* p){
    uint32_t a;
    asm("{ .reg .u64 t; cvta.to.shared.u64 t, %1; cvt.u32.u64 %0, t; }" : "=r"(a) : "l"(p));
    return a;
}
__device__ __forceinline__ void cp_async16(uint32_t saddr, const void* gaddr){
    asm volatile("cp.async.cg.shared.global [%0], [%1], 16;" :: "r"(saddr), "l"(gaddr));
}
__device__ __forceinline__ void cp_commit(){ asm volatile("cp.async.commit_group;"); }
template<int N>
__device__ __forceinline__ void cp_wait(){ asm volatile("cp.async.wait_group %0;" :: "n"(N)); }

__device__ __forceinline__ void ldm_x4(uint32_t addr, uint32_t& r0, uint32_t& r1,
                                       uint32_t& r2, uint32_t& r3){
    asm volatile("ldmatrix.sync.aligned.m8n8.x4.shared.b16 {%0,%1,%2,%3}, [%4];"
        : "=r"(r0), "=r"(r1), "=r"(r2), "=r"(r3) : "r"(addr));
}
__device__ __forceinline__ void mma_bf16(float& c0, float& c1, float& c2, float& c3,
                                         uint32_t a0, uint32_t a1, uint32_t a2, uint32_t a3,
                                         uint32_t b0, uint32_t b1){
    asm volatile("mma.sync.aligned.m16n8k16.row.col.f32.bf16.bf16.f32 "
        "{%0,%1,%2,%3}, {%4,%5,%6,%7}, {%8,%9}, {%0,%1,%2,%3};"
        : "+f"(c0), "+f"(c1), "+f"(c2), "+f"(c3)
        : "r"(a0), "r"(a1), "r"(a2), "r"(a3), "r"(b0), "r"(b1));
}
__device__ __forceinline__ void split2(float f, __nv_bfloat16& h, __nv_bfloat16& l){
    h = __float2bfloat16(f);
    l = __float2bfloat16(f - __bfloat162float(h));
}

// ---------------- scratch (~2.3 GB) ----------------
__device__ __align__(256) float g_f0 [TOK*MDIM];          // h (residual)
__device__ __align__(256) float g_qkv[(size_t)TOK*1536];  // qkv / att_out / h1 / ff2
__device__ __align__(256) __nv_bfloat16 g_a1[(size_t)TOK*1024];  // split 512-wide acts
__device__ __align__(256) __nv_bfloat16 g_a2[(size_t)TOK*4096];  // split ff / x acts
__device__ __align__(256) __nv_bfloat16 g_win2 [512*256];
__device__ __align__(256) __nv_bfloat16 g_wqkv2[(size_t)1536*1024];
__device__ __align__(256) __nv_bfloat16 g_wo2  [512*1024];
__device__ __align__(256) __nv_bfloat16 g_wf12 [(size_t)2048*1024];
__device__ __align__(256) __nv_bfloat16 g_wf22 [(size_t)512*4096];
__device__ __align__(256) __nv_bfloat16 g_wout2[128*1024];

// ---------------- fused weight conversion (ONE launch for all 8) ----------
struct WtDesc { const float* W; __nv_bfloat16* Y; int K; int N; };
struct WtTable { WtDesc d[8]; };

__global__ void __launch_bounds__(256)
split_wt_all(WtTable tab)
{
    const WtDesc& e = tab.d[blockIdx.y];
    size_t total = (size_t)e.N * 2 * e.K;
    size_t id = (size_t)blockIdx.x * 256 + threadIdx.x;
    if (id >= total) return;
    int K2 = 2 * e.K;
    size_t n = id / K2;
    int c = (int)(id % K2);
    int reg = c >= e.K, cs = c - (reg ? e.K : 0);
    float x = e.W[(size_t)cs * e.N + n];
    __nv_bfloat16 h, l;
    split2(x, h, l);
    e.Y[id] = reg ? l : h;
}

// ---------------- split conversion: activations (x only) ----------------
__global__ void __launch_bounds__(256)
split_act(const float* __restrict__ X, __nv_bfloat16* __restrict__ Y,
          int K, size_t total /* R*K/4 */)
{
    size_t id = (size_t)blockIdx.x * 256 + threadIdx.x;
    if (id >= total) return;
    int kq = K >> 2;
    size_t r = id / kq;
    int c = (int)(id % kq) << 2;
    float4 x = *(const float4*)(X + r * K + c);
    __nv_bfloat16 h0,h1,h2,h3,l0,l1,l2,l3;
    split2(x.x,h0,l0); split2(x.y,h1,l1); split2(x.z,h2,l2); split2(x.w,h3,l3);
    __nv_bfloat162 hA = __halves2bfloat162(h0,h1), hB = __halves2bfloat162(h2,h3);
    __nv_bfloat162 lA = __halves2bfloat162(l0,l1), lB = __halves2bfloat162(l2,l3);
    size_t ob = r * (size_t)(2 * K);
    *(uint2*)(Y + ob + c)     = make_uint2(*(uint32_t*)&hA, *(uint32_t*)&hB);
    *(uint2*)(Y + ob + K + c) = make_uint2(*(uint32_t*)&lA, *(uint32_t*)&lB);
}

// ---------------- mma.sync bf16 GEMM, 3-segment split schedule ----------------
// A [M, 2K] = [hi|lo], Bt [Ntot, 2K] = [hi|lo] (K-major rows).
// Segments: (Ahi,Bhi), (Alo,Bhi), (Ahi,Blo) accumulated in registers.
// CTA tile 128x128; 4 warps (2x2); warp tile 64x64; BK=32; 4 stages;
// 128 threads -> 2 CTAs/SM (independent barrier domains overlap bubbles).
// mode: 0=f32, 1=silu+split, 2=f32+split.
__global__ void __launch_bounds__(128)
mma_gemm(const __nv_bfloat16* __restrict__ A, const __nv_bfloat16* __restrict__ Bt,
         float* __restrict__ Cf, __nv_bfloat16* __restrict__ Csp,
         int K, int Ntot, int mode)
{
    constexpr int THREADS = 128;
    constexpr int STAGES = 4;
    constexpr int A_BYTES = 128 * 80;
    constexpr int STAGE_BYTES = 256 * 80;
    constexpr int A_CH = 4;   // (128 rows * 4 chunks) / 128 threads
    constexpr int B_CH = 4;
    extern __shared__ __align__(16) char smem[];

    const int tid  = threadIdx.x;
    const int lane = tid & 31;
    const int wid  = tid >> 5;
    const int wm   = wid >> 1;        // 0..1
    const int wn   = wid & 1;         // 0..1
    const int m0   = blockIdx.y * 128;
    const int n0   = blockIdx.x * 128;

    const int lda = 2 * K;
    const __nv_bfloat16* Ab = A  + (size_t)m0 * lda;
    const __nv_bfloat16* Bb = Bt + (size_t)n0 * lda;
    const uint32_t sbase = smem_to_u32(smem);

    float c[4][8][4];
    #pragma unroll
    for (int i = 0; i < 4; i++)
        #pragma unroll
        for (int j = 0; j < 8; j++)
            #pragma unroll
            for (int q = 0; q < 4; q++) c[i][j][q] = 0.f;

    const int kch = K >> 5;
    const int nch = 3 * kch;

    auto load_chunk = [&](int tt, int stage){
        int seg = (tt >= kch) + (tt >= 2 * kch);
        int kk = tt - seg * kch;
        int ac = ((seg == 1) ? K : 0) + (kk << 5);
        int bc = ((seg == 2) ? K : 0) + (kk << 5);
        uint32_t sa = sbase + stage * STAGE_BYTES;
        uint32_t sb = sa + A_BYTES;
        #pragma unroll
        for (int it = 0; it < A_CH; it++){
            int idx = tid + it * THREADS;
            int r = idx >> 2, ch = idx & 3;
            cp_async16(sa + r * 80 + ch * 16, Ab + (size_t)r * lda + ac + ch * 8);
        }
        #pragma unroll
        for (int it = 0; it < B_CH; it++){
            int idx = tid + it * THREADS;
            int r = idx >> 2, ch = idx & 3;
            cp_async16(sb + r * 80 + ch * 16, Bb + (size_t)r * lda + bc + ch * 8);
        }
    };

    #pragma unroll
    for (int s = 0; s < STAGES - 1; s++){
        if (s < nch) load_chunk(s, s);
        cp_commit();
    }

    for (int t = 0; t < nch; t++){
        cp_wait<STAGES - 2>();
        __syncthreads();
        const int pf = t + STAGES - 1;
        if (pf < nch) load_chunk(pf, pf % STAGES);
        cp_commit();

        const uint32_t sa = sbase + (t % STAGES) * STAGE_BYTES;
        const uint32_t sb = sa + A_BYTES;
        #pragma unroll
        for (int ks = 0; ks < 2; ks++){
            uint32_t a[4][4], b[8][2];
            #pragma unroll
            for (int mf = 0; mf < 4; mf++){
                int r = wm * 64 + mf * 16 + (lane & 15);
                int col = ks * 16 + (lane >> 4) * 8;
                ldm_x4(sa + r * 80 + col * 2, a[mf][0], a[mf][1], a[mf][2], a[mf][3]);
            }
            #pragma unroll
            for (int g = 0; g < 4; g++){
                int r = wn * 64 + g * 16 + ((lane >> 4) << 3) + (lane & 7);
                int col = ks * 16 + ((lane >> 3) & 1) * 8;
                ldm_x4(sb + r * 80 + col * 2,
                       b[2*g][0], b[2*g][1], b[2*g+1][0], b[2*g+1][1]);
            }
            #pragma unroll
            for (int mf = 0; mf < 4; mf++)
                #pragma unroll
                for (int nf = 0; nf < 8; nf++)
                    mma_bf16(c[mf][nf][0], c[mf][nf][1], c[mf][nf][2], c[mf][nf][3],
                             a[mf][0], a[mf][1], a[mf][2], a[mf][3],
                             b[nf][0], b[nf][1]);
        }
    }

    // epilogue
    #pragma unroll
    for (int mf = 0; mf < 4; mf++){
        #pragma unroll
        for (int half = 0; half < 2; half++){
            const int row = m0 + wm * 64 + mf * 16 + (lane >> 2) + half * 8;
            #pragma unroll
            for (int nf = 0; nf < 8; nf++){
                const int col = n0 + wn * 64 + nf * 8 + (lane & 3) * 2;
                float fx = c[mf][nf][half * 2 + 0];
                float fy = c[mf][nf][half * 2 + 1];
                if (mode == 1){
                    fx = fx / (1.f + __expf(-fx));
                    fy = fy / (1.f + __expf(-fy));
                }
                if (mode != 1){
                    *(float2*)&Cf[(size_t)row * Ntot + col] = make_float2(fx, fy);
                }
                if (mode != 0){
                    __nv_bfloat16 hx, hy, lx, ly;
                    split2(fx, hx, lx);
                    split2(fy, hy, ly);
                    __nv_bfloat162 hp = __halves2bfloat162(hx, hy);
                    __nv_bfloat162 lp = __halves2bfloat162(lx, ly);
                    size_t rb = (size_t)row * (2 * Ntot);
                    *(__nv_bfloat162*)&Csp[rb + col]        = hp;
                    *(__nv_bfloat162*)&Csp[rb + Ntot + col] = lp;
                }
            }
        }
    }
}

// ---------------- fused attention: one block per m, all 8 heads ------------
__global__ void __launch_bounds__(256)
attn_kernel(const float* __restrict__ qkv,
            const int*   __restrict__ dist, const int* __restrict__ phi,
            const float* __restrict__ dtab, const float* __restrict__ ptab,
            const float* __restrict__ Wb,   __nv_bfloat16* __restrict__ osp)
{
    extern __shared__ float sm[];
    float* bias8 = sm;              // [h*1056 + i*33 + j]  (8448)
    float* qs    = sm + 8448;       // [i*68 + d]           (2176)
    float* ks    = sm + 10624;      // (2176)
    float* vs    = sm + 12800;      // (2176)
    float* sc    = sm + 14976;      // [i*33 + j]           (1056)
    float* wb8   = sm + 16032;      // [p*8 + h]            (256)

    const int m = blockIdx.x;
    const int t = threadIdx.x;

    wb8[t] = Wb[t];                 // 256 = PED*HEADS
    __syncthreads();

    // ---- bias for all heads: 4 pairs per thread ----
    const int base_mm = m * (NH * NH);
    #pragma unroll
    for (int q4 = 0; q4 < 4; q4++){
        int pair = t * 4 + q4;              // 0..1023
        int i = pair >> 5, j = pair & 31;
        int id = dist[base_mm + pair];
        int ip = phi [base_mm + pair];
        const float4* dp = (const float4*)(dtab + (size_t)id * 32);
        const float4* fp = (const float4*)(ptab + (size_t)ip * 32);
        float acc[8];
        #pragma unroll
        for (int h = 0; h < 8; h++) acc[h] = 0.f;
        #pragma unroll
        for (int v4 = 0; v4 < 8; v4++){
            float4 d4 = dp[v4];
            float4 f4 = fp[v4];
            float pr[4] = { d4.x*f4.x, d4.y*f4.y, d4.z*f4.z, d4.w*f4.w };
            #pragma unroll
            for (int pp = 0; pp < 4; pp++){
                int p = v4 * 4 + pp;
                #pragma unroll
                for (int h = 0; h < 8; h++)
                    acc[h] += pr[pp] * wb8[p * 8 + h];
            }
        }
        #pragma unroll
        for (int h = 0; h < 8; h++) bias8[h * 1056 + i * 33 + j] = acc[h];
    }

    const int i = t >> 3;          // row 0..31
    const int g = t & 7;           // group 0..7

    for (int h = 0; h < 8; h++){
        __syncthreads();   // bias ready (h=0) / prior head done (h>0)
        // load q,k,v head slices (32 rows x 16 float4 each), vectorized
        #pragma unroll
        for (int it = 0; it < 2; it++){
            int idx = t + it * 256;        // 0..511
            int r  = idx >> 4;             // row 0..31
            int c4 = idx & 15;             // float4 within row 0..15
            size_t gb = (size_t)(m * NH + r) * 1536 + h * 64 + c4 * 4;
            *(float4*)(qs + r * 68 + c4 * 4) = *(const float4*)(qkv + gb);
            *(float4*)(ks + r * 68 + c4 * 4) = *(const float4*)(qkv + gb + 512);
            *(float4*)(vs + r * 68 + c4 * 4) = *(const float4*)(qkv + gb + 1024);
        }
        __syncthreads();

        // scores: 4 j's per thread
        float sv[4];
        #pragma unroll
        for (int jj = 0; jj < 4; jj++){
            int j = g * 4 + jj;
            float s = 0.f;
            #pragma unroll
            for (int d4 = 0; d4 < 16; d4++){
                float4 qa = *(float4*)(qs + i * 68 + d4 * 4);
                float4 ka = *(float4*)(ks + j * 68 + d4 * 4);
                s += qa.x*ka.x + qa.y*ka.y + qa.z*ka.z + qa.w*ka.w;
            }
            sv[jj] = s * 0.125f + bias8[h * 1056 + i * 33 + j];
        }
        // softmax across the 8 threads of row i
        float mx = fmaxf(fmaxf(sv[0], sv[1]), fmaxf(sv[2], sv[3]));
        mx = fmaxf(mx, __shfl_xor_sync(0xffffffffu, mx, 1));
        mx = fmaxf(mx, __shfl_xor_sync(0xffffffffu, mx, 2));
        mx = fmaxf(mx, __shfl_xor_sync(0xffffffffu, mx, 4));
        float ev[4], sum = 0.f;
        #pragma unroll
        for (int jj = 0; jj < 4; jj++){ ev[jj] = __expf(sv[jj] - mx); sum += ev[jj]; }
        sum += __shfl_xor_sync(0xffffffffu, sum, 1);
        sum += __shfl_xor_sync(0xffffffffu, sum, 2);
        sum += __shfl_xor_sync(0xffffffffu, sum, 4);
        const float inv = 1.f / sum;
        #pragma unroll
        for (int jj = 0; jj < 4; jj++) sc[i * 33 + g * 4 + jj] = ev[jj] * inv;
        __syncwarp();

        // AV: thread owns d-segment g*8 .. g*8+7 of row i
        const int dseg = g * 8;
        float acc[8];
        #pragma unroll
        for (int dd = 0; dd < 8; dd++) acc[dd] = 0.f;
        for (int j = 0; j < NH; j++){
            float p = sc[i * 33 + j];
            float4 v0 = *(float4*)(vs + j * 68 + dseg);
            float4 v1 = *(float4*)(vs + j * 68 + dseg + 4);
            acc[0] += p * v0.x; acc[1] += p * v0.y;
            acc[2] += p * v0.z; acc[3] += p * v0.w;
            acc[4] += p * v1.x; acc[5] += p * v1.y;
            acc[6] += p * v1.z; acc[7] += p * v1.w;
        }
        // split-bf16 output, row stride 1024 = [hi(512) | lo(512)]
        size_t rb = ((size_t)(m * NH) + i) * 1024 + h * 64 + dseg;
        #pragma unroll
        for (int dd = 0; dd < 8; dd += 2){
            __nv_bfloat16 hx, hy, lx, ly;
            split2(acc[dd],   hx, lx);
            split2(acc[dd+1], hy, ly);
            *(__nv_bfloat162*)&osp[rb + dd]       = __halves2bfloat162(hx, hy);
            *(__nv_bfloat162*)&osp[rb + 512 + dd] = __halves2bfloat162(lx, ly);
        }
    }
}

// ---------------- fused residual add + LayerNorm (+optional split out) ----
__global__ void __launch_bounds__(128)
add_ln_kernel2(const float* __restrict__ a, const float* __restrict__ b,
               const float* __restrict__ g, const float* __restrict__ be,
               float* __restrict__ outf, __nv_bfloat16* __restrict__ outsp)
{
    const int row = blockIdx.x;
    const int t   = threadIdx.x;
    const size_t off = (size_t)row * MDIM + t * 4;

    float4 va = *(const float4*)(a + off);
    float4 vb = *(const float4*)(b + off);
    float4 vv = make_float4(va.x + vb.x, va.y + vb.y, va.z + vb.z, va.w + vb.w);

    float s  = vv.x + vv.y + vv.z + vv.w;
    float ss = vv.x*vv.x + vv.y*vv.y + vv.z*vv.z + vv.w*vv.w;
    #pragma unroll
    for (int o2 = 16; o2; o2 >>= 1){
        s  += __shfl_xor_sync(0xffffffffu, s,  o2);
        ss += __shfl_xor_sync(0xffffffffu, ss, o2);
    }
    __shared__ float sh_s[4], sh_ss[4];
    const int w = t >> 5, l = t & 31;
    if (l == 0){ sh_s[w] = s; sh_ss[w] = ss; }
    __syncthreads();
    s  = sh_s[0]  + sh_s[1]  + sh_s[2]  + sh_s[3];
    ss = sh_ss[0] + sh_ss[1] + sh_ss[2] + sh_ss[3];

    const float mean = s * (1.f / 512.f);
    const float var  = ss * (1.f / 512.f) - mean * mean;
    const float rstd = rsqrtf(var + 1e-5f);

    float4 vg  = *(const float4*)(g  + t*4);
    float4 vbe = *(const float4*)(be + t*4);
    float4 r;
    r.x = (vv.x - mean) * rstd * vg.x + vbe.x;
    r.y = (vv.y - mean) * rstd * vg.y + vbe.y;
    r.z = (vv.z - mean) * rstd * vg.z + vbe.z;
    r.w = (vv.w - mean) * rstd * vg.w + vbe.w;
    if (outf) *(float4*)(outf + off) = r;
    if (outsp){
        __nv_bfloat16 h0,h1,h2,h3,l0,l1,l2,l3;
        split2(r.x,h0,l0); split2(r.y,h1,l1); split2(r.z,h2,l2); split2(r.w,h3,l3);
        __nv_bfloat162 hA = __halves2bfloat162(h0,h1), hB = __halves2bfloat162(h2,h3);
        __nv_bfloat162 lA = __halves2bfloat162(l0,l1), lB = __halves2bfloat162(l2,l3);
        size_t rb = (size_t)row * 1024 + t * 4;
        *(uint2*)(outsp + rb)       = make_uint2(*(uint32_t*)&hA, *(uint32_t*)&hB);
        *(uint2*)(outsp + rb + 512) = make_uint2(*(uint32_t*)&lA, *(uint32_t*)&lB);
    }
}

// ---------------- driver ----------------
extern "C" void kernel_launch(void* const* d_in, const int* in_sizes, int n_in,
                              void* d_out, int out_size)
{
    (void)in_sizes; (void)n_in; (void)out_size;

    const float* x    = (const float*)d_in[0];
    const int*   dist = (const int*)  d_in[1];
    const int*   phis = (const int*)  d_in[2];
    const float* W_in = (const float*)d_in[3];
    const float* dtab = (const float*)d_in[4];
    const float* ptab = (const float*)d_in[5];
    const float* Wb   = (const float*)d_in[6];
    const float* Wq   = (const float*)d_in[7];
    const float* Wk   = (const float*)d_in[8];
    const float* Wv   = (const float*)d_in[9];
    const float* Wo   = (const float*)d_in[10];
    const float* Wf1  = (const float*)d_in[11];
    const float* Wf2  = (const float*)d_in[12];
    const float* g1   = (const float*)d_in[13];
    const float* b1   = (const float*)d_in[14];
    const float* g2   = (const float*)d_in[15];
    const float* b2   = (const float*)d_in[16];
    const float* Wout = (const float*)d_in[17];
    float* out = (float*)d_out;

    float *pf0, *pqkv;
    __nv_bfloat16 *pa1, *pa2, *pwin, *pwqkv, *pwo, *pwf1, *pwf2, *pwout;
    cudaGetSymbolAddress((void**)&pf0,  g_f0);
    cudaGetSymbolAddress((void**)&pqkv, g_qkv);
    cudaGetSymbolAddress((void**)&pa1,  g_a1);
    cudaGetSymbolAddress((void**)&pa2,  g_a2);
    cudaGetSymbolAddress((void**)&pwin, g_win2);
    cudaGetSymbolAddress((void**)&pwqkv,g_wqkv2);
    cudaGetSymbolAddress((void**)&pwo,  g_wo2);
    cudaGetSymbolAddress((void**)&pwf1, g_wf12);
    cudaGetSymbolAddress((void**)&pwf2, g_wf22);
    cudaGetSymbolAddress((void**)&pwout,g_wout2);

    float* att_out = pqkv;                       // aliases (sequential deps)
    float* h1      = pqkv + (size_t)TOK * 512;
    float* ff2     = pqkv + (size_t)TOK * 1024;

    const int SMG = 256 * 80 * 4;           // 81920 per CTA (2 CTAs/SM)
    const int SMA = 16288 * 4;              // 65152 (attention)
    cudaFuncSetAttribute(mma_gemm, cudaFuncAttributeMaxDynamicSharedMemorySize, SMG);
    cudaFuncSetAttribute(attn_kernel, cudaFuncAttributeMaxDynamicSharedMemorySize, SMA);

    const unsigned MT = TOK / 128;   // 1024 m-tiles

    // 0) all weight conversions in one launch
    WtTable tab;
    tab.d[0] = { W_in, pwin,                      128,  512 };
    tab.d[1] = { Wq,   pwqkv,                     512,  512 };
    tab.d[2] = { Wk,   pwqkv + (size_t)512*1024,  512,  512 };
    tab.d[3] = { Wv,   pwqkv + (size_t)1024*1024, 512,  512 };
    tab.d[4] = { Wo,   pwo,                       512,  512 };
    tab.d[5] = { Wf1,  pwf1,                      512, 2048 };
    tab.d[6] = { Wf2,  pwf2,                     2048,  512 };
    tab.d[7] = { Wout, pwout,                     512,  128 };
    split_wt_all<<<dim3(8192, 8), 256>>>(tab);

    // 1) split x -> a2  [TOK, 256]
    {
        size_t total = (size_t)TOK * 128 / 4;
        split_act<<<(unsigned)((total + 255) / 256), 256>>>(x, pa2, 128, total);
    }
    // 2) h = x @ W_in -> f0 (fp32) + split -> a1
    mma_gemm<<<dim3(4, MT), 128, SMG>>>(pa2, pwin, pf0, pa1, 128, 512, 2);
    // 3) qkv = h @ Wqkv -> fp32 [TOK,1536]
    mma_gemm<<<dim3(12, MT), 128, SMG>>>(pa1, pwqkv, pqkv, nullptr, 512, 1536, 0);
    // 4) attention -> split o -> a1
    attn_kernel<<<MCNT, 256, SMA>>>(pqkv, dist, phis, dtab, ptab, Wb, pa1);
    // 5) att_out = o @ Wo -> fp32
    mma_gemm<<<dim3(4, MT), 128, SMG>>>(pa1, pwo, att_out, nullptr, 512, 512, 0);
    // 6) h1 = LN(h + att_out) -> fp32 h1 + split -> a1
    add_ln_kernel2<<<TOK, 128>>>(pf0, att_out, g1, b1, h1, pa1);
    // 7) ff = silu(h1 @ Wf1) -> split -> a2
    mma_gemm<<<dim3(16, MT), 128, SMG>>>(pa1, pwf1, nullptr, pa2, 512, 2048, 1);
    // 8) ff2 = ff @ Wf2 -> fp32
    mma_gemm<<<dim3(4, MT), 128, SMG>>>(pa2, pwf2, ff2, nullptr, 2048, 512, 0);
    // 9) h2 = LN(h1 + ff2) -> split only -> a1
    add_ln_kernel2<<<TOK, 128>>>(h1, ff2, g2, b2, nullptr, pa1);
    // 10) out = h2 @ W_out
    mma_gemm<<<dim3(1, MT), 128, SMG>>>(pa1, pwout, out, nullptr, 512, 128, 0);
}

// round 11
// speedup vs baseline: 2.6497x; 1.0854x over previous
#include <cuda_runtime.h>
#include <cuda_bf16.h>
#include <cstdint>
#include <math.h>

// ---------------- problem constants ----------------
#define TOK   131072          // B*N*NH tokens
#define MDIM  512
#define FFD   2048
#define MCNT  4096
#define NH    32
#define HEADS 8
#define HD    64

// ---------------- helpers ----------------
__device__ __forceinline__ uint32_t smem_to_u32(const void* p){
    uint32_t a;
    asm("{ .reg .u64 t; cvta.to.shared.u64 t, %1; cvt.u32.u64 %0, t; }" : "=r"(a) : "l"(p));
    return a;
}
__device__ __forceinline__ void cp_async16(uint32_t saddr, const void* gaddr){
    asm volatile("cp.async.cg.shared.global [%0], [%1], 16;" :: "r"(saddr), "l"(gaddr));
}
__device__ __forceinline__ void cp_commit(){ asm volatile("cp.async.commit_group;"); }
template<int N>
__device__ __forceinline__ void cp_wait(){ asm volatile("cp.async.wait_group %0;" :: "n"(N)); }

__device__ __forceinline__ void ldm_x4(uint32_t addr, uint32_t& r0, uint32_t& r1,
                                       uint32_t& r2, uint32_t& r3){
    asm volatile("ldmatrix.sync.aligned.m8n8.x4.shared.b16 {%0,%1,%2,%3}, [%4];"
        : "=r"(r0), "=r"(r1), "=r"(r2), "=r"(r3) : "r"(addr));
}
__device__ __forceinline__ void mma_bf16(float& c0, float& c1, float& c2, float& c3,
                                         uint32_t a0, uint32_t a1, uint32_t a2, uint32_t a3,
                                         uint32_t b0, uint32_t b1){
    asm volatile("mma.sync.aligned.m16n8k16.row.col.f32.bf16.bf16.f32 "
        "{%0,%1,%2,%3}, {%4,%5,%6,%7}, {%8,%9}, {%0,%1,%2,%3};"
        : "+f"(c0), "+f"(c1), "+f"(c2), "+f"(c3)
        : "r"(a0), "r"(a1), "r"(a2), "r"(a3), "r"(b0), "r"(b1));
}
__device__ __forceinline__ void split2(float f, __nv_bfloat16& h, __nv_bfloat16& l){
    h = __float2bfloat16(f);
    l = __float2bfloat16(f - __bfloat162float(h));
}

// ---------------- scratch (~2.3 GB) ----------------
__device__ __align__(256) float g_f0 [TOK*MDIM];          // h (residual)
__device__ __align__(256) float g_qkv[(size_t)TOK*1536];  // qkv / att_out / h1 / ff2
__device__ __align__(256) __nv_bfloat16 g_a1[(size_t)TOK*1024];  // split 512-wide acts
__device__ __align__(256) __nv_bfloat16 g_a2[(size_t)TOK*4096];  // split ff / x acts
__device__ __align__(256) __nv_bfloat16 g_win2 [512*256];
__device__ __align__(256) __nv_bfloat16 g_wqkv2[(size_t)1536*1024];
__device__ __align__(256) __nv_bfloat16 g_wo2  [512*1024];
__device__ __align__(256) __nv_bfloat16 g_wf12 [(size_t)2048*1024];
__device__ __align__(256) __nv_bfloat16 g_wf22 [(size_t)512*4096];
__device__ __align__(256) __nv_bfloat16 g_wout2[128*1024];

// ---------------- fused weight conversion (ONE launch for all 8) ----------
struct WtDesc { const float* W; __nv_bfloat16* Y; int K; int N; };
struct WtTable { WtDesc d[8]; };

__global__ void __launch_bounds__(256)
split_wt_all(WtTable tab)
{
    const WtDesc& e = tab.d[blockIdx.y];
    size_t total = (size_t)e.N * 2 * e.K;
    size_t id = (size_t)blockIdx.x * 256 + threadIdx.x;
    if (id >= total) return;
    int K2 = 2 * e.K;
    size_t n = id / K2;
    int c = (int)(id % K2);
    int reg = c >= e.K, cs = c - (reg ? e.K : 0);
    float x = e.W[(size_t)cs * e.N + n];
    __nv_bfloat16 h, l;
    split2(x, h, l);
    e.Y[id] = reg ? l : h;
}

// ---------------- split conversion: activations (x only) ----------------
__global__ void __launch_bounds__(256)
split_act(const float* __restrict__ X, __nv_bfloat16* __restrict__ Y,
          int K, size_t total /* R*K/4 */)
{
    size_t id = (size_t)blockIdx.x * 256 + threadIdx.x;
    if (id >= total) return;
    int kq = K >> 2;
    size_t r = id / kq;
    int c = (int)(id % kq) << 2;
    float4 x = *(const float4*)(X + r * K + c);
    __nv_bfloat16 h0,h1,h2,h3,l0,l1,l2,l3;
    split2(x.x,h0,l0); split2(x.y,h1,l1); split2(x.z,h2,l2); split2(x.w,h3,l3);
    __nv_bfloat162 hA = __halves2bfloat162(h0,h1), hB = __halves2bfloat162(h2,h3);
    __nv_bfloat162 lA = __halves2bfloat162(l0,l1), lB = __halves2bfloat162(l2,l3);
    size_t ob = r * (size_t)(2 * K);
    *(uint2*)(Y + ob + c)     = make_uint2(*(uint32_t*)&hA, *(uint32_t*)&hB);
    *(uint2*)(Y + ob + K + c) = make_uint2(*(uint32_t*)&lA, *(uint32_t*)&lB);
}

// ---------------- mma.sync bf16 GEMM, 3-segment split schedule ----------------
// A [M, 2K] = [hi|lo], Bt [Ntot, 2K] = [hi|lo] (K-major rows).
// Segments: (Ahi,Bhi), (Alo,Bhi), (Ahi,Blo) accumulated in registers.
// CTA tile 128x128; 4 warps (2x2); warp tile 64x64; BK=32; 3 stages;
// 128 threads, 61.4 KB smem -> 3 CTAs/SM (3 barrier domains overlap bubbles).
// mode: 0=f32, 1=silu+split, 2=f32+split.
__global__ void __launch_bounds__(128, 3)
mma_gemm(const __nv_bfloat16* __restrict__ A, const __nv_bfloat16* __restrict__ Bt,
         float* __restrict__ Cf, __nv_bfloat16* __restrict__ Csp,
         int K, int Ntot, int mode)
{
    constexpr int THREADS = 128;
    constexpr int STAGES = 3;
    constexpr int A_BYTES = 128 * 80;
    constexpr int STAGE_BYTES = 256 * 80;
    constexpr int A_CH = 4;   // (128 rows * 4 chunks) / 128 threads
    constexpr int B_CH = 4;
    extern __shared__ __align__(16) char smem[];

    const int tid  = threadIdx.x;
    const int lane = tid & 31;
    const int wid  = tid >> 5;
    const int wm   = wid >> 1;        // 0..1
    const int wn   = wid & 1;         // 0..1
    const int m0   = blockIdx.y * 128;
    const int n0   = blockIdx.x * 128;

    const int lda = 2 * K;
    const __nv_bfloat16* Ab = A  + (size_t)m0 * lda;
    const __nv_bfloat16* Bb = Bt + (size_t)n0 * lda;
    const uint32_t sbase = smem_to_u32(smem);

    float c[4][8][4];
    #pragma unroll
    for (int i = 0; i < 4; i++)
        #pragma unroll
        for (int j = 0; j < 8; j++)
            #pragma unroll
            for (int q = 0; q < 4; q++) c[i][j][q] = 0.f;

    const int kch = K >> 5;
    const int nch = 3 * kch;

    auto load_chunk = [&](int tt, int stage){
        int seg = (tt >= kch) + (tt >= 2 * kch);
        int kk = tt - seg * kch;
        int ac = ((seg == 1) ? K : 0) + (kk << 5);
        int bc = ((seg == 2) ? K : 0) + (kk << 5);
        uint32_t sa = sbase + stage * STAGE_BYTES;
        uint32_t sb = sa + A_BYTES;
        #pragma unroll
        for (int it = 0; it < A_CH; it++){
            int idx = tid + it * THREADS;
            int r = idx >> 2, ch = idx & 3;
            cp_async16(sa + r * 80 + ch * 16, Ab + (size_t)r * lda + ac + ch * 8);
        }
        #pragma unroll
        for (int it = 0; it < B_CH; it++){
            int idx = tid + it * THREADS;
            int r = idx >> 2, ch = idx & 3;
            cp_async16(sb + r * 80 + ch * 16, Bb + (size_t)r * lda + bc + ch * 8);
        }
    };

    #pragma unroll
    for (int s = 0; s < STAGES - 1; s++){
        if (s < nch) load_chunk(s, s);
        cp_commit();
    }

    for (int t = 0; t < nch; t++){
        cp_wait<STAGES - 2>();
        __syncthreads();
        const int pf = t + STAGES - 1;
        if (pf < nch) load_chunk(pf, pf % STAGES);
        cp_commit();

        const uint32_t sa = sbase + (t % STAGES) * STAGE_BYTES;
        const uint32_t sb = sa + A_BYTES;
        #pragma unroll
        for (int ks = 0; ks < 2; ks++){
            uint32_t a[4][4], b[8][2];
            #pragma unroll
            for (int mf = 0; mf < 4; mf++){
                int r = wm * 64 + mf * 16 + (lane & 15);
                int col = ks * 16 + (lane >> 4) * 8;
                ldm_x4(sa + r * 80 + col * 2, a[mf][0], a[mf][1], a[mf][2], a[mf][3]);
            }
            #pragma unroll
            for (int g = 0; g < 4; g++){
                int r = wn * 64 + g * 16 + ((lane >> 4) << 3) + (lane & 7);
                int col = ks * 16 + ((lane >> 3) & 1) * 8;
                ldm_x4(sb + r * 80 + col * 2,
                       b[2*g][0], b[2*g][1], b[2*g+1][0], b[2*g+1][1]);
            }
            #pragma unroll
            for (int mf = 0; mf < 4; mf++)
                #pragma unroll
                for (int nf = 0; nf < 8; nf++)
                    mma_bf16(c[mf][nf][0], c[mf][nf][1], c[mf][nf][2], c[mf][nf][3],
                             a[mf][0], a[mf][1], a[mf][2], a[mf][3],
                             b[nf][0], b[nf][1]);
        }
    }

    // epilogue
    #pragma unroll
    for (int mf = 0; mf < 4; mf++){
        #pragma unroll
        for (int half = 0; half < 2; half++){
            const int row = m0 + wm * 64 + mf * 16 + (lane >> 2) + half * 8;
            #pragma unroll
            for (int nf = 0; nf < 8; nf++){
                const int col = n0 + wn * 64 + nf * 8 + (lane & 3) * 2;
                float fx = c[mf][nf][half * 2 + 0];
                float fy = c[mf][nf][half * 2 + 1];
                if (mode == 1){
                    fx = fx / (1.f + __expf(-fx));
                    fy = fy / (1.f + __expf(-fy));
                }
                if (mode != 1){
                    *(float2*)&Cf[(size_t)row * Ntot + col] = make_float2(fx, fy);
                }
                if (mode != 0){
                    __nv_bfloat16 hx, hy, lx, ly;
                    split2(fx, hx, lx);
                    split2(fy, hy, ly);
                    __nv_bfloat162 hp = __halves2bfloat162(hx, hy);
                    __nv_bfloat162 lp = __halves2bfloat162(lx, ly);
                    size_t rb = (size_t)row * (2 * Ntot);
                    *(__nv_bfloat162*)&Csp[rb + col]        = hp;
                    *(__nv_bfloat162*)&Csp[rb + Ntot + col] = lp;
                }
            }
        }
    }
}

// ---------------- fused attention: one block per m, all 8 heads ------------
__global__ void __launch_bounds__(256)
attn_kernel(const float* __restrict__ qkv,
            const int*   __restrict__ dist, const int* __restrict__ phi,
            const float* __restrict__ dtab, const float* __restrict__ ptab,
            const float* __restrict__ Wb,   __nv_bfloat16* __restrict__ osp)
{
    extern __shared__ float sm[];
    float* bias8 = sm;              // [h*1056 + i*33 + j]  (8448)
    float* qs    = sm + 8448;       // [i*68 + d]           (2176)
    float* ks    = sm + 10624;      // (2176)
    float* vs    = sm + 12800;      // (2176)
    float* sc    = sm + 14976;      // [i*33 + j]           (1056)
    float* wb8   = sm + 16032;      // [p*8 + h]            (256)

    const int m = blockIdx.x;
    const int t = threadIdx.x;

    wb8[t] = Wb[t];                 // 256 = PED*HEADS
    __syncthreads();

    // ---- bias for all heads: 4 pairs per thread ----
    const int base_mm = m * (NH * NH);
    #pragma unroll
    for (int q4 = 0; q4 < 4; q4++){
        int pair = t * 4 + q4;              // 0..1023
        int i = pair >> 5, j = pair & 31;
        int id = dist[base_mm + pair];
        int ip = phi [base_mm + pair];
        const float4* dp = (const float4*)(dtab + (size_t)id * 32);
        const float4* fp = (const float4*)(ptab + (size_t)ip * 32);
        float acc[8];
        #pragma unroll
        for (int h = 0; h < 8; h++) acc[h] = 0.f;
        #pragma unroll
        for (int v4 = 0; v4 < 8; v4++){
            float4 d4 = dp[v4];
            float4 f4 = fp[v4];
            float pr[4] = { d4.x*f4.x, d4.y*f4.y, d4.z*f4.z, d4.w*f4.w };
            #pragma unroll
            for (int pp = 0; pp < 4; pp++){
                int p = v4 * 4 + pp;
                #pragma unroll
                for (int h = 0; h < 8; h++)
                    acc[h] += pr[pp] * wb8[p * 8 + h];
            }
        }
        #pragma unroll
        for (int h = 0; h < 8; h++) bias8[h * 1056 + i * 33 + j] = acc[h];
    }

    const int i = t >> 3;          // row 0..31
    const int g = t & 7;           // group 0..7

    for (int h = 0; h < 8; h++){
        __syncthreads();   // bias ready (h=0) / prior head done (h>0)
        // load q,k,v head slices (32 rows x 16 float4 each), vectorized
        #pragma unroll
        for (int it = 0; it < 2; it++){
            int idx = t + it * 256;        // 0..511
            int r  = idx >> 4;             // row 0..31
            int c4 = idx & 15;             // float4 within row 0..15
            size_t gb = (size_t)(m * NH + r) * 1536 + h * 64 + c4 * 4;
            *(float4*)(qs + r * 68 + c4 * 4) = *(const float4*)(qkv + gb);
            *(float4*)(ks + r * 68 + c4 * 4) = *(const float4*)(qkv + gb + 512);
            *(float4*)(vs + r * 68 + c4 * 4) = *(const float4*)(qkv + gb + 1024);
        }
        __syncthreads();

        // scores: 4 j's per thread
        float sv[4];
        #pragma unroll
        for (int jj = 0; jj < 4; jj++){
            int j = g * 4 + jj;
            float s = 0.f;
            #pragma unroll
            for (int d4 = 0; d4 < 16; d4++){
                float4 qa = *(float4*)(qs + i * 68 + d4 * 4);
                float4 ka = *(float4*)(ks + j * 68 + d4 * 4);
                s += qa.x*ka.x + qa.y*ka.y + qa.z*ka.z + qa.w*ka.w;
            }
            sv[jj] = s * 0.125f + bias8[h * 1056 + i * 33 + j];
        }
        // softmax across the 8 threads of row i
        float mx = fmaxf(fmaxf(sv[0], sv[1]), fmaxf(sv[2], sv[3]));
        mx = fmaxf(mx, __shfl_xor_sync(0xffffffffu, mx, 1));
        mx = fmaxf(mx, __shfl_xor_sync(0xffffffffu, mx, 2));
        mx = fmaxf(mx, __shfl_xor_sync(0xffffffffu, mx, 4));
        float ev[4], sum = 0.f;
        #pragma unroll
        for (int jj = 0; jj < 4; jj++){ ev[jj] = __expf(sv[jj] - mx); sum += ev[jj]; }
        sum += __shfl_xor_sync(0xffffffffu, sum, 1);
        sum += __shfl_xor_sync(0xffffffffu, sum, 2);
        sum += __shfl_xor_sync(0xffffffffu, sum, 4);
        const float inv = 1.f / sum;
        #pragma unroll
        for (int jj = 0; jj < 4; jj++) sc[i * 33 + g * 4 + jj] = ev[jj] * inv;
        __syncwarp();

        // AV: thread owns d-segment g*8 .. g*8+7 of row i
        const int dseg = g * 8;
        float acc[8];
        #pragma unroll
        for (int dd = 0; dd < 8; dd++) acc[dd] = 0.f;
        for (int j = 0; j < NH; j++){
            float p = sc[i * 33 + j];
            float4 v0 = *(float4*)(vs + j * 68 + dseg);
            float4 v1 = *(float4*)(vs + j * 68 + dseg + 4);
            acc[0] += p * v0.x; acc[1] += p * v0.y;
            acc[2] += p * v0.z; acc[3] += p * v0.w;
            acc[4] += p * v1.x; acc[5] += p * v1.y;
            acc[6] += p * v1.z; acc[7] += p * v1.w;
        }
        // split-bf16 output, row stride 1024 = [hi(512) | lo(512)]
        size_t rb = ((size_t)(m * NH) + i) * 1024 + h * 64 + dseg;
        #pragma unroll
        for (int dd = 0; dd < 8; dd += 2){
            __nv_bfloat16 hx, hy, lx, ly;
            split2(acc[dd],   hx, lx);
            split2(acc[dd+1], hy, ly);
            *(__nv_bfloat162*)&osp[rb + dd]       = __halves2bfloat162(hx, hy);
            *(__nv_bfloat162*)&osp[rb + 512 + dd] = __halves2bfloat162(lx, ly);
        }
    }
}

// ---------------- fused residual add + LayerNorm (+optional split out) ----
__global__ void __launch_bounds__(128)
add_ln_kernel2(const float* __restrict__ a, const float* __restrict__ b,
               const float* __restrict__ g, const float* __restrict__ be,
               float* __restrict__ outf, __nv_bfloat16* __restrict__ outsp)
{
    const int row = blockIdx.x;
    const int t   = threadIdx.x;
    const size_t off = (size_t)row * MDIM + t * 4;

    float4 va = *(const float4*)(a + off);
    float4 vb = *(const float4*)(b + off);
    float4 vv = make_float4(va.x + vb.x, va.y + vb.y, va.z + vb.z, va.w + vb.w);

    float s  = vv.x + vv.y + vv.z + vv.w;
    float ss = vv.x*vv.x + vv.y*vv.y + vv.z*vv.z + vv.w*vv.w;
    #pragma unroll
    for (int o2 = 16; o2; o2 >>= 1){
        s  += __shfl_xor_sync(0xffffffffu, s,  o2);
        ss += __shfl_xor_sync(0xffffffffu, ss, o2);
    }
    __shared__ float sh_s[4], sh_ss[4];
    const int w = t >> 5, l = t & 31;
    if (l == 0){ sh_s[w] = s; sh_ss[w] = ss; }
    __syncthreads();
    s  = sh_s[0]  + sh_s[1]  + sh_s[2]  + sh_s[3];
    ss = sh_ss[0] + sh_ss[1] + sh_ss[2] + sh_ss[3];

    const float mean = s * (1.f / 512.f);
    const float var  = ss * (1.f / 512.f) - mean * mean;
    const float rstd = rsqrtf(var + 1e-5f);

    float4 vg  = *(const float4*)(g  + t*4);
    float4 vbe = *(const float4*)(be + t*4);
    float4 r;
    r.x = (vv.x - mean) * rstd * vg.x + vbe.x;
    r.y = (vv.y - mean) * rstd * vg.y + vbe.y;
    r.z = (vv.z - mean) * rstd * vg.z + vbe.z;
    r.w = (vv.w - mean) * rstd * vg.w + vbe.w;
    if (outf) *(float4*)(outf + off) = r;
    if (outsp){
        __nv_bfloat16 h0,h1,h2,h3,l0,l1,l2,l3;
        split2(r.x,h0,l0); split2(r.y,h1,l1); split2(r.z,h2,l2); split2(r.w,h3,l3);
        __nv_bfloat162 hA = __halves2bfloat162(h0,h1), hB = __halves2bfloat162(h2,h3);
        __nv_bfloat162 lA = __halves2bfloat162(l0,l1), lB = __halves2bfloat162(l2,l3);
        size_t rb = (size_t)row * 1024 + t * 4;
        *(uint2*)(outsp + rb)       = make_uint2(*(uint32_t*)&hA, *(uint32_t*)&hB);
        *(uint2*)(outsp + rb + 512) = make_uint2(*(uint32_t*)&lA, *(uint32_t*)&lB);
    }
}

// ---------------- driver ----------------
extern "C" void kernel_launch(void* const* d_in, const int* in_sizes, int n_in,
                              void* d_out, int out_size)
{
    (void)in_sizes; (void)n_in; (void)out_size;

    const float* x    = (const float*)d_in[0];
    const int*   dist = (const int*)  d_in[1];
    const int*   phis = (const int*)  d_in[2];
    const float* W_in = (const float*)d_in[3];
    const float* dtab = (const float*)d_in[4];
    const float* ptab = (const float*)d_in[5];
    const float* Wb   = (const float*)d_in[6];
    const float* Wq   = (const float*)d_in[7];
    const float* Wk   = (const float*)d_in[8];
    const float* Wv   = (const float*)d_in[9];
    const float* Wo   = (const float*)d_in[10];
    const float* Wf1  = (const float*)d_in[11];
    const float* Wf2  = (const float*)d_in[12];
    const float* g1   = (const float*)d_in[13];
    const float* b1   = (const float*)d_in[14];
    const float* g2   = (const float*)d_in[15];
    const float* b2   = (const float*)d_in[16];
    const float* Wout = (const float*)d_in[17];
    float* out = (float*)d_out;

    float *pf0, *pqkv;
    __nv_bfloat16 *pa1, *pa2, *pwin, *pwqkv, *pwo, *pwf1, *pwf2, *pwout;
    cudaGetSymbolAddress((void**)&pf0,  g_f0);
    cudaGetSymbolAddress((void**)&pqkv, g_qkv);
    cudaGetSymbolAddress((void**)&pa1,  g_a1);
    cudaGetSymbolAddress((void**)&pa2,  g_a2);
    cudaGetSymbolAddress((void**)&pwin, g_win2);
    cudaGetSymbolAddress((void**)&pwqkv,g_wqkv2);
    cudaGetSymbolAddress((void**)&pwo,  g_wo2);
    cudaGetSymbolAddress((void**)&pwf1, g_wf12);
    cudaGetSymbolAddress((void**)&pwf2, g_wf22);
    cudaGetSymbolAddress((void**)&pwout,g_wout2);

    float* att_out = pqkv;                       // aliases (sequential deps)
    float* h1      = pqkv + (size_t)TOK * 512;
    float* ff2     = pqkv + (size_t)TOK * 1024;

    const int SMG = 256 * 80 * 3;           // 61440 per CTA (3 CTAs/SM)
    const int SMA = 16288 * 4;              // 65152 (attention)
    cudaFuncSetAttribute(mma_gemm, cudaFuncAttributeMaxDynamicSharedMemorySize, SMG);
    cudaFuncSetAttribute(attn_kernel, cudaFuncAttributeMaxDynamicSharedMemorySize, SMA);

    const unsigned MT = TOK / 128;   // 1024 m-tiles

    // 0) all weight conversions in one launch
    WtTable tab;
    tab.d[0] = { W_in, pwin,                      128,  512 };
    tab.d[1] = { Wq,   pwqkv,                     512,  512 };
    tab.d[2] = { Wk,   pwqkv + (size_t)512*1024,  512,  512 };
    tab.d[3] = { Wv,   pwqkv + (size_t)1024*1024, 512,  512 };
    tab.d[4] = { Wo,   pwo,                       512,  512 };
    tab.d[5] = { Wf1,  pwf1,                      512, 2048 };
    tab.d[6] = { Wf2,  pwf2,                     2048,  512 };
    tab.d[7] = { Wout, pwout,                     512,  128 };
    split_wt_all<<<dim3(8192, 8), 256>>>(tab);

    // 1) split x -> a2  [TOK, 256]
    {
        size_t total = (size_t)TOK * 128 / 4;
        split_act<<<(unsigned)((total + 255) / 256), 256>>>(x, pa2, 128, total);
    }
    // 2) h = x @ W_in -> f0 (fp32) + split -> a1
    mma_gemm<<<dim3(4, MT), 128, SMG>>>(pa2, pwin, pf0, pa1, 128, 512, 2);
    // 3) qkv = h @ Wqkv -> fp32 [TOK,1536]
    mma_gemm<<<dim3(12, MT), 128, SMG>>>(pa1, pwqkv, pqkv, nullptr, 512, 1536, 0);
    // 4) attention -> split o -> a1
    attn_kernel<<<MCNT, 256, SMA>>>(pqkv, dist, phis, dtab, ptab, Wb, pa1);
    // 5) att_out = o @ Wo -> fp32
    mma_gemm<<<dim3(4, MT), 128, SMG>>>(pa1, pwo, att_out, nullptr, 512, 512, 0);
    // 6) h1 = LN(h + att_out) -> fp32 h1 + split -> a1
    add_ln_kernel2<<<TOK, 128>>>(pf0, att_out, g1, b1, h1, pa1);
    // 7) ff = silu(h1 @ Wf1) -> split -> a2
    mma_gemm<<<dim3(16, MT), 128, SMG>>>(pa1, pwf1, nullptr, pa2, 512, 2048, 1);
    // 8) ff2 = ff @ Wf2 -> fp32
    mma_gemm<<<dim3(4, MT), 128, SMG>>>(pa2, pwf2, ff2, nullptr, 2048, 512, 0);
    // 9) h2 = LN(h1 + ff2) -> split only -> a1
    add_ln_kernel2<<<TOK, 128>>>(h1, ff2, g2, b2, nullptr, pa1);
    // 10) out = h2 @ W_out
    mma_gemm<<<dim3(1, MT), 128, SMG>>>(pa1, pwout, out, nullptr, 512, 128, 0);
}

// round 12
// speedup vs baseline: 2.9995x; 1.1320x over previous
#include <cuda_runtime.h>
#include <cuda_bf16.h>
#include <cstdint>
#include <math.h>

// ---------------- problem constants ----------------
#define TOK   131072          // B*N*NH tokens
#define MDIM  512
#define FFD   2048
#define MCNT  4096
#define NH    32
#define HEADS 8
#define HD    64

// ---------------- helpers ----------------
__device__ __forceinline__ uint32_t smem_to_u32(const void* p){
    uint32_t a;
    asm("{ .reg .u64 t; cvta.to.shared.u64 t, %1; cvt.u32.u64 %0, t; }" : "=r"(a) : "l"(p));
    return a;
}
__device__ __forceinline__ void cp_async16(uint32_t saddr, const void* gaddr){
    asm volatile("cp.async.cg.shared.global [%0], [%1], 16;" :: "r"(saddr), "l"(gaddr));
}
__device__ __forceinline__ void cp_commit(){ asm volatile("cp.async.commit_group;"); }
template<int N>
__device__ __forceinline__ void cp_wait(){ asm volatile("cp.async.wait_group %0;" :: "n"(N)); }

__device__ __forceinline__ void ldm_x4(uint32_t addr, uint32_t& r0, uint32_t& r1,
                                       uint32_t& r2, uint32_t& r3){
    asm volatile("ldmatrix.sync.aligned.m8n8.x4.shared.b16 {%0,%1,%2,%3}, [%4];"
        : "=r"(r0), "=r"(r1), "=r"(r2), "=r"(r3) : "r"(addr));
}
__device__ __forceinline__ void mma_bf16(float& c0, float& c1, float& c2, float& c3,
                                         uint32_t a0, uint32_t a1, uint32_t a2, uint32_t a3,
                                         uint32_t b0, uint32_t b1){
    asm volatile("mma.sync.aligned.m16n8k16.row.col.f32.bf16.bf16.f32 "
        "{%0,%1,%2,%3}, {%4,%5,%6,%7}, {%8,%9}, {%0,%1,%2,%3};"
        : "+f"(c0), "+f"(c1), "+f"(c2), "+f"(c3)
        : "r"(a0), "r"(a1), "r"(a2), "r"(a3), "r"(b0), "r"(b1));
}
__device__ __forceinline__ void split2(float f, __nv_bfloat16& h, __nv_bfloat16& l){
    h = __float2bfloat16(f);
    l = __float2bfloat16(f - __bfloat162float(h));
}

// ---------------- scratch (~2.3 GB) ----------------
__device__ __align__(256) float g_f0 [TOK*MDIM];          // h (residual)
__device__ __align__(256) float g_qkv[(size_t)TOK*1536];  // qkv / att_out / h1 / ff2
__device__ __align__(256) __nv_bfloat16 g_a1[(size_t)TOK*1024];  // split 512-wide acts
__device__ __align__(256) __nv_bfloat16 g_a2[(size_t)TOK*4096];  // split ff / x acts
__device__ __align__(256) __nv_bfloat16 g_win2 [512*256];
__device__ __align__(256) __nv_bfloat16 g_wqkv2[(size_t)1536*1024];
__device__ __align__(256) __nv_bfloat16 g_wo2  [512*1024];
__device__ __align__(256) __nv_bfloat16 g_wf12 [(size_t)2048*1024];
__device__ __align__(256) __nv_bfloat16 g_wf22 [(size_t)512*4096];
__device__ __align__(256) __nv_bfloat16 g_wout2[128*1024];

// ---------------- fused weight conversion (ONE launch for all 8) ----------
struct WtDesc { const float* W; __nv_bfloat16* Y; int K; int N; };
struct WtTable { WtDesc d[8]; };

__global__ void __launch_bounds__(256)
split_wt_all(WtTable tab)
{
    const WtDesc& e = tab.d[blockIdx.y];
    size_t total = (size_t)e.N * 2 * e.K;
    size_t id = (size_t)blockIdx.x * 256 + threadIdx.x;
    if (id >= total) return;
    int K2 = 2 * e.K;
    size_t n = id / K2;
    int c = (int)(id % K2);
    int reg = c >= e.K, cs = c - (reg ? e.K : 0);
    float x = e.W[(size_t)cs * e.N + n];
    __nv_bfloat16 h, l;
    split2(x, h, l);
    e.Y[id] = reg ? l : h;
}

// ---------------- split conversion: activations (x only) ----------------
__global__ void __launch_bounds__(256)
split_act(const float* __restrict__ X, __nv_bfloat16* __restrict__ Y,
          int K, size_t total /* R*K/4 */)
{
    size_t id = (size_t)blockIdx.x * 256 + threadIdx.x;
    if (id >= total) return;
    int kq = K >> 2;
    size_t r = id / kq;
    int c = (int)(id % kq) << 2;
    float4 x = *(const float4*)(X + r * K + c);
    __nv_bfloat16 h0,h1,h2,h3,l0,l1,l2,l3;
    split2(x.x,h0,l0); split2(x.y,h1,l1); split2(x.z,h2,l2); split2(x.w,h3,l3);
    __nv_bfloat162 hA = __halves2bfloat162(h0,h1), hB = __halves2bfloat162(h2,h3);
    __nv_bfloat162 lA = __halves2bfloat162(l0,l1), lB = __halves2bfloat162(l2,l3);
    size_t ob = r * (size_t)(2 * K);
    *(uint2*)(Y + ob + c)     = make_uint2(*(uint32_t*)&hA, *(uint32_t*)&hB);
    *(uint2*)(Y + ob + K + c) = make_uint2(*(uint32_t*)&lA, *(uint32_t*)&lB);
}

// ---------------- mma.sync bf16 GEMM, 3-segment split schedule ----------------
// A [M, 2K] = [hi|lo], Bt [Ntot, 2K] = [hi|lo] (K-major rows).
// Segments: (Ahi,Bhi), (Alo,Bhi), (Ahi,Blo) accumulated in registers.
// CTA tile 128x128; 4 warps (2x2); warp tile 64x64; BK=64 (128B rows, XOR
// swizzle, no pad); 2 stages (32KB each); 128 threads, 64KB smem ->
// 3 CTAs/SM. Half the barrier cadence of BK=32.
// mode: 0=f32, 1=silu+split, 2=f32+split.
__global__ void __launch_bounds__(128, 3)
mma_gemm(const __nv_bfloat16* __restrict__ A, const __nv_bfloat16* __restrict__ Bt,
         float* __restrict__ Cf, __nv_bfloat16* __restrict__ Csp,
         int K, int Ntot, int mode)
{
    constexpr int THREADS = 128;
    constexpr int A_BYTES = 128 * 128;       // 16384
    constexpr int STAGE_BYTES = 256 * 128;   // 32768
    extern __shared__ __align__(16) char smem[];

    const int tid  = threadIdx.x;
    const int lane = tid & 31;
    const int wid  = tid >> 5;
    const int wm   = wid >> 1;        // 0..1
    const int wn   = wid & 1;         // 0..1
    const int m0   = blockIdx.y * 128;
    const int n0   = blockIdx.x * 128;

    const int lda = 2 * K;
    const __nv_bfloat16* Ab = A  + (size_t)m0 * lda;
    const __nv_bfloat16* Bb = Bt + (size_t)n0 * lda;
    const uint32_t sbase = smem_to_u32(smem);

    float c[4][8][4];
    #pragma unroll
    for (int i = 0; i < 4; i++)
        #pragma unroll
        for (int j = 0; j < 8; j++)
            #pragma unroll
            for (int q = 0; q < 4; q++) c[i][j][q] = 0.f;

    const int kch = K >> 6;       // chunks of 64 columns
    const int nch = 3 * kch;

    // XOR-swizzled smem offset for (row, 16B-chunk)
    auto sw = [](int r, int ch) -> uint32_t {
        return (uint32_t)(r * 128 + ((ch ^ (r & 7)) << 4));
    };

    auto load_chunk = [&](int tt, int stage){
        int seg = (tt >= kch) + (tt >= 2 * kch);
        int kk = tt - seg * kch;
        int ac = ((seg == 1) ? K : 0) + (kk << 6);
        int bc = ((seg == 2) ? K : 0) + (kk << 6);
        uint32_t sa = sbase + stage * STAGE_BYTES;
        uint32_t sb = sa + A_BYTES;
        #pragma unroll
        for (int it = 0; it < 8; it++){
            int idx = tid + it * THREADS;
            int r = idx >> 3, ch = idx & 7;
            cp_async16(sa + sw(r, ch), Ab + (size_t)r * lda + ac + ch * 8);
        }
        #pragma unroll
        for (int it = 0; it < 8; it++){
            int idx = tid + it * THREADS;
            int r = idx >> 3, ch = idx & 7;
            cp_async16(sb + sw(r, ch), Bb + (size_t)r * lda + bc + ch * 8);
        }
    };

    load_chunk(0, 0);
    cp_commit();

    for (int t = 0; t < nch; t++){
        cp_wait<0>();
        __syncthreads();
        if (t + 1 < nch){
            load_chunk(t + 1, (t + 1) & 1);
            cp_commit();
        }
        const uint32_t sa = sbase + (t & 1) * STAGE_BYTES;
        const uint32_t sb = sa + A_BYTES;
        #pragma unroll
        for (int ks = 0; ks < 4; ks++){
            uint32_t a[4][4], b[8][2];
            #pragma unroll
            for (int mf = 0; mf < 4; mf++){
                int r = wm * 64 + mf * 16 + (lane & 15);
                int ch = 2 * ks + (lane >> 4);
                ldm_x4(sa + sw(r, ch), a[mf][0], a[mf][1], a[mf][2], a[mf][3]);
            }
            #pragma unroll
            for (int g = 0; g < 4; g++){
                int r = wn * 64 + g * 16 + ((lane >> 4) << 3) + (lane & 7);
                int ch = 2 * ks + ((lane >> 3) & 1);
                ldm_x4(sb + sw(r, ch),
                       b[2*g][0], b[2*g][1], b[2*g+1][0], b[2*g+1][1]);
            }
            #pragma unroll
            for (int mf = 0; mf < 4; mf++)
                #pragma unroll
                for (int nf = 0; nf < 8; nf++)
                    mma_bf16(c[mf][nf][0], c[mf][nf][1], c[mf][nf][2], c[mf][nf][3],
                             a[mf][0], a[mf][1], a[mf][2], a[mf][3],
                             b[nf][0], b[nf][1]);
        }
    }

    // epilogue
    #pragma unroll
    for (int mf = 0; mf < 4; mf++){
        #pragma unroll
        for (int half = 0; half < 2; half++){
            const int row = m0 + wm * 64 + mf * 16 + (lane >> 2) + half * 8;
            #pragma unroll
            for (int nf = 0; nf < 8; nf++){
                const int col = n0 + wn * 64 + nf * 8 + (lane & 3) * 2;
                float fx = c[mf][nf][half * 2 + 0];
                float fy = c[mf][nf][half * 2 + 1];
                if (mode == 1){
                    fx = fx / (1.f + __expf(-fx));
                    fy = fy / (1.f + __expf(-fy));
                }
                if (mode != 1){
                    *(float2*)&Cf[(size_t)row * Ntot + col] = make_float2(fx, fy);
                }
                if (mode != 0){
                    __nv_bfloat16 hx, hy, lx, ly;
                    split2(fx, hx, lx);
                    split2(fy, hy, ly);
                    __nv_bfloat162 hp = __halves2bfloat162(hx, hy);
                    __nv_bfloat162 lp = __halves2bfloat162(lx, ly);
                    size_t rb = (size_t)row * (2 * Ntot);
                    *(__nv_bfloat162*)&Csp[rb + col]        = hp;
                    *(__nv_bfloat162*)&Csp[rb + Ntot + col] = lp;
                }
            }
        }
    }
}

// ---------------- fused attention: one block per m, all 8 heads ------------
__global__ void __launch_bounds__(256)
attn_kernel(const float* __restrict__ qkv,
            const int*   __restrict__ dist, const int* __restrict__ phi,
            const float* __restrict__ dtab, const float* __restrict__ ptab,
            const float* __restrict__ Wb,   __nv_bfloat16* __restrict__ osp)
{
    extern __shared__ float sm[];
    float* bias8 = sm;              // [h*1056 + i*33 + j]  (8448)
    float* qs    = sm + 8448;       // [i*68 + d]           (2176)
    float* ks    = sm + 10624;      // (2176)
    float* vs    = sm + 12800;      // (2176)
    float* sc    = sm + 14976;      // [i*33 + j]           (1056)
    float* wb8   = sm + 16032;      // [p*8 + h]            (256)

    const int m = blockIdx.x;
    const int t = threadIdx.x;

    wb8[t] = Wb[t];                 // 256 = PED*HEADS
    __syncthreads();

    // ---- bias for all heads: 4 pairs per thread ----
    const int base_mm = m * (NH * NH);
    #pragma unroll
    for (int q4 = 0; q4 < 4; q4++){
        int pair = t * 4 + q4;              // 0..1023
        int i = pair >> 5, j = pair & 31;
        int id = dist[base_mm + pair];
        int ip = phi [base_mm + pair];
        const float4* dp = (const float4*)(dtab + (size_t)id * 32);
        const float4* fp = (const float4*)(ptab + (size_t)ip * 32);
        float acc[8];
        #pragma unroll
        for (int h = 0; h < 8; h++) acc[h] = 0.f;
        #pragma unroll
        for (int v4 = 0; v4 < 8; v4++){
            float4 d4 = dp[v4];
            float4 f4 = fp[v4];
            float pr[4] = { d4.x*f4.x, d4.y*f4.y, d4.z*f4.z, d4.w*f4.w };
            #pragma unroll
            for (int pp = 0; pp < 4; pp++){
                int p = v4 * 4 + pp;
                #pragma unroll
                for (int h = 0; h < 8; h++)
                    acc[h] += pr[pp] * wb8[p * 8 + h];
            }
        }
        #pragma unroll
        for (int h = 0; h < 8; h++) bias8[h * 1056 + i * 33 + j] = acc[h];
    }

    const int i = t >> 3;          // row 0..31
    const int g = t & 7;           // group 0..7

    for (int h = 0; h < 8; h++){
        __syncthreads();   // bias ready (h=0) / prior head done (h>0)
        // load q,k,v head slices (32 rows x 16 float4 each), vectorized
        #pragma unroll
        for (int it = 0; it < 2; it++){
            int idx = t + it * 256;        // 0..511
            int r  = idx >> 4;             // row 0..31
            int c4 = idx & 15;             // float4 within row 0..15
            size_t gb = (size_t)(m * NH + r) * 1536 + h * 64 + c4 * 4;
            *(float4*)(qs + r * 68 + c4 * 4) = *(const float4*)(qkv + gb);
            *(float4*)(ks + r * 68 + c4 * 4) = *(const float4*)(qkv + gb + 512);
            *(float4*)(vs + r * 68 + c4 * 4) = *(const float4*)(qkv + gb + 1024);
        }
        __syncthreads();

        // scores: 4 j's per thread
        float sv[4];
        #pragma unroll
        for (int jj = 0; jj < 4; jj++){
            int j = g * 4 + jj;
            float s = 0.f;
            #pragma unroll
            for (int d4 = 0; d4 < 16; d4++){
                float4 qa = *(float4*)(qs + i * 68 + d4 * 4);
                float4 ka = *(float4*)(ks + j * 68 + d4 * 4);
                s += qa.x*ka.x + qa.y*ka.y + qa.z*ka.z + qa.w*ka.w;
            }
            sv[jj] = s * 0.125f + bias8[h * 1056 + i * 33 + j];
        }
        // softmax across the 8 threads of row i
        float mx = fmaxf(fmaxf(sv[0], sv[1]), fmaxf(sv[2], sv[3]));
        mx = fmaxf(mx, __shfl_xor_sync(0xffffffffu, mx, 1));
        mx = fmaxf(mx, __shfl_xor_sync(0xffffffffu, mx, 2));
        mx = fmaxf(mx, __shfl_xor_sync(0xffffffffu, mx, 4));
        float ev[4], sum = 0.f;
        #pragma unroll
        for (int jj = 0; jj < 4; jj++){ ev[jj] = __expf(sv[jj] - mx); sum += ev[jj]; }
        sum += __shfl_xor_sync(0xffffffffu, sum, 1);
        sum += __shfl_xor_sync(0xffffffffu, sum, 2);
        sum += __shfl_xor_sync(0xffffffffu, sum, 4);
        const float inv = 1.f / sum;
        #pragma unroll
        for (int jj = 0; jj < 4; jj++) sc[i * 33 + g * 4 + jj] = ev[jj] * inv;
        __syncwarp();

        // AV: thread owns d-segment g*8 .. g*8+7 of row i
        const int dseg = g * 8;
        float acc[8];
        #pragma unroll
        for (int dd = 0; dd < 8; dd++) acc[dd] = 0.f;
        for (int j = 0; j < NH; j++){
            float p = sc[i * 33 + j];
            float4 v0 = *(float4*)(vs + j * 68 + dseg);
            float4 v1 = *(float4*)(vs + j * 68 + dseg + 4);
            acc[0] += p * v0.x; acc[1] += p * v0.y;
            acc[2] += p * v0.z; acc[3] += p * v0.w;
            acc[4] += p * v1.x; acc[5] += p * v1.y;
            acc[6] += p * v1.z; acc[7] += p * v1.w;
        }
        // split-bf16 output, row stride 1024 = [hi(512) | lo(512)]
        size_t rb = ((size_t)(m * NH) + i) * 1024 + h * 64 + dseg;
        #pragma unroll
        for (int dd = 0; dd < 8; dd += 2){
            __nv_bfloat16 hx, hy, lx, ly;
            split2(acc[dd],   hx, lx);
            split2(acc[dd+1], hy, ly);
            *(__nv_bfloat162*)&osp[rb + dd]       = __halves2bfloat162(hx, hy);
            *(__nv_bfloat162*)&osp[rb + 512 + dd] = __halves2bfloat162(lx, ly);
        }
    }
}

// ---------------- fused residual add + LayerNorm (+optional split out) ----
__global__ void __launch_bounds__(128)
add_ln_kernel2(const float* __restrict__ a, const float* __restrict__ b,
               const float* __restrict__ g, const float* __restrict__ be,
               float* __restrict__ outf, __nv_bfloat16* __restrict__ outsp)
{
    const int row = blockIdx.x;
    const int t   = threadIdx.x;
    const size_t off = (size_t)row * MDIM + t * 4;

    float4 va = *(const float4*)(a + off);
    float4 vb = *(const float4*)(b + off);
    float4 vv = make_float4(va.x + vb.x, va.y + vb.y, va.z + vb.z, va.w + vb.w);

    float s  = vv.x + vv.y + vv.z + vv.w;
    float ss = vv.x*vv.x + vv.y*vv.y + vv.z*vv.z + vv.w*vv.w;
    #pragma unroll
    for (int o2 = 16; o2; o2 >>= 1){
        s  += __shfl_xor_sync(0xffffffffu, s,  o2);
        ss += __shfl_xor_sync(0xffffffffu, ss, o2);
    }
    __shared__ float sh_s[4], sh_ss[4];
    const int w = t >> 5, l = t & 31;
    if (l == 0){ sh_s[w] = s; sh_ss[w] = ss; }
    __syncthreads();
    s  = sh_s[0]  + sh_s[1]  + sh_s[2]  + sh_s[3];
    ss = sh_ss[0] + sh_ss[1] + sh_ss[2] + sh_ss[3];

    const float mean = s * (1.f / 512.f);
    const float var  = ss * (1.f / 512.f) - mean * mean;
    const float rstd = rsqrtf(var + 1e-5f);

    float4 vg  = *(const float4*)(g  + t*4);
    float4 vbe = *(const float4*)(be + t*4);
    float4 r;
    r.x = (vv.x - mean) * rstd * vg.x + vbe.x;
    r.y = (vv.y - mean) * rstd * vg.y + vbe.y;
    r.z = (vv.z - mean) * rstd * vg.z + vbe.z;
    r.w = (vv.w - mean) * rstd * vg.w + vbe.w;
    if (outf) *(float4*)(outf + off) = r;
    if (outsp){
        __nv_bfloat16 h0,h1,h2,h3,l0,l1,l2,l3;
        split2(r.x,h0,l0); split2(r.y,h1,l1); split2(r.z,h2,l2); split2(r.w,h3,l3);
        __nv_bfloat162 hA = __halves2bfloat162(h0,h1), hB = __halves2bfloat162(h2,h3);
        __nv_bfloat162 lA = __halves2bfloat162(l0,l1), lB = __halves2bfloat162(l2,l3);
        size_t rb = (size_t)row * 1024 + t * 4;
        *(uint2*)(outsp + rb)       = make_uint2(*(uint32_t*)&hA, *(uint32_t*)&hB);
        *(uint2*)(outsp + rb + 512) = make_uint2(*(uint32_t*)&lA, *(uint32_t*)&lB);
    }
}

// ---------------- driver ----------------
extern "C" void kernel_launch(void* const* d_in, const int* in_sizes, int n_in,
                              void* d_out, int out_size)
{
    (void)in_sizes; (void)n_in; (void)out_size;

    const float* x    = (const float*)d_in[0];
    const int*   dist = (const int*)  d_in[1];
    const int*   phis = (const int*)  d_in[2];
    const float* W_in = (const float*)d_in[3];
    const float* dtab = (const float*)d_in[4];
    const float* ptab = (const float*)d_in[5];
    const float* Wb   = (const float*)d_in[6];
    const float* Wq   = (const float*)d_in[7];
    const float* Wk   = (const float*)d_in[8];
    const float* Wv   = (const float*)d_in[9];
    const float* Wo   = (const float*)d_in[10];
    const float* Wf1  = (const float*)d_in[11];
    const float* Wf2  = (const float*)d_in[12];
    const float* g1   = (const float*)d_in[13];
    const float* b1   = (const float*)d_in[14];
    const float* g2   = (const float*)d_in[15];
    const float* b2   = (const float*)d_in[16];
    const float* Wout = (const float*)d_in[17];
    float* out = (float*)d_out;

    float *pf0, *pqkv;
    __nv_bfloat16 *pa1, *pa2, *pwin, *pwqkv, *pwo, *pwf1, *pwf2, *pwout;
    cudaGetSymbolAddress((void**)&pf0,  g_f0);
    cudaGetSymbolAddress((void**)&pqkv, g_qkv);
    cudaGetSymbolAddress((void**)&pa1,  g_a1);
    cudaGetSymbolAddress((void**)&pa2,  g_a2);
    cudaGetSymbolAddress((void**)&pwin, g_win2);
    cudaGetSymbolAddress((void**)&pwqkv,g_wqkv2);
    cudaGetSymbolAddress((void**)&pwo,  g_wo2);
    cudaGetSymbolAddress((void**)&pwf1, g_wf12);
    cudaGetSymbolAddress((void**)&pwf2, g_wf22);
    cudaGetSymbolAddress((void**)&pwout,g_wout2);

    float* att_out = pqkv;                       // aliases (sequential deps)
    float* h1      = pqkv + (size_t)TOK * 512;
    float* ff2     = pqkv + (size_t)TOK * 1024;

    const int SMG = 256 * 128 * 2;          // 65536 per CTA (3 CTAs/SM)
    const int SMA = 16288 * 4;              // 65152 (attention)
    cudaFuncSetAttribute(mma_gemm, cudaFuncAttributeMaxDynamicSharedMemorySize, SMG);
    cudaFuncSetAttribute(attn_kernel, cudaFuncAttributeMaxDynamicSharedMemorySize, SMA);

    const unsigned MT = TOK / 128;   // 1024 m-tiles

    // 0) all weight conversions in one launch
    WtTable tab;
    tab.d[0] = { W_in, pwin,                      128,  512 };
    tab.d[1] = { Wq,   pwqkv,                     512,  512 };
    tab.d[2] = { Wk,   pwqkv + (size_t)512*1024,  512,  512 };
    tab.d[3] = { Wv,   pwqkv + (size_t)1024*1024, 512,  512 };
    tab.d[4] = { Wo,   pwo,                       512,  512 };
    tab.d[5] = { Wf1,  pwf1,                      512, 2048 };
    tab.d[6] = { Wf2,  pwf2,                     2048,  512 };
    tab.d[7] = { Wout, pwout,                     512,  128 };
    split_wt_all<<<dim3(8192, 8), 256>>>(tab);

    // 1) split x -> a2  [TOK, 256]
    {
        size_t total = (size_t)TOK * 128 / 4;
        split_act<<<(unsigned)((total + 255) / 256), 256>>>(x, pa2, 128, total);
    }
    // 2) h = x @ W_in -> f0 (fp32) + split -> a1
    mma_gemm<<<dim3(4, MT), 128, SMG>>>(pa2, pwin, pf0, pa1, 128, 512, 2);
    // 3) qkv = h @ Wqkv -> fp32 [TOK,1536]
    mma_gemm<<<dim3(12, MT), 128, SMG>>>(pa1, pwqkv, pqkv, nullptr, 512, 1536, 0);
    // 4) attention -> split o -> a1
    attn_kernel<<<MCNT, 256, SMA>>>(pqkv, dist, phis, dtab, ptab, Wb, pa1);
    // 5) att_out = o @ Wo -> fp32
    mma_gemm<<<dim3(4, MT), 128, SMG>>>(pa1, pwo, att_out, nullptr, 512, 512, 0);
    // 6) h1 = LN(h + att_out) -> fp32 h1 + split -> a1
    add_ln_kernel2<<<TOK, 128>>>(pf0, att_out, g1, b1, h1, pa1);
    // 7) ff = silu(h1 @ Wf1) -> split -> a2
    mma_gemm<<<dim3(16, MT), 128, SMG>>>(pa1, pwf1, nullptr, pa2, 512, 2048, 1);
    // 8) ff2 = ff @ Wf2 -> fp32
    mma_gemm<<<dim3(4, MT), 128, SMG>>>(pa2, pwf2, ff2, nullptr, 2048, 512, 0);
    // 9) h2 = LN(h1 + ff2) -> split only -> a1
    add_ln_kernel2<<<TOK, 128>>>(h1, ff2, g2, b2, nullptr, pa1);
    // 10) out = h2 @ W_out
    mma_gemm<<<dim3(1, MT), 128, SMG>>>(pa1, pwout, out, nullptr, 512, 128, 0);
}

// round 13
// speedup vs baseline: 2.9999x; 1.0001x over previous
#include <cuda_runtime.h>
#include <cuda_bf16.h>
#include <cstdint>
#include <math.h>

// ---------------- problem constants ----------------
#define TOK   131072          // B*N*NH tokens
#define MDIM  512
#define FFD   2048
#define MCNT  4096
#define NH    32
#define HEADS 8
#define HD    64

// ---------------- helpers ----------------
__device__ __forceinline__ uint32_t smem_to_u32(const void* p){
    uint32_t a;
    asm("{ .reg .u64 t; cvta.to.shared.u64 t, %1; cvt.u32.u64 %0, t; }" : "=r"(a) : "l"(p));
    return a;
}
__device__ __forceinline__ void cp_async16(uint32_t saddr, const void* gaddr){
    asm volatile("cp.async.cg.shared.global [%0], [%1], 16;" :: "r"(saddr), "l"(gaddr));
}
__device__ __forceinline__ void cp_commit(){ asm volatile("cp.async.commit_group;"); }
template<int N>
__device__ __forceinline__ void cp_wait(){ asm volatile("cp.async.wait_group %0;" :: "n"(N)); }

__device__ __forceinline__ void ldm_x4(uint32_t addr, uint32_t& r0, uint32_t& r1,
                                       uint32_t& r2, uint32_t& r3){
    asm volatile("ldmatrix.sync.aligned.m8n8.x4.shared.b16 {%0,%1,%2,%3}, [%4];"
        : "=r"(r0), "=r"(r1), "=r"(r2), "=r"(r3) : "r"(addr));
}
__device__ __forceinline__ void mma_bf16(float& c0, float& c1, float& c2, float& c3,
                                         uint32_t a0, uint32_t a1, uint32_t a2, uint32_t a3,
                                         uint32_t b0, uint32_t b1){
    asm volatile("mma.sync.aligned.m16n8k16.row.col.f32.bf16.bf16.f32 "
        "{%0,%1,%2,%3}, {%4,%5,%6,%7}, {%8,%9}, {%0,%1,%2,%3};"
        : "+f"(c0), "+f"(c1), "+f"(c2), "+f"(c3)
        : "r"(a0), "r"(a1), "r"(a2), "r"(a3), "r"(b0), "r"(b1));
}
__device__ __forceinline__ void split2(float f, __nv_bfloat16& h, __nv_bfloat16& l){
    h = __float2bfloat16(f);
    l = __float2bfloat16(f - __bfloat162float(h));
}

// ---------------- scratch (~2.3 GB) ----------------
__device__ __align__(256) float g_f0 [TOK*MDIM];          // h (residual)
__device__ __align__(256) float g_qkv[(size_t)TOK*1536];  // qkv / att_out / h1 / ff2
__device__ __align__(256) __nv_bfloat16 g_a1[(size_t)TOK*1024];  // split 512-wide acts
__device__ __align__(256) __nv_bfloat16 g_a2[(size_t)TOK*4096];  // split ff / x acts
__device__ __align__(256) __nv_bfloat16 g_win2 [512*256];
__device__ __align__(256) __nv_bfloat16 g_wqkv2[(size_t)1536*1024];
__device__ __align__(256) __nv_bfloat16 g_wo2  [512*1024];
__device__ __align__(256) __nv_bfloat16 g_wf12 [(size_t)2048*1024];
__device__ __align__(256) __nv_bfloat16 g_wf22 [(size_t)512*4096];
__device__ __align__(256) __nv_bfloat16 g_wout2[128*1024];

// ---------------- fused weight conversion (ONE launch for all 8) ----------
struct WtDesc { const float* W; __nv_bfloat16* Y; int K; int N; };
struct WtTable { WtDesc d[8]; };

__global__ void __launch_bounds__(256)
split_wt_all(WtTable tab)
{
    const WtDesc& e = tab.d[blockIdx.y];
    size_t total = (size_t)e.N * 2 * e.K;
    size_t id = (size_t)blockIdx.x * 256 + threadIdx.x;
    if (id >= total) return;
    int K2 = 2 * e.K;
    size_t n = id / K2;
    int c = (int)(id % K2);
    int reg = c >= e.K, cs = c - (reg ? e.K : 0);
    float x = e.W[(size_t)cs * e.N + n];
    __nv_bfloat16 h, l;
    split2(x, h, l);
    e.Y[id] = reg ? l : h;
}

// ---------------- split conversion: activations (x only) ----------------
__global__ void __launch_bounds__(256)
split_act(const float* __restrict__ X, __nv_bfloat16* __restrict__ Y,
          int K, size_t total /* R*K/4 */)
{
    size_t id = (size_t)blockIdx.x * 256 + threadIdx.x;
    if (id >= total) return;
    int kq = K >> 2;
    size_t r = id / kq;
    int c = (int)(id % kq) << 2;
    float4 x = *(const float4*)(X + r * K + c);
    __nv_bfloat16 h0,h1,h2,h3,l0,l1,l2,l3;
    split2(x.x,h0,l0); split2(x.y,h1,l1); split2(x.z,h2,l2); split2(x.w,h3,l3);
    __nv_bfloat162 hA = __halves2bfloat162(h0,h1), hB = __halves2bfloat162(h2,h3);
    __nv_bfloat162 lA = __halves2bfloat162(l0,l1), lB = __halves2bfloat162(l2,l3);
    size_t ob = r * (size_t)(2 * K);
    *(uint2*)(Y + ob + c)     = make_uint2(*(uint32_t*)&hA, *(uint32_t*)&hB);
    *(uint2*)(Y + ob + K + c) = make_uint2(*(uint32_t*)&lA, *(uint32_t*)&lB);
}

// ---------------- mma.sync bf16 GEMM, 3-segment split schedule ----------------
// A [M, 2K] = [hi|lo], Bt [Ntot, 2K] = [hi|lo] (K-major rows).
// Segments: (Ahi,Bhi), (Alo,Bhi), (Ahi,Blo) accumulated in registers.
// CTA tile 128x128; 4 warps (2x2); warp tile 64x64; BK=64; 144-byte row
// stride (128B data + 16B pad, affine addresses, conflict-free ldmatrix);
// 2 stages (36.9KB each); 128 threads, 73.7KB smem -> 3 CTAs/SM.
// mode: 0=f32, 1=silu+split, 2=f32+split.
__global__ void __launch_bounds__(128, 3)
mma_gemm(const __nv_bfloat16* __restrict__ A, const __nv_bfloat16* __restrict__ Bt,
         float* __restrict__ Cf, __nv_bfloat16* __restrict__ Csp,
         int K, int Ntot, int mode)
{
    constexpr int THREADS = 128;
    constexpr int ROWB = 144;                 // bytes per smem row
    constexpr int A_BYTES = 128 * ROWB;       // 18432
    constexpr int STAGE_BYTES = 256 * ROWB;   // 36864
    extern __shared__ __align__(16) char smem[];

    const int tid  = threadIdx.x;
    const int lane = tid & 31;
    const int wid  = tid >> 5;
    const int wm   = wid >> 1;        // 0..1
    const int wn   = wid & 1;         // 0..1
    const int m0   = blockIdx.y * 128;
    const int n0   = blockIdx.x * 128;

    const int lda = 2 * K;
    const __nv_bfloat16* Ab = A  + (size_t)m0 * lda;
    const __nv_bfloat16* Bb = Bt + (size_t)n0 * lda;
    const uint32_t sbase = smem_to_u32(smem);

    float c[4][8][4];
    #pragma unroll
    for (int i = 0; i < 4; i++)
        #pragma unroll
        for (int j = 0; j < 8; j++)
            #pragma unroll
            for (int q = 0; q < 4; q++) c[i][j][q] = 0.f;

    const int kch = K >> 6;       // chunks of 64 columns
    const int nch = 3 * kch;

    auto load_chunk = [&](int tt, int stage){
        int seg = (tt >= kch) + (tt >= 2 * kch);
        int kk = tt - seg * kch;
        int ac = ((seg == 1) ? K : 0) + (kk << 6);
        int bc = ((seg == 2) ? K : 0) + (kk << 6);
        uint32_t sa = sbase + stage * STAGE_BYTES;
        uint32_t sb = sa + A_BYTES;
        #pragma unroll
        for (int it = 0; it < 8; it++){
            int idx = tid + it * THREADS;
            int r = idx >> 3, ch = idx & 7;
            cp_async16(sa + r * ROWB + ch * 16, Ab + (size_t)r * lda + ac + ch * 8);
        }
        #pragma unroll
        for (int it = 0; it < 8; it++){
            int idx = tid + it * THREADS;
            int r = idx >> 3, ch = idx & 7;
            cp_async16(sb + r * ROWB + ch * 16, Bb + (size_t)r * lda + bc + ch * 8);
        }
    };

    load_chunk(0, 0);
    cp_commit();

    for (int t = 0; t < nch; t++){
        cp_wait<0>();
        __syncthreads();
        if (t + 1 < nch){
            load_chunk(t + 1, (t + 1) & 1);
            cp_commit();
        }
        const uint32_t sa = sbase + (t & 1) * STAGE_BYTES;
        const uint32_t sb = sa + A_BYTES;
        #pragma unroll
        for (int ks = 0; ks < 4; ks++){
            uint32_t a[4][4], b[8][2];
            #pragma unroll
            for (int mf = 0; mf < 4; mf++){
                int r = wm * 64 + mf * 16 + (lane & 15);
                int ch = 2 * ks + (lane >> 4);
                ldm_x4(sa + r * ROWB + ch * 16,
                       a[mf][0], a[mf][1], a[mf][2], a[mf][3]);
            }
            #pragma unroll
            for (int g = 0; g < 4; g++){
                int r = wn * 64 + g * 16 + ((lane >> 4) << 3) + (lane & 7);
                int ch = 2 * ks + ((lane >> 3) & 1);
                ldm_x4(sb + r * ROWB + ch * 16,
                       b[2*g][0], b[2*g][1], b[2*g+1][0], b[2*g+1][1]);
            }
            #pragma unroll
            for (int mf = 0; mf < 4; mf++)
                #pragma unroll
                for (int nf = 0; nf < 8; nf++)
                    mma_bf16(c[mf][nf][0], c[mf][nf][1], c[mf][nf][2], c[mf][nf][3],
                             a[mf][0], a[mf][1], a[mf][2], a[mf][3],
                             b[nf][0], b[nf][1]);
        }
    }

    // epilogue
    #pragma unroll
    for (int mf = 0; mf < 4; mf++){
        #pragma unroll
        for (int half = 0; half < 2; half++){
            const int row = m0 + wm * 64 + mf * 16 + (lane >> 2) + half * 8;
            #pragma unroll
            for (int nf = 0; nf < 8; nf++){
                const int col = n0 + wn * 64 + nf * 8 + (lane & 3) * 2;
                float fx = c[mf][nf][half * 2 + 0];
                float fy = c[mf][nf][half * 2 + 1];
                if (mode == 1){
                    fx = fx / (1.f + __expf(-fx));
                    fy = fy / (1.f + __expf(-fy));
                }
                if (mode != 1){
                    *(float2*)&Cf[(size_t)row * Ntot + col] = make_float2(fx, fy);
                }
                if (mode != 0){
                    __nv_bfloat16 hx, hy, lx, ly;
                    split2(fx, hx, lx);
                    split2(fy, hy, ly);
                    __nv_bfloat162 hp = __halves2bfloat162(hx, hy);
                    __nv_bfloat162 lp = __halves2bfloat162(lx, ly);
                    size_t rb = (size_t)row * (2 * Ntot);
                    *(__nv_bfloat162*)&Csp[rb + col]        = hp;
                    *(__nv_bfloat162*)&Csp[rb + Ntot + col] = lp;
                }
            }
        }
    }
}

// ---------------- fused attention: one block per m, all 8 heads ------------
__global__ void __launch_bounds__(256)
attn_kernel(const float* __restrict__ qkv,
            const int*   __restrict__ dist, const int* __restrict__ phi,
            const float* __restrict__ dtab, const float* __restrict__ ptab,
            const float* __restrict__ Wb,   __nv_bfloat16* __restrict__ osp)
{
    extern __shared__ float sm[];
    float* bias8 = sm;              // [h*1056 + i*33 + j]  (8448)
    float* qs    = sm + 8448;       // [i*68 + d]           (2176)
    float* ks    = sm + 10624;      // (2176)
    float* vs    = sm + 12800;      // (2176)
    float* sc    = sm + 14976;      // [i*33 + j]           (1056)
    float* wb8   = sm + 16032;      // [p*8 + h]            (256)

    const int m = blockIdx.x;
    const int t = threadIdx.x;

    wb8[t] = Wb[t];                 // 256 = PED*HEADS
    __syncthreads();

    // ---- bias for all heads: 4 pairs per thread ----
    const int base_mm = m * (NH * NH);
    #pragma unroll
    for (int q4 = 0; q4 < 4; q4++){
        int pair = t * 4 + q4;              // 0..1023
        int i = pair >> 5, j = pair & 31;
        int id = dist[base_mm + pair];
        int ip = phi [base_mm + pair];
        const float4* dp = (const float4*)(dtab + (size_t)id * 32);
        const float4* fp = (const float4*)(ptab + (size_t)ip * 32);
        float acc[8];
        #pragma unroll
        for (int h = 0; h < 8; h++) acc[h] = 0.f;
        #pragma unroll
        for (int v4 = 0; v4 < 8; v4++){
            float4 d4 = dp[v4];
            float4 f4 = fp[v4];
            float pr[4] = { d4.x*f4.x, d4.y*f4.y, d4.z*f4.z, d4.w*f4.w };
            #pragma unroll
            for (int pp = 0; pp < 4; pp++){
                int p = v4 * 4 + pp;
                #pragma unroll
                for (int h = 0; h < 8; h++)
                    acc[h] += pr[pp] * wb8[p * 8 + h];
            }
        }
        #pragma unroll
        for (int h = 0; h < 8; h++) bias8[h * 1056 + i * 33 + j] = acc[h];
    }

    const int i = t >> 3;          // row 0..31
    const int g = t & 7;           // group 0..7

    for (int h = 0; h < 8; h++){
        __syncthreads();   // bias ready (h=0) / prior head done (h>0)
        // load q,k,v head slices (32 rows x 16 float4 each), vectorized
        #pragma unroll
        for (int it = 0; it < 2; it++){
            int idx = t + it * 256;        // 0..511
            int r  = idx >> 4;             // row 0..31
            int c4 = idx & 15;             // float4 within row 0..15
            size_t gb = (size_t)(m * NH + r) * 1536 + h * 64 + c4 * 4;
            *(float4*)(qs + r * 68 + c4 * 4) = *(const float4*)(qkv + gb);
            *(float4*)(ks + r * 68 + c4 * 4) = *(const float4*)(qkv + gb + 512);
            *(float4*)(vs + r * 68 + c4 * 4) = *(const float4*)(qkv + gb + 1024);
        }
        __syncthreads();

        // scores: 4 j's per thread
        float sv[4];
        #pragma unroll
        for (int jj = 0; jj < 4; jj++){
            int j = g * 4 + jj;
            float s = 0.f;
            #pragma unroll
            for (int d4 = 0; d4 < 16; d4++){
                float4 qa = *(float4*)(qs + i * 68 + d4 * 4);
                float4 ka = *(float4*)(ks + j * 68 + d4 * 4);
                s += qa.x*ka.x + qa.y*ka.y + qa.z*ka.z + qa.w*ka.w;
            }
            sv[jj] = s * 0.125f + bias8[h * 1056 + i * 33 + j];
        }
        // softmax across the 8 threads of row i
        float mx = fmaxf(fmaxf(sv[0], sv[1]), fmaxf(sv[2], sv[3]));
        mx = fmaxf(mx, __shfl_xor_sync(0xffffffffu, mx, 1));
        mx = fmaxf(mx, __shfl_xor_sync(0xffffffffu, mx, 2));
        mx = fmaxf(mx, __shfl_xor_sync(0xffffffffu, mx, 4));
        float ev[4], sum = 0.f;
        #pragma unroll
        for (int jj = 0; jj < 4; jj++){ ev[jj] = __expf(sv[jj] - mx); sum += ev[jj]; }
        sum += __shfl_xor_sync(0xffffffffu, sum, 1);
        sum += __shfl_xor_sync(0xffffffffu, sum, 2);
        sum += __shfl_xor_sync(0xffffffffu, sum, 4);
        const float inv = 1.f / sum;
        #pragma unroll
        for (int jj = 0; jj < 4; jj++) sc[i * 33 + g * 4 + jj] = ev[jj] * inv;
        __syncwarp();

        // AV: thread owns d-segment g*8 .. g*8+7 of row i
        const int dseg = g * 8;
        float acc[8];
        #pragma unroll
        for (int dd = 0; dd < 8; dd++) acc[dd] = 0.f;
        for (int j = 0; j < NH; j++){
            float p = sc[i * 33 + j];
            float4 v0 = *(float4*)(vs + j * 68 + dseg);
            float4 v1 = *(float4*)(vs + j * 68 + dseg + 4);
            acc[0] += p * v0.x; acc[1] += p * v0.y;
            acc[2] += p * v0.z; acc[3] += p * v0.w;
            acc[4] += p * v1.x; acc[5] += p * v1.y;
            acc[6] += p * v1.z; acc[7] += p * v1.w;
        }
        // split-bf16 output, row stride 1024 = [hi(512) | lo(512)]
        size_t rb = ((size_t)(m * NH) + i) * 1024 + h * 64 + dseg;
        #pragma unroll
        for (int dd = 0; dd < 8; dd += 2){
            __nv_bfloat16 hx, hy, lx, ly;
            split2(acc[dd],   hx, lx);
            split2(acc[dd+1], hy, ly);
            *(__nv_bfloat162*)&osp[rb + dd]       = __halves2bfloat162(hx, hy);
            *(__nv_bfloat162*)&osp[rb + 512 + dd] = __halves2bfloat162(lx, ly);
        }
    }
}

// ---------------- fused residual add + LayerNorm (+optional split out) ----
__global__ void __launch_bounds__(128)
add_ln_kernel2(const float* __restrict__ a, const float* __restrict__ b,
               const float* __restrict__ g, const float* __restrict__ be,
               float* __restrict__ outf, __nv_bfloat16* __restrict__ outsp)
{
    const int row = blockIdx.x;
    const int t   = threadIdx.x;
    const size_t off = (size_t)row * MDIM + t * 4;

    float4 va = *(const float4*)(a + off);
    float4 vb = *(const float4*)(b + off);
    float4 vv = make_float4(va.x + vb.x, va.y + vb.y, va.z + vb.z, va.w + vb.w);

    float s  = vv.x + vv.y + vv.z + vv.w;
    float ss = vv.x*vv.x + vv.y*vv.y + vv.z*vv.z + vv.w*vv.w;
    #pragma unroll
    for (int o2 = 16; o2; o2 >>= 1){
        s  += __shfl_xor_sync(0xffffffffu, s,  o2);
        ss += __shfl_xor_sync(0xffffffffu, ss, o2);
    }
    __shared__ float sh_s[4], sh_ss[4];
    const int w = t >> 5, l = t & 31;
    if (l == 0){ sh_s[w] = s; sh_ss[w] = ss; }
    __syncthreads();
    s  = sh_s[0]  + sh_s[1]  + sh_s[2]  + sh_s[3];
    ss = sh_ss[0] + sh_ss[1] + sh_ss[2] + sh_ss[3];

    const float mean = s * (1.f / 512.f);
    const float var  = ss * (1.f / 512.f) - mean * mean;
    const float rstd = rsqrtf(var + 1e-5f);

    float4 vg  = *(const float4*)(g  + t*4);
    float4 vbe = *(const float4*)(be + t*4);
    float4 r;
    r.x = (vv.x - mean) * rstd * vg.x + vbe.x;
    r.y = (vv.y - mean) * rstd * vg.y + vbe.y;
    r.z = (vv.z - mean) * rstd * vg.z + vbe.z;
    r.w = (vv.w - mean) * rstd * vg.w + vbe.w;
    if (outf) *(float4*)(outf + off) = r;
    if (outsp){
        __nv_bfloat16 h0,h1,h2,h3,l0,l1,l2,l3;
        split2(r.x,h0,l0); split2(r.y,h1,l1); split2(r.z,h2,l2); split2(r.w,h3,l3);
        __nv_bfloat162 hA = __halves2bfloat162(h0,h1), hB = __halves2bfloat162(h2,h3);
        __nv_bfloat162 lA = __halves2bfloat162(l0,l1), lB = __halves2bfloat162(l2,l3);
        size_t rb = (size_t)row * 1024 + t * 4;
        *(uint2*)(outsp + rb)       = make_uint2(*(uint32_t*)&hA, *(uint32_t*)&hB);
        *(uint2*)(outsp + rb + 512) = make_uint2(*(uint32_t*)&lA, *(uint32_t*)&lB);
    }
}

// ---------------- driver ----------------
extern "C" void kernel_launch(void* const* d_in, const int* in_sizes, int n_in,
                              void* d_out, int out_size)
{
    (void)in_sizes; (void)n_in; (void)out_size;

    const float* x    = (const float*)d_in[0];
    const int*   dist = (const int*)  d_in[1];
    const int*   phis = (const int*)  d_in[2];
    const float* W_in = (const float*)d_in[3];
    const float* dtab = (const float*)d_in[4];
    const float* ptab = (const float*)d_in[5];
    const float* Wb   = (const float*)d_in[6];
    const float* Wq   = (const float*)d_in[7];
    const float* Wk   = (const float*)d_in[8];
    const float* Wv   = (const float*)d_in[9];
    const float* Wo   = (const float*)d_in[10];
    const float* Wf1  = (const float*)d_in[11];
    const float* Wf2  = (const float*)d_in[12];
    const float* g1   = (const float*)d_in[13];
    const float* b1   = (const float*)d_in[14];
    const float* g2   = (const float*)d_in[15];
    const float* b2   = (const float*)d_in[16];
    const float* Wout = (const float*)d_in[17];
    float* out = (float*)d_out;

    float *pf0, *pqkv;
    __nv_bfloat16 *pa1, *pa2, *pwin, *pwqkv, *pwo, *pwf1, *pwf2, *pwout;
    cudaGetSymbolAddress((void**)&pf0,  g_f0);
    cudaGetSymbolAddress((void**)&pqkv, g_qkv);
    cudaGetSymbolAddress((void**)&pa1,  g_a1);
    cudaGetSymbolAddress((void**)&pa2,  g_a2);
    cudaGetSymbolAddress((void**)&pwin, g_win2);
    cudaGetSymbolAddress((void**)&pwqkv,g_wqkv2);
    cudaGetSymbolAddress((void**)&pwo,  g_wo2);
    cudaGetSymbolAddress((void**)&pwf1, g_wf12);
    cudaGetSymbolAddress((void**)&pwf2, g_wf22);
    cudaGetSymbolAddress((void**)&pwout,g_wout2);

    float* att_out = pqkv;                       // aliases (sequential deps)
    float* h1      = pqkv + (size_t)TOK * 512;
    float* ff2     = pqkv + (size_t)TOK * 1024;

    const int SMG = 256 * 144 * 2;          // 73728 per CTA (3 CTAs/SM)
    const int SMA = 16288 * 4;              // 65152 (attention)
    cudaFuncSetAttribute(mma_gemm, cudaFuncAttributeMaxDynamicSharedMemorySize, SMG);
    cudaFuncSetAttribute(attn_kernel, cudaFuncAttributeMaxDynamicSharedMemorySize, SMA);

    const unsigned MT = TOK / 128;   // 1024 m-tiles

    // 0) all weight conversions in one launch
    WtTable tab;
    tab.d[0] = { W_in, pwin,                      128,  512 };
    tab.d[1] = { Wq,   pwqkv,                     512,  512 };
    tab.d[2] = { Wk,   pwqkv + (size_t)512*1024,  512,  512 };
    tab.d[3] = { Wv,   pwqkv + (size_t)1024*1024, 512,  512 };
    tab.d[4] = { Wo,   pwo,                       512,  512 };
    tab.d[5] = { Wf1,  pwf1,                      512, 2048 };
    tab.d[6] = { Wf2,  pwf2,                     2048,  512 };
    tab.d[7] = { Wout, pwout,                     512,  128 };
    split_wt_all<<<dim3(8192, 8), 256>>>(tab);

    // 1) split x -> a2  [TOK, 256]
    {
        size_t total = (size_t)TOK * 128 / 4;
        split_act<<<(unsigned)((total + 255) / 256), 256>>>(x, pa2, 128, total);
    }
    // 2) h = x @ W_in -> f0 (fp32) + split -> a1
    mma_gemm<<<dim3(4, MT), 128, SMG>>>(pa2, pwin, pf0, pa1, 128, 512, 2);
    // 3) qkv = h @ Wqkv -> fp32 [TOK,1536]
    mma_gemm<<<dim3(12, MT), 128, SMG>>>(pa1, pwqkv, pqkv, nullptr, 512, 1536, 0);
    // 4) attention -> split o -> a1
    attn_kernel<<<MCNT, 256, SMA>>>(pqkv, dist, phis, dtab, ptab, Wb, pa1);
    // 5) att_out = o @ Wo -> fp32
    mma_gemm<<<dim3(4, MT), 128, SMG>>>(pa1, pwo, att_out, nullptr, 512, 512, 0);
    // 6) h1 = LN(h + att_out) -> fp32 h1 + split -> a1
    add_ln_kernel2<<<TOK, 128>>>(pf0, att_out, g1, b1, h1, pa1);
    // 7) ff = silu(h1 @ Wf1) -> split -> a2
    mma_gemm<<<dim3(16, MT), 128, SMG>>>(pa1, pwf1, nullptr, pa2, 512, 2048, 1);
    // 8) ff2 = ff @ Wf2 -> fp32
    mma_gemm<<<dim3(4, MT), 128, SMG>>>(pa2, pwf2, ff2, nullptr, 2048, 512, 0);
    // 9) h2 = LN(h1 + ff2) -> split only -> a1
    add_ln_kernel2<<<TOK, 128>>>(h1, ff2, g2, b2, nullptr, pa1);
    // 10) out = h2 @ W_out
    mma_gemm<<<dim3(1, MT), 128, SMG>>>(pa1, pwout, out, nullptr, 512, 128, 0);
}